// round 1
// baseline (speedup 1.0000x reference)
#include <cuda_runtime.h>
#include <math.h>

// Problem constants
#define NB    4
#define CC    64          // CR == CA == CO == 64
#define HEADS 4
#define HCH   16
#define HH    48
#define WW    48
#define PP    (HH*WW)     // 2304 query positions
#define VH    46
#define VW    46
#define DD    (VH*VW)     // 2116 key/value positions

// Scratch layout (floats)
#define OFF_XIN   0
#define OFF_Q0    (OFF_XIN  + NB*CC*PP)
#define OFF_A0    (OFF_Q0   + NB*CC*PP)
#define OFF_HOUT  (OFF_A0   + NB*CC*PP)
#define OFF_K0    (OFF_HOUT + NB*CC*PP)
#define OFF_V0    (OFF_K0   + NB*CC*DD)
#define OFF_V2    (OFF_V0   + NB*CC*DD)
#define OFF_GC    (OFF_V2   + NB*CC*DD)
#define SCRATCH_TOTAL (OFF_GC + NB*3*CC)

__device__ float g_scratch[SCRATCH_TOTAL];

// ---------------------------------------------------------------------------
// 1x1 conv (pointwise 64->64 GEMM per pixel): out[n,o,p] = b[o] + sum_c W[o,c]*in[n,c,p]
// grid: (PP/256, NB), block 256
// ---------------------------------------------------------------------------
__global__ __launch_bounds__(256) void pointwise_k(
    const float* __restrict__ in, const float* __restrict__ wmat,
    const float* __restrict__ bias, float* __restrict__ out)
{
    __shared__ float sw[CC*CC];
    const int n = blockIdx.y;
    const int p = blockIdx.x * 256 + threadIdx.x;
    for (int i = threadIdx.x; i < CC*CC; i += 256) sw[i] = wmat[i];
    __syncthreads();

    float a[CC];
    const float* ib = in + (n*CC)*PP + p;
    #pragma unroll
    for (int c = 0; c < CC; c++) a[c] = ib[c*PP];

    float* ob = out + (n*CC)*PP + p;
    #pragma unroll 4
    for (int o = 0; o < CC; o++) {
        float acc = bias[o];
        #pragma unroll
        for (int c = 0; c < CC; c++) acc += sw[o*CC + c] * a[c];
        ob[o*PP] = acc;
    }
}

// ---------------------------------------------------------------------------
// 3x3 conv, SAME (valid=0, 48x48 out) or VALID (valid=1, 46x46 out).
// One block per (output row y, batch n). Input row-slab (64ch x 3rows x 50cols) in smem.
// 256 threads = 64 oc x 4 column-groups of 12.
// ---------------------------------------------------------------------------
__global__ __launch_bounds__(256) void conv3x3_k(
    const float* __restrict__ in, const float* __restrict__ wgt,
    float* __restrict__ out, int valid)
{
    __shared__ float tile[CC][3][50];
    const int y   = blockIdx.x;
    const int n   = blockIdx.y;
    const int ow  = valid ? VW : WW;
    const int ohw = valid ? DD : PP;
    const int ofs = valid ? 0 : -1;

    const float* inN = in + n*CC*PP;
    for (int idx = threadIdx.x; idx < CC*3*50; idx += 256) {
        int c = idx / 150;
        int rem = idx % 150;
        int r = rem / 50;
        int j = rem % 50;
        int gy = y + r + ofs;
        int gx = j + ofs;
        float v = 0.f;
        if (gy >= 0 && gy < HH && gx >= 0 && gx < WW)
            v = inN[c*PP + gy*WW + gx];
        tile[c][r][j] = v;
    }
    __syncthreads();

    const int oc = threadIdx.x >> 2;
    const int x0 = (threadIdx.x & 3) * 12;
    float acc[12];
    #pragma unroll
    for (int i = 0; i < 12; i++) acc[i] = 0.f;

    const float* wo = wgt + oc * (CC*9);
    #pragma unroll 4
    for (int c = 0; c < CC; c++) {
        #pragma unroll
        for (int r = 0; r < 3; r++) {
            float w0 = __ldg(wo + c*9 + r*3 + 0);
            float w1 = __ldg(wo + c*9 + r*3 + 1);
            float w2 = __ldg(wo + c*9 + r*3 + 2);
            #pragma unroll
            for (int xi = 0; xi < 12; xi++) {
                acc[xi] += w0 * tile[c][r][x0+xi]
                         + w1 * tile[c][r][x0+xi+1]
                         + w2 * tile[c][r][x0+xi+2];
            }
        }
    }

    float* ob = out + (n*CC + oc)*ohw + y*ow;
    #pragma unroll
    for (int xi = 0; xi < 12; xi++) {
        int x = x0 + xi;
        if (x < ow) ob[x] = acc[xi];
    }
}

// ---------------------------------------------------------------------------
// Attention for branch 0 only. One block per (q-tile of 128, n*head).
// Each thread owns one query: 16-dim dot with all 2116 keys, streaming
// softmax (no max-shift; logits are tiny), value accumulation in registers.
// ---------------------------------------------------------------------------
#define DCH 92   // 2116 = 23 * 92
__global__ __launch_bounds__(128) void attn_k(
    const float* __restrict__ q0, const float* __restrict__ k0,
    const float* __restrict__ v0, float* __restrict__ A0)
{
    __shared__ float sk[HCH][DCH];
    __shared__ float sv[HCH][DCH];
    const int nh = blockIdx.y;
    const int n = nh >> 2, head = nh & 3;
    const int q = blockIdx.x * 128 + threadIdx.x;

    const float* qb = q0 + (n*CC + head*HCH)*PP + q;
    float qv[HCH];
    #pragma unroll
    for (int c = 0; c < HCH; c++) qv[c] = qb[c*PP];

    float acc[HCH];
    #pragma unroll
    for (int c = 0; c < HCH; c++) acc[c] = 0.f;
    float l = 0.f;

    const float* kb = k0 + (n*CC + head*HCH)*DD;
    const float* vb = v0 + (n*CC + head*HCH)*DD;

    for (int d0 = 0; d0 < DD; d0 += DCH) {
        for (int i = threadIdx.x; i < HCH*DCH; i += 128) {
            int c = i / DCH, j = i % DCH;
            sk[c][j] = kb[c*DD + d0 + j];
            sv[c][j] = vb[c*DD + d0 + j];
        }
        __syncthreads();
        #pragma unroll 2
        for (int j = 0; j < DCH; j++) {
            float s = 0.f;
            #pragma unroll
            for (int c = 0; c < HCH; c++) s += qv[c] * sk[c][j];
            float p = __expf(s);
            l += p;
            #pragma unroll
            for (int c = 0; c < HCH; c++) acc[c] += p * sv[c][j];
        }
        __syncthreads();
    }

    const float inv = 1.f / l;
    float* ab = A0 + (n*CC + head*HCH)*PP + q;
    #pragma unroll
    for (int c = 0; c < HCH; c++) ab[c*PP] = acc[c] * inv;
}

// ---------------------------------------------------------------------------
// Branch-2 constant: a2[n,c] = mean_d conv_VALID(xin,Wv[2])[n,c,d]
// then gate consts gc[n,gi,o] = b_gates[gate,o] + sum_c Wproj[gate,2,o,c]*a2[n,c]
// for gates gi=0->i(gate0), 1->g(gate2), 2->o(gate3). One block per n.
// ---------------------------------------------------------------------------
__global__ __launch_bounds__(256) void a2gc_k(
    const float* __restrict__ v2, const float* __restrict__ Wproj,
    const float* __restrict__ bg, float* __restrict__ gc)
{
    __shared__ float a2[CC];
    const int n = blockIdx.x;
    const int t = threadIdx.x;
    if (t < CC) {
        const float* vb = v2 + (n*CC + t)*DD;
        float s = 0.f;
        for (int d = 0; d < DD; d++) s += vb[d];
        a2[t] = s * (1.f / (float)DD);
    }
    __syncthreads();
    if (t < 3*CC) {
        int gi = t / CC;
        int o  = t % CC;
        int gate = (gi == 0) ? 0 : (gi == 1 ? 2 : 3);
        const float* wp = Wproj + ((gate*4 + 2)*CC + o)*CC;  // [gate][branch=2][o][c]
        float acc = bg[gate*CC + o];
        #pragma unroll
        for (int c = 0; c < CC; c++) acc += wp[c] * a2[c];
        gc[(n*3 + gi)*CC + o] = acc;
    }
}

// ---------------------------------------------------------------------------
// Gates (i,g,o only; f is dead at cold start) + LSTM cell + hidden output.
// hout[n,o,p] = sigmoid(pre_o) * tanh( sigmoid(pre_i) * tanh(pre_g) )
// pre_g/i/o = Wproj[gate,0] @ A0 + gc(n).  Wi,Wg in smem; Wo via uniform __ldg.
// ---------------------------------------------------------------------------
__global__ __launch_bounds__(256) void gates_k(
    const float* __restrict__ A0, const float* __restrict__ Wproj,
    const float* __restrict__ gc, float* __restrict__ hout)
{
    __shared__ float swi[CC*CC];
    __shared__ float swg[CC*CC];
    const int n = blockIdx.y;
    const int p = blockIdx.x * 256 + threadIdx.x;
    for (int i = threadIdx.x; i < CC*CC; i += 256) {
        swi[i] = Wproj[(0*4 + 0)*CC*CC + i];   // gate i, branch 0
        swg[i] = Wproj[(2*4 + 0)*CC*CC + i];   // gate g, branch 0
    }
    __syncthreads();

    float a[CC];
    const float* ab = A0 + (n*CC)*PP + p;
    #pragma unroll
    for (int c = 0; c < CC; c++) a[c] = ab[c*PP];

    const float* gcn = gc + n*3*CC;
    const float* wo_g = Wproj + (3*4 + 0)*CC*CC;  // gate o, branch 0
    float* hb = hout + (n*CC)*PP + p;

    #pragma unroll 2
    for (int o = 0; o < CC; o++) {
        float ai = gcn[o];
        float ag = gcn[CC + o];
        float ao = gcn[2*CC + o];
        #pragma unroll
        for (int c = 0; c < CC; c++) {
            float av = a[c];
            ai += swi[o*CC + c] * av;
            ag += swg[o*CC + c] * av;
            ao += __ldg(wo_g + o*CC + c) * av;
        }
        float ig = 1.f / (1.f + __expf(-ai));
        float gg = tanhf(ag);
        float og = 1.f / (1.f + __expf(-ao));
        float cc = ig * gg;
        hb[o*PP] = og * tanhf(cc);
    }
}

// ---------------------------------------------------------------------------
extern "C" void kernel_launch(void* const* d_in, const int* in_sizes, int n_in,
                              void* d_out, int out_size)
{
    const float* x     = (const float*)d_in[0];
    const float* W_in  = (const float*)d_in[1];
    const float* b_in  = (const float*)d_in[2];
    const float* Wq    = (const float*)d_in[3];   // [4][64][64][3][3]
    const float* Wk    = (const float*)d_in[4];
    const float* Wv    = (const float*)d_in[5];
    const float* Wproj = (const float*)d_in[6];   // [4][4][64][64]
    const float* b_g   = (const float*)d_in[7];   // [4][64]
    const float* W_out = (const float*)d_in[8];
    const float* b_out = (const float*)d_in[9];
    float* out = (float*)d_out;

    void* sp = nullptr;
    cudaGetSymbolAddress(&sp, g_scratch);
    float* s = (float*)sp;

    const dim3 pwGrid(PP/256, NB);

    // 1) input 1x1 projection
    pointwise_k<<<pwGrid, 256>>>(x, W_in, b_in, s + OFF_XIN);
    // 2) 3x3 convs: q (SAME, Wq[0]); k,v (VALID, Wk[0], Wv[0]); v2 (VALID, Wv[2])
    conv3x3_k<<<dim3(HH, NB), 256>>>(s + OFF_XIN, Wq,                s + OFF_Q0, 0);
    conv3x3_k<<<dim3(VH, NB), 256>>>(s + OFF_XIN, Wk,                s + OFF_K0, 1);
    conv3x3_k<<<dim3(VH, NB), 256>>>(s + OFF_XIN, Wv,                s + OFF_V0, 1);
    conv3x3_k<<<dim3(VH, NB), 256>>>(s + OFF_XIN, Wv + 2*CC*CC*9,    s + OFF_V2, 1);
    // 3) attention branch 0
    attn_k<<<dim3(PP/128, NB*HEADS), 128>>>(s + OFF_Q0, s + OFF_K0, s + OFF_V0, s + OFF_A0);
    // 4) branch-2 constant + gate biases
    a2gc_k<<<NB, 256>>>(s + OFF_V2, Wproj, b_g, s + OFF_GC);
    // 5) gates + cell + hidden
    gates_k<<<pwGrid, 256>>>(s + OFF_A0, Wproj, s + OFF_GC, s + OFF_HOUT);
    // 6) output 1x1 projection
    pointwise_k<<<pwGrid, 256>>>(s + OFF_HOUT, W_out, b_out, out);
}

// round 2
// speedup vs baseline: 1.9145x; 1.9145x over previous
#include <cuda_runtime.h>
#include <math.h>

// Problem constants
#define NB    4
#define CC    64
#define HEADS 4
#define HCH   16
#define HH    48
#define WW    48
#define PP    (HH*WW)     // 2304
#define VH    46
#define VW    46
#define DD    (VH*VW)     // 2116

// Scratch layout (floats)
#define OFF_XIN   0
#define OFF_Q0    (OFF_XIN  + NB*CC*PP)
#define OFF_A0    (OFF_Q0   + NB*CC*PP)
#define OFF_HOUT  (OFF_A0   + NB*CC*PP)
#define OFF_K0    (OFF_HOUT + NB*CC*PP)
#define OFF_V0    (OFF_K0   + NB*CC*DD)
#define OFF_V2    (OFF_V0   + NB*CC*DD)
#define OFF_GC    (OFF_V2   + NB*CC*DD)
#define SCRATCH_TOTAL (OFF_GC + NB*3*CC)

__device__ float g_scratch[SCRATCH_TOTAL];

// ---- packed fp32x2 helpers (Blackwell FFMA2 path) -------------------------
typedef unsigned long long u64t;

__device__ __forceinline__ u64t pack2(float a, float b) {
    u64t r; asm("mov.b64 %0, {%1,%2};" : "=l"(r) : "f"(a), "f"(b)); return r;
}
__device__ __forceinline__ float2 unpack2(u64t v) {
    float2 r; asm("mov.b64 {%0,%1}, %2;" : "=f"(r.x), "=f"(r.y) : "l"(v)); return r;
}
__device__ __forceinline__ u64t ffma2(u64t a, u64t b, u64t c) {
    u64t d; asm("fma.rn.f32x2 %0, %1, %2, %3;" : "=l"(d) : "l"(a), "l"(b), "l"(c)); return d;
}

// ---------------------------------------------------------------------------
// Pointwise 1x1 conv: out[n,o,p] = b[o] + sum_c W[o,c]*in[n,c,p]
// Block: 256 threads = 64 px * 4 oc-groups (oc = ocg + 4u). Grid (PP/64, NB).
// Weights staged transposed [c][o] -> conflict-free broadcast reads.
// ---------------------------------------------------------------------------
__global__ __launch_bounds__(256) void pointwise_k(
    const float* __restrict__ in, const float* __restrict__ wmat,
    const float* __restrict__ bias, float* __restrict__ out)
{
    __shared__ float swT[CC*CC];   // [c][o]
    __shared__ float sx[CC][64];   // [c][px]
    const int n  = blockIdx.y;
    const int p0 = blockIdx.x * 64;

    for (int idx = threadIdx.x; idx < CC*CC; idx += 256) {
        int o = idx & 63, c = idx >> 6;
        swT[c*CC + o] = wmat[o*CC + c];        // transposed (store coalesced)
        int px = idx & 63, ci = idx >> 6;
        sx[ci][px] = in[(n*CC + ci)*PP + p0 + px];
    }
    __syncthreads();

    const int px  = threadIdx.x >> 2;
    const int ocg = threadIdx.x & 3;

    float acc[16];
    #pragma unroll
    for (int u = 0; u < 16; u++) acc[u] = bias[ocg + 4*u];

    #pragma unroll 4
    for (int c = 0; c < CC; c++) {
        float xv = sx[c][px];
        #pragma unroll
        for (int u = 0; u < 16; u++)
            acc[u] += swT[c*CC + ocg + 4*u] * xv;
    }

    #pragma unroll
    for (int u = 0; u < 16; u++)
        out[(n*CC + ocg + 4*u)*PP + p0 + px] = acc[u];
}

// ---------------------------------------------------------------------------
// Fused 3x3 convs: branch 0 = q (SAME, Wq[0]), 1 = k (VALID, Wk[0]),
// 2 = v (VALID, Wv[0]), 3 = v2 (VALID, Wv[2]).
// One block per (row y, batch n, branch). Tile row padded to 52 for float4 LDS.
// 256 threads = 64 oc * 4 column groups of 12.
// ---------------------------------------------------------------------------
__global__ __launch_bounds__(256) void conv4_k(
    const float* __restrict__ xin,
    const float* __restrict__ Wq, const float* __restrict__ Wk,
    const float* __restrict__ Wv,
    float* __restrict__ Q0, float* __restrict__ K0,
    float* __restrict__ V0, float* __restrict__ V2)
{
    const int br = blockIdx.z;
    const int y  = blockIdx.x;
    const int n  = blockIdx.y;
    if (br != 0 && y >= VH) return;

    const float* wgt; float* out; int ow, ohw, ofs;
    if (br == 0)      { wgt = Wq;             out = Q0; ow = WW; ohw = PP; ofs = -1; }
    else if (br == 1) { wgt = Wk;             out = K0; ow = VW; ohw = DD; ofs = 0;  }
    else if (br == 2) { wgt = Wv;             out = V0; ow = VW; ohw = DD; ofs = 0;  }
    else              { wgt = Wv + 2*CC*CC*9; out = V2; ow = VW; ohw = DD; ofs = 0;  }

    __shared__ float tile[CC][3][52];
    const float* inN = xin + n*CC*PP;
    for (int idx = threadIdx.x; idx < CC*3*52; idx += 256) {
        int c = idx / 156, rem = idx % 156, r = rem / 52, j = rem % 52;
        int gy = y + r + ofs, gx = j + ofs;
        float v = 0.f;
        if (gy >= 0 && gy < HH && gx >= 0 && gx < WW)
            v = inN[c*PP + gy*WW + gx];
        tile[c][r][j] = v;
    }
    __syncthreads();

    const int oc = threadIdx.x >> 2;
    const int x0 = (threadIdx.x & 3) * 12;   // 0,12,24,36: 16B aligned

    float acc[12];
    #pragma unroll
    for (int i = 0; i < 12; i++) acc[i] = 0.f;

    const float* wo = wgt + oc*(CC*9);
    #pragma unroll 2
    for (int c = 0; c < CC; c++) {
        #pragma unroll
        for (int r = 0; r < 3; r++) {
            const float4* t4 = (const float4*)&tile[c][r][x0];
            float4 a = t4[0], b = t4[1], d = t4[2], e = t4[3];
            float v[16] = {a.x,a.y,a.z,a.w, b.x,b.y,b.z,b.w,
                           d.x,d.y,d.z,d.w, e.x,e.y,e.z,e.w};
            float w0 = __ldg(wo + c*9 + r*3 + 0);
            float w1 = __ldg(wo + c*9 + r*3 + 1);
            float w2 = __ldg(wo + c*9 + r*3 + 2);
            #pragma unroll
            for (int xi = 0; xi < 12; xi++)
                acc[xi] += w0*v[xi] + w1*v[xi+1] + w2*v[xi+2];
        }
    }

    float* ob = out + (n*CC + oc)*ohw + y*ow;
    #pragma unroll
    for (int xi = 0; xi < 12; xi++) {
        int x = x0 + xi;
        if (x < ow) ob[x] = acc[xi];
    }
}

// ---------------------------------------------------------------------------
// Attention (branch 0): 1 query/thread, 128 threads/block, grid (PP/128, NB*HEADS).
// Streaming softmax, f32x2-packed along the key dim. k/v staged as u64 pairs.
// ---------------------------------------------------------------------------
#define DCH 92   // 2116 = 23 * 92; 92/4 = 23 groups of 4
__global__ __launch_bounds__(128) void attn_k(
    const float* __restrict__ q0, const float* __restrict__ k0,
    const float* __restrict__ v0, float* __restrict__ A0)
{
    __shared__ __align__(16) u64t sk2[HCH][DCH/2];   // (j, j+1) packs
    __shared__ __align__(16) u64t sv2[HCH][DCH/2];

    const int nh = blockIdx.y;
    const int n = nh >> 2, head = nh & 3;
    const int q = blockIdx.x * 128 + threadIdx.x;

    const float* qb = q0 + (n*CC + head*HCH)*PP + q;
    u64t qv2[HCH];
    #pragma unroll
    for (int c = 0; c < HCH; c++) { float qc = qb[c*PP]; qv2[c] = pack2(qc, qc); }

    u64t acc2[HCH];
    #pragma unroll
    for (int c = 0; c < HCH; c++) acc2[c] = 0ULL;
    float l = 0.f;

    const float* kb = k0 + (n*CC + head*HCH)*DD;
    const float* vb = v0 + (n*CC + head*HCH)*DD;

    for (int d0 = 0; d0 < DD; d0 += DCH) {
        for (int idx = threadIdx.x; idx < HCH*(DCH/2)*2; idx += 128) {
            int half = idx >= HCH*(DCH/2);
            int i = idx - half*HCH*(DCH/2);
            int c = i / (DCH/2), jj = i % (DCH/2);
            const float* src = half ? vb : kb;
            u64t val = *(const u64t*)(src + c*DD + d0 + 2*jj);
            if (half) sv2[c][jj] = val; else sk2[c][jj] = val;
        }
        __syncthreads();

        #pragma unroll 1
        for (int jg = 0; jg < DCH/2; jg += 2) {      // 4 keys per iteration
            u64t s2a = 0ULL, s2b = 0ULL;
            #pragma unroll
            for (int c = 0; c < HCH; c++) {
                ulonglong2 kk = *(const ulonglong2*)&sk2[c][jg];
                s2a = ffma2(qv2[c], kk.x, s2a);
                s2b = ffma2(qv2[c], kk.y, s2b);
            }
            float2 sa = unpack2(s2a), sb = unpack2(s2b);
            float p0 = __expf(sa.x), p1 = __expf(sa.y);
            float p2 = __expf(sb.x), p3 = __expf(sb.y);
            l += (p0 + p1) + (p2 + p3);
            u64t pA = pack2(p0, p1), pB = pack2(p2, p3);
            #pragma unroll
            for (int c = 0; c < HCH; c++) {
                ulonglong2 vv = *(const ulonglong2*)&sv2[c][jg];
                acc2[c] = ffma2(pA, vv.x, acc2[c]);
                acc2[c] = ffma2(pB, vv.y, acc2[c]);
            }
        }
        __syncthreads();
    }

    const float inv = 1.f / l;
    float* ab = A0 + (n*CC + head*HCH)*PP + q;
    #pragma unroll
    for (int c = 0; c < HCH; c++) {
        float2 a = unpack2(acc2[c]);
        ab[c*PP] = (a.x + a.y) * inv;
    }
}

// ---------------------------------------------------------------------------
// Branch-2 constant (uniform-softmax branch) + gate bias constants.
// ---------------------------------------------------------------------------
__global__ __launch_bounds__(256) void a2gc_k(
    const float* __restrict__ v2, const float* __restrict__ Wproj,
    const float* __restrict__ bg, float* __restrict__ gc)
{
    __shared__ float a2[CC];
    const int n = blockIdx.x;
    const int t = threadIdx.x;
    if (t < CC) {
        const float* vbp = v2 + (n*CC + t)*DD;
        float s = 0.f;
        for (int d = 0; d < DD; d++) s += vbp[d];
        a2[t] = s * (1.f / (float)DD);
    }
    __syncthreads();
    if (t < 3*CC) {
        int gi = t / CC;
        int o  = t % CC;
        int gate = (gi == 0) ? 0 : (gi == 1 ? 2 : 3);
        const float* wp = Wproj + ((gate*4 + 2)*CC + o)*CC;
        float acc = bg[gate*CC + o];
        #pragma unroll
        for (int c = 0; c < CC; c++) acc += wp[c] * a2[c];
        gc[(n*3 + gi)*CC + o] = acc;
    }
}

// ---------------------------------------------------------------------------
// Gates i,g,o (f dead: c_prev=0) + cell + hidden.
// Block: 256 = 64 px * 4 oc-groups; swi/swg transposed in smem, swo via __ldg.
// ---------------------------------------------------------------------------
__global__ __launch_bounds__(256) void gates_k(
    const float* __restrict__ A0, const float* __restrict__ Wproj,
    const float* __restrict__ gc, float* __restrict__ hout)
{
    __shared__ float swiT[CC*CC];  // [c][o]
    __shared__ float swgT[CC*CC];
    __shared__ float sx[CC][64];
    const int n  = blockIdx.y;
    const int p0 = blockIdx.x * 64;

    const float* Wi = Wproj + (0*4 + 0)*CC*CC;
    const float* Wg = Wproj + (2*4 + 0)*CC*CC;
    const float* Wo = Wproj + (3*4 + 0)*CC*CC;
    for (int idx = threadIdx.x; idx < CC*CC; idx += 256) {
        int o = idx & 63, c = idx >> 6;
        swiT[c*CC + o] = Wi[o*CC + c];
        swgT[c*CC + o] = Wg[o*CC + c];
        int px = idx & 63, ci = idx >> 6;
        sx[ci][px] = A0[(n*CC + ci)*PP + p0 + px];
    }
    __syncthreads();

    const int px  = threadIdx.x >> 2;
    const int ocg = threadIdx.x & 3;
    const float* gcn = gc + n*3*CC;

    float ai[16], ag[16], ao[16];
    #pragma unroll
    for (int u = 0; u < 16; u++) {
        int oc = ocg + 4*u;
        ai[u] = gcn[oc]; ag[u] = gcn[CC + oc]; ao[u] = gcn[2*CC + oc];
    }

    #pragma unroll 2
    for (int c = 0; c < CC; c++) {
        float xv = sx[c][px];
        #pragma unroll
        for (int u = 0; u < 16; u++) {
            int oc = ocg + 4*u;
            ai[u] += swiT[c*CC + oc] * xv;
            ag[u] += swgT[c*CC + oc] * xv;
            ao[u] += __ldg(Wo + oc*CC + c) * xv;
        }
    }

    #pragma unroll
    for (int u = 0; u < 16; u++) {
        int oc = ocg + 4*u;
        float ig = 1.f / (1.f + __expf(-ai[u]));
        float gg = tanhf(ag[u]);
        float og = 1.f / (1.f + __expf(-ao[u]));
        hout[(n*CC + oc)*PP + p0 + px] = og * tanhf(ig * gg);
    }
}

// ---------------------------------------------------------------------------
extern "C" void kernel_launch(void* const* d_in, const int* in_sizes, int n_in,
                              void* d_out, int out_size)
{
    const float* x     = (const float*)d_in[0];
    const float* W_in  = (const float*)d_in[1];
    const float* b_in  = (const float*)d_in[2];
    const float* Wq    = (const float*)d_in[3];
    const float* Wk    = (const float*)d_in[4];
    const float* Wv    = (const float*)d_in[5];
    const float* Wproj = (const float*)d_in[6];
    const float* b_g   = (const float*)d_in[7];
    const float* W_out = (const float*)d_in[8];
    const float* b_out = (const float*)d_in[9];
    float* out = (float*)d_out;

    void* sp = nullptr;
    cudaGetSymbolAddress(&sp, g_scratch);
    float* s = (float*)sp;

    const dim3 pwGrid(PP/64, NB);

    pointwise_k<<<pwGrid, 256>>>(x, W_in, b_in, s + OFF_XIN);
    conv4_k<<<dim3(HH, NB, 4), 256>>>(s + OFF_XIN, Wq, Wk, Wv,
                                      s + OFF_Q0, s + OFF_K0, s + OFF_V0, s + OFF_V2);
    attn_k<<<dim3(PP/128, NB*HEADS), 128>>>(s + OFF_Q0, s + OFF_K0, s + OFF_V0, s + OFF_A0);
    a2gc_k<<<NB, 256>>>(s + OFF_V2, Wproj, b_g, s + OFF_GC);
    gates_k<<<pwGrid, 256>>>(s + OFF_A0, Wproj, s + OFF_GC, s + OFF_HOUT);
    pointwise_k<<<pwGrid, 256>>>(s + OFF_HOUT, W_out, b_out, out);
}

// round 4
// speedup vs baseline: 2.4888x; 1.2999x over previous
#include <cuda_runtime.h>
#include <math.h>

// Problem constants
#define NB    4
#define CC    64
#define HEADS 4
#define HCH   16
#define HH    48
#define WW    48
#define PP    (HH*WW)     // 2304
#define VH    46
#define VW    46
#define DD    (VH*VW)     // 2116

// Scratch layout (floats)
#define OFF_XIN   0
#define OFF_Q0    (OFF_XIN  + NB*CC*PP)
#define OFF_A0    (OFF_Q0   + NB*CC*PP)
#define OFF_K0    (OFF_A0   + NB*CC*PP)
#define OFF_V0    (OFF_K0   + NB*CC*DD)
#define OFF_S     (OFF_V0   + NB*CC*DD)
#define OFF_GC    (OFF_S    + NB*CC*9)
#define SCRATCH_TOTAL (OFF_GC + NB*3*CC)

__device__ float g_scratch[SCRATCH_TOTAL];

// ---- packed fp32x2 helpers -------------------------------------------------
typedef unsigned long long u64t;

__device__ __forceinline__ u64t pack2(float a, float b) {
    u64t r; asm("mov.b64 %0, {%1,%2};" : "=l"(r) : "f"(a), "f"(b)); return r;
}
__device__ __forceinline__ float2 unpack2(u64t v) {
    float2 r; asm("mov.b64 {%0,%1}, %2;" : "=f"(r.x), "=f"(r.y) : "l"(v)); return r;
}
__device__ __forceinline__ u64t ffma2(u64t a, u64t b, u64t c) {
    u64t d; asm("fma.rn.f32x2 %0, %1, %2, %3;" : "=l"(d) : "l"(a), "l"(b), "l"(c)); return d;
}

// ---------------------------------------------------------------------------
// Pointwise 1x1 conv (input projection).
// ---------------------------------------------------------------------------
__global__ __launch_bounds__(256) void pointwise_k(
    const float* __restrict__ in, const float* __restrict__ wmat,
    const float* __restrict__ bias, float* __restrict__ out)
{
    __shared__ float swT[CC*CC];   // [c][o]
    __shared__ float sx[CC][64];   // [c][px]
    const int n  = blockIdx.y;
    const int p0 = blockIdx.x * 64;

    for (int idx = threadIdx.x; idx < CC*CC; idx += 256) {
        int o = idx & 63, c = idx >> 6;
        swT[c*CC + o] = wmat[o*CC + c];
        sx[c][o] = in[(n*CC + c)*PP + p0 + o];
    }
    __syncthreads();

    const int px  = threadIdx.x >> 2;
    const int ocg = threadIdx.x & 3;

    float acc[16];
    #pragma unroll
    for (int u = 0; u < 16; u++) acc[u] = bias[ocg + 4*u];

    #pragma unroll 4
    for (int c = 0; c < CC; c++) {
        float xv = sx[c][px];
        #pragma unroll
        for (int u = 0; u < 16; u++)
            acc[u] += swT[c*CC + ocg + 4*u] * xv;
    }

    #pragma unroll
    for (int u = 0; u < 16; u++)
        out[(n*CC + ocg + 4*u)*PP + p0 + px] = acc[u];
}

// ---------------------------------------------------------------------------
// Fused 3x3 convs: branch 0 = q (SAME), 1 = k (VALID), 2 = v (VALID).
// ---------------------------------------------------------------------------
__global__ __launch_bounds__(256) void conv3_k(
    const float* __restrict__ xin,
    const float* __restrict__ Wq, const float* __restrict__ Wk,
    const float* __restrict__ Wv,
    float* __restrict__ Q0, float* __restrict__ K0, float* __restrict__ V0)
{
    const int br = blockIdx.z;
    const int y  = blockIdx.x;
    const int n  = blockIdx.y;
    if (br != 0 && y >= VH) return;

    const float* wgt; float* out; int ow, ohw, ofs;
    if (br == 0)      { wgt = Wq; out = Q0; ow = WW; ohw = PP; ofs = -1; }
    else if (br == 1) { wgt = Wk; out = K0; ow = VW; ohw = DD; ofs = 0;  }
    else              { wgt = Wv; out = V0; ow = VW; ohw = DD; ofs = 0;  }

    __shared__ float tile[CC][3][52];
    const float* inN = xin + n*CC*PP;
    for (int idx = threadIdx.x; idx < CC*3*52; idx += 256) {
        int c = idx / 156, rem = idx % 156, r = rem / 52, j = rem % 52;
        int gy = y + r + ofs, gx = j + ofs;
        float v = 0.f;
        if (gy >= 0 && gy < HH && gx >= 0 && gx < WW)
            v = inN[c*PP + gy*WW + gx];
        tile[c][r][j] = v;
    }
    __syncthreads();

    const int oc = threadIdx.x >> 2;
    const int x0 = (threadIdx.x & 3) * 12;   // 16B aligned

    float acc[12];
    #pragma unroll
    for (int i = 0; i < 12; i++) acc[i] = 0.f;

    const float* wo = wgt + oc*(CC*9);
    #pragma unroll 2
    for (int c = 0; c < CC; c++) {
        #pragma unroll
        for (int r = 0; r < 3; r++) {
            const float4* t4 = (const float4*)&tile[c][r][x0];
            float4 a = t4[0], b = t4[1], d = t4[2], e = t4[3];
            float v[16] = {a.x,a.y,a.z,a.w, b.x,b.y,b.z,b.w,
                           d.x,d.y,d.z,d.w, e.x,e.y,e.z,e.w};
            float w0 = __ldg(wo + c*9 + r*3 + 0);
            float w1 = __ldg(wo + c*9 + r*3 + 1);
            float w2 = __ldg(wo + c*9 + r*3 + 2);
            #pragma unroll
            for (int xi = 0; xi < 12; xi++)
                acc[xi] += w0*v[xi] + w1*v[xi+1] + w2*v[xi+2];
        }
    }

    float* ob = out + (n*CC + oc)*ohw + y*ow;
    #pragma unroll
    for (int xi = 0; xi < 12; xi++) {
        int x = x0 + xi;
        if (x < ow) ob[x] = acc[xi];
    }
}

// ---------------------------------------------------------------------------
// Window sums: S[n,c,r,s] = sum of xin[n,c] over 46x46 window at offset (r,s).
// grid (CC, NB), block 256; parallel tree reduction.
// ---------------------------------------------------------------------------
__global__ __launch_bounds__(256) void winsum_k(
    const float* __restrict__ xin, float* __restrict__ S)
{
    const int c = blockIdx.x, n = blockIdx.y;
    const float* ib = xin + (n*CC + c)*PP;

    float rect[9];
    #pragma unroll
    for (int i = 0; i < 9; i++) rect[i] = 0.f;

    for (int idx = threadIdx.x; idx < PP; idx += 256) {
        int y = idx / WW, x = idx % WW;
        float v = ib[idx];
        int rlo = y - 45 > 0 ? y - 45 : 0;
        int rhi = y < 2 ? y : 2;
        int slo = x - 45 > 0 ? x - 45 : 0;
        int shi = x < 2 ? x : 2;
        for (int r = rlo; r <= rhi; r++)
            for (int s = slo; s <= shi; s++)
                rect[r*3 + s] += v;
    }
    // warp reduce
    #pragma unroll
    for (int i = 0; i < 9; i++) {
        #pragma unroll
        for (int off = 16; off > 0; off >>= 1)
            rect[i] += __shfl_xor_sync(0xffffffff, rect[i], off);
    }
    __shared__ float red[8][9];
    const int warp = threadIdx.x >> 5, lane = threadIdx.x & 31;
    if (lane == 0) {
        #pragma unroll
        for (int i = 0; i < 9; i++) red[warp][i] = rect[i];
    }
    __syncthreads();
    if (threadIdx.x < 9) {
        float s = 0.f;
        #pragma unroll
        for (int w = 0; w < 8; w++) s += red[w][threadIdx.x];
        S[(n*CC + c)*9 + threadIdx.x] = s;
    }
}

// ---------------------------------------------------------------------------
// Attention (branch 0), f32x2 packed along key dim.
// ---------------------------------------------------------------------------
#define DCH 92
__global__ __launch_bounds__(128) void attn_k(
    const float* __restrict__ q0, const float* __restrict__ k0,
    const float* __restrict__ v0, float* __restrict__ A0)
{
    __shared__ __align__(16) u64t sk2[HCH][DCH/2];
    __shared__ __align__(16) u64t sv2[HCH][DCH/2];

    const int nh = blockIdx.y;
    const int n = nh >> 2, head = nh & 3;
    const int q = blockIdx.x * 128 + threadIdx.x;

    const float* qb = q0 + (n*CC + head*HCH)*PP + q;
    u64t qv2[HCH];
    #pragma unroll
    for (int c = 0; c < HCH; c++) { float qc = qb[c*PP]; qv2[c] = pack2(qc, qc); }

    u64t acc2[HCH];
    #pragma unroll
    for (int c = 0; c < HCH; c++) acc2[c] = 0ULL;
    float l = 0.f;

    const float* kb = k0 + (n*CC + head*HCH)*DD;
    const float* vb = v0 + (n*CC + head*HCH)*DD;

    for (int d0 = 0; d0 < DD; d0 += DCH) {
        for (int idx = threadIdx.x; idx < HCH*(DCH/2)*2; idx += 128) {
            int half = idx >= HCH*(DCH/2);
            int i = idx - half*HCH*(DCH/2);
            int c = i / (DCH/2), jj = i % (DCH/2);
            const float* src = half ? vb : kb;
            u64t val = *(const u64t*)(src + c*DD + d0 + 2*jj);
            if (half) sv2[c][jj] = val; else sk2[c][jj] = val;
        }
        __syncthreads();

        #pragma unroll 1
        for (int jg = 0; jg < DCH/2; jg += 2) {
            u64t s2a = 0ULL, s2b = 0ULL;
            #pragma unroll
            for (int c = 0; c < HCH; c++) {
                ulonglong2 kk = *(const ulonglong2*)&sk2[c][jg];
                s2a = ffma2(qv2[c], kk.x, s2a);
                s2b = ffma2(qv2[c], kk.y, s2b);
            }
            float2 sa = unpack2(s2a), sb = unpack2(s2b);
            float p0 = __expf(sa.x), p1 = __expf(sa.y);
            float p2 = __expf(sb.x), p3 = __expf(sb.y);
            l += (p0 + p1) + (p2 + p3);
            u64t pA = pack2(p0, p1), pB = pack2(p2, p3);
            #pragma unroll
            for (int c = 0; c < HCH; c++) {
                ulonglong2 vv = *(const ulonglong2*)&sv2[c][jg];
                acc2[c] = ffma2(pA, vv.x, acc2[c]);
                acc2[c] = ffma2(pB, vv.y, acc2[c]);
            }
        }
        __syncthreads();
    }

    const float inv = 1.f / l;
    float* ab = A0 + (n*CC + head*HCH)*PP + q;
    #pragma unroll
    for (int c = 0; c < HCH; c++) {
        float2 a = unpack2(acc2[c]);
        ab[c*PP] = (a.x + a.y) * inv;
    }
}

// ---------------------------------------------------------------------------
// a2 from window sums + Wv[2], then gate bias constants. One block per n.
// a2[c] = (1/DD) * sum_{ci,t} Wv2[c,ci,t] * S[n,ci,t]
// ---------------------------------------------------------------------------
__global__ __launch_bounds__(256) void a2gc_k(
    const float* __restrict__ S, const float* __restrict__ Wv,
    const float* __restrict__ Wproj, const float* __restrict__ bg,
    float* __restrict__ gc)
{
    __shared__ float sS[CC*9];
    __shared__ float a2[CC];
    const int n = blockIdx.x;
    const int t = threadIdx.x;
    const float* Wv2 = Wv + 2*CC*CC*9;

    for (int i = t; i < CC*9; i += 256) sS[i] = S[n*CC*9 + i];
    __syncthreads();

    // 4 threads per output channel
    {
        const int o = t >> 2, part = t & 3;
        const float* wrow = Wv2 + o*(CC*9) + part*(16*9);
        const float* srow = sS + part*(16*9);
        float acc = 0.f;
        #pragma unroll 4
        for (int i = 0; i < 16*9; i++) acc += wrow[i] * srow[i];
        acc += __shfl_xor_sync(0xffffffff, acc, 1);
        acc += __shfl_xor_sync(0xffffffff, acc, 2);
        if (part == 0) a2[o] = acc * (1.f / (float)DD);
    }
    __syncthreads();

    if (t < 3*CC) {
        int gi = t / CC, o = t % CC;
        int gate = (gi == 0) ? 0 : (gi == 1 ? 2 : 3);
        const float* wp = Wproj + ((gate*4 + 2)*CC + o)*CC;
        float acc = bg[gate*CC + o];
        #pragma unroll
        for (int c = 0; c < CC; c++) acc += wp[c] * a2[c];
        gc[(n*3 + gi)*CC + o] = acc;
    }
}

// ---------------------------------------------------------------------------
// Gates i,g,o + cell + hidden + fused output 1x1 projection.
// ---------------------------------------------------------------------------
__global__ __launch_bounds__(256) void gates_out_k(
    const float* __restrict__ A0, const float* __restrict__ Wproj,
    const float* __restrict__ gc, const float* __restrict__ W_out,
    const float* __restrict__ b_out, float* __restrict__ out)
{
    __shared__ float swiT[CC*CC];  // [c][o] ; later reused for W_out^T
    __shared__ float swgT[CC*CC];
    __shared__ float sx[CC][64];   // A0 tile; later reused for hout
    const int n  = blockIdx.y;
    const int p0 = blockIdx.x * 64;

    const float* Wi = Wproj + (0*4 + 0)*CC*CC;
    const float* Wg = Wproj + (2*4 + 0)*CC*CC;
    const float* Wo = Wproj + (3*4 + 0)*CC*CC;
    for (int idx = threadIdx.x; idx < CC*CC; idx += 256) {
        int o = idx & 63, c = idx >> 6;
        swiT[c*CC + o] = Wi[o*CC + c];
        swgT[c*CC + o] = Wg[o*CC + c];
        sx[c][o] = A0[(n*CC + c)*PP + p0 + o];
    }
    __syncthreads();

    const int px  = threadIdx.x >> 2;
    const int ocg = threadIdx.x & 3;
    const float* gcn = gc + n*3*CC;

    float ai[16], ag[16], ao[16];
    #pragma unroll
    for (int u = 0; u < 16; u++) {
        int oc = ocg + 4*u;
        ai[u] = gcn[oc]; ag[u] = gcn[CC + oc]; ao[u] = gcn[2*CC + oc];
    }

    #pragma unroll 2
    for (int c = 0; c < CC; c++) {
        float xv = sx[c][px];
        #pragma unroll
        for (int u = 0; u < 16; u++) {
            int oc = ocg + 4*u;
            ai[u] += swiT[c*CC + oc] * xv;
            ag[u] += swgT[c*CC + oc] * xv;
            ao[u] += __ldg(Wo + oc*CC + c) * xv;
        }
    }

    float hv[16];
    #pragma unroll
    for (int u = 0; u < 16; u++) {
        float ig = 1.f / (1.f + __expf(-ai[u]));
        float gg = tanhf(ag[u]);
        float og = 1.f / (1.f + __expf(-ao[u]));
        hv[u] = og * tanhf(ig * gg);
    }

    __syncthreads();   // everyone done reading sx / swiT
    #pragma unroll
    for (int u = 0; u < 16; u++) sx[ocg + 4*u][px] = hv[u];
    for (int idx = threadIdx.x; idx < CC*CC; idx += 256) {
        int o = idx & 63, c = idx >> 6;
        swiT[c*CC + o] = W_out[o*CC + c];
    }
    __syncthreads();

    float acc[16];
    #pragma unroll
    for (int u = 0; u < 16; u++) acc[u] = b_out[ocg + 4*u];
    #pragma unroll 4
    for (int c = 0; c < CC; c++) {
        float xv = sx[c][px];
        #pragma unroll
        for (int u = 0; u < 16; u++)
            acc[u] += swiT[c*CC + ocg + 4*u] * xv;
    }
    #pragma unroll
    for (int u = 0; u < 16; u++)
        out[(n*CC + ocg + 4*u)*PP + p0 + px] = acc[u];
}

// ---------------------------------------------------------------------------
extern "C" void kernel_launch(void* const* d_in, const int* in_sizes, int n_in,
                              void* d_out, int out_size)
{
    const float* x     = (const float*)d_in[0];
    const float* W_in  = (const float*)d_in[1];
    const float* b_in  = (const float*)d_in[2];
    const float* Wq    = (const float*)d_in[3];
    const float* Wk    = (const float*)d_in[4];
    const float* Wv    = (const float*)d_in[5];
    const float* Wproj = (const float*)d_in[6];
    const float* b_g   = (const float*)d_in[7];
    const float* W_out = (const float*)d_in[8];
    const float* b_out = (const float*)d_in[9];
    float* out = (float*)d_out;

    void* sp = nullptr;
    cudaGetSymbolAddress(&sp, g_scratch);
    float* s = (float*)sp;

    const dim3 pwGrid(PP/64, NB);

    pointwise_k<<<pwGrid, 256>>>(x, W_in, b_in, s + OFF_XIN);
    conv3_k<<<dim3(HH, NB, 3), 256>>>(s + OFF_XIN, Wq, Wk, Wv,
                                      s + OFF_Q0, s + OFF_K0, s + OFF_V0);
    winsum_k<<<dim3(CC, NB), 256>>>(s + OFF_XIN, s + OFF_S);
    attn_k<<<dim3(PP/128, NB*HEADS), 128>>>(s + OFF_Q0, s + OFF_K0, s + OFF_V0, s + OFF_A0);
    a2gc_k<<<NB, 256>>>(s + OFF_S, Wv, Wproj, b_g, s + OFF_GC);
    gates_out_k<<<pwGrid, 256>>>(s + OFF_A0, Wproj, s + OFF_GC, W_out, b_out, out);
}

// round 5
// speedup vs baseline: 2.5414x; 1.0212x over previous
#include <cuda_runtime.h>
#include <math.h>

// Problem constants
#define NB    4
#define CC    64
#define HEADS 4
#define HCH   16
#define HH    48
#define WW    48
#define PP    (HH*WW)     // 2304
#define VH    46
#define VW    46
#define DD    (VH*VW)     // 2116

#define SPLIT 6           // key-dim split for attention

// Scratch layout (floats)
#define OFF_XIN   0
#define OFF_Q0    (OFF_XIN  + NB*CC*PP)
#define OFF_A0    (OFF_Q0   + NB*CC*PP)
#define OFF_K0    (OFF_A0   + NB*CC*PP)
#define OFF_V0    (OFF_K0   + NB*CC*DD)
#define OFF_S     (OFF_V0   + NB*CC*DD)
#define OFF_GC    (OFF_S    + NB*CC*9)
#define OFF_PART  (OFF_GC   + NB*3*CC)
#define SCRATCH_TOTAL (OFF_PART + SPLIT*NB*HEADS*17*PP)

__device__ float g_scratch[SCRATCH_TOTAL];

// ---- packed fp32x2 helpers -------------------------------------------------
typedef unsigned long long u64t;

__device__ __forceinline__ u64t pack2(float a, float b) {
    u64t r; asm("mov.b64 %0, {%1,%2};" : "=l"(r) : "f"(a), "f"(b)); return r;
}
__device__ __forceinline__ float2 unpack2(u64t v) {
    float2 r; asm("mov.b64 {%0,%1}, %2;" : "=f"(r.x), "=f"(r.y) : "l"(v)); return r;
}
__device__ __forceinline__ u64t ffma2(u64t a, u64t b, u64t c) {
    u64t d; asm("fma.rn.f32x2 %0, %1, %2, %3;" : "=l"(d) : "l"(a), "l"(b), "l"(c)); return d;
}

// ---------------------------------------------------------------------------
// Pointwise 1x1 conv (input projection).
// ---------------------------------------------------------------------------
__global__ __launch_bounds__(256) void pointwise_k(
    const float* __restrict__ in, const float* __restrict__ wmat,
    const float* __restrict__ bias, float* __restrict__ out)
{
    __shared__ float swT[CC*CC];   // [c][o]
    __shared__ float sx[CC][64];   // [c][px]
    const int n  = blockIdx.y;
    const int p0 = blockIdx.x * 64;

    for (int idx = threadIdx.x; idx < CC*CC; idx += 256) {
        int o = idx & 63, c = idx >> 6;
        swT[c*CC + o] = wmat[o*CC + c];
        sx[c][o] = in[(n*CC + c)*PP + p0 + o];
    }
    __syncthreads();

    const int px  = threadIdx.x >> 2;
    const int ocg = threadIdx.x & 3;

    float acc[16];
    #pragma unroll
    for (int u = 0; u < 16; u++) acc[u] = bias[ocg + 4*u];

    #pragma unroll 4
    for (int c = 0; c < CC; c++) {
        float xv = sx[c][px];
        #pragma unroll
        for (int u = 0; u < 16; u++)
            acc[u] += swT[c*CC + ocg + 4*u] * xv;
    }

    #pragma unroll
    for (int u = 0; u < 16; u++)
        out[(n*CC + ocg + 4*u)*PP + p0 + px] = acc[u];
}

// ---------------------------------------------------------------------------
// Fused 3x3 convs: branch 0 = q (SAME), 1 = k (VALID), 2 = v (VALID).
// ---------------------------------------------------------------------------
__global__ __launch_bounds__(256) void conv3_k(
    const float* __restrict__ xin,
    const float* __restrict__ Wq, const float* __restrict__ Wk,
    const float* __restrict__ Wv,
    float* __restrict__ Q0, float* __restrict__ K0, float* __restrict__ V0)
{
    const int br = blockIdx.z;
    const int y  = blockIdx.x;
    const int n  = blockIdx.y;
    if (br != 0 && y >= VH) return;

    const float* wgt; float* out; int ow, ohw, ofs;
    if (br == 0)      { wgt = Wq; out = Q0; ow = WW; ohw = PP; ofs = -1; }
    else if (br == 1) { wgt = Wk; out = K0; ow = VW; ohw = DD; ofs = 0;  }
    else              { wgt = Wv; out = V0; ow = VW; ohw = DD; ofs = 0;  }

    __shared__ float tile[CC][3][52];
    const float* inN = xin + n*CC*PP;
    for (int idx = threadIdx.x; idx < CC*3*52; idx += 256) {
        int c = idx / 156, rem = idx % 156, r = rem / 52, j = rem % 52;
        int gy = y + r + ofs, gx = j + ofs;
        float v = 0.f;
        if (gy >= 0 && gy < HH && gx >= 0 && gx < WW)
            v = inN[c*PP + gy*WW + gx];
        tile[c][r][j] = v;
    }
    __syncthreads();

    const int oc = threadIdx.x >> 2;
    const int x0 = (threadIdx.x & 3) * 12;   // 16B aligned

    float acc[12];
    #pragma unroll
    for (int i = 0; i < 12; i++) acc[i] = 0.f;

    const float* wo = wgt + oc*(CC*9);
    #pragma unroll 2
    for (int c = 0; c < CC; c++) {
        #pragma unroll
        for (int r = 0; r < 3; r++) {
            const float4* t4 = (const float4*)&tile[c][r][x0];
            float4 a = t4[0], b = t4[1], d = t4[2], e = t4[3];
            float v[16] = {a.x,a.y,a.z,a.w, b.x,b.y,b.z,b.w,
                           d.x,d.y,d.z,d.w, e.x,e.y,e.z,e.w};
            float w0 = __ldg(wo + c*9 + r*3 + 0);
            float w1 = __ldg(wo + c*9 + r*3 + 1);
            float w2 = __ldg(wo + c*9 + r*3 + 2);
            #pragma unroll
            for (int xi = 0; xi < 12; xi++)
                acc[xi] += w0*v[xi] + w1*v[xi+1] + w2*v[xi+2];
        }
    }

    float* ob = out + (n*CC + oc)*ohw + y*ow;
    #pragma unroll
    for (int xi = 0; xi < 12; xi++) {
        int x = x0 + xi;
        if (x < ow) ob[x] = acc[xi];
    }
}

// ---------------------------------------------------------------------------
// Window sums: S[n,c,r,s] = sum of xin[n,c] over 46x46 window at offset (r,s).
// ---------------------------------------------------------------------------
__global__ __launch_bounds__(256) void winsum_k(
    const float* __restrict__ xin, float* __restrict__ S)
{
    const int c = blockIdx.x, n = blockIdx.y;
    const float* ib = xin + (n*CC + c)*PP;

    float rect[9];
    #pragma unroll
    for (int i = 0; i < 9; i++) rect[i] = 0.f;

    for (int idx = threadIdx.x; idx < PP; idx += 256) {
        int y = idx / WW, x = idx % WW;
        float v = ib[idx];
        int rlo = y - 45 > 0 ? y - 45 : 0;
        int rhi = y < 2 ? y : 2;
        int slo = x - 45 > 0 ? x - 45 : 0;
        int shi = x < 2 ? x : 2;
        for (int r = rlo; r <= rhi; r++)
            for (int s = slo; s <= shi; s++)
                rect[r*3 + s] += v;
    }
    #pragma unroll
    for (int i = 0; i < 9; i++) {
        #pragma unroll
        for (int off = 16; off > 0; off >>= 1)
            rect[i] += __shfl_xor_sync(0xffffffff, rect[i], off);
    }
    __shared__ float red[8][9];
    const int warp = threadIdx.x >> 5, lane = threadIdx.x & 31;
    if (lane == 0) {
        #pragma unroll
        for (int i = 0; i < 9; i++) red[warp][i] = rect[i];
    }
    __syncthreads();
    if (threadIdx.x < 9) {
        float s = 0.f;
        #pragma unroll
        for (int w = 0; w < 8; w++) s += red[w][threadIdx.x];
        S[(n*CC + c)*9 + threadIdx.x] = s;
    }
}

// ---------------------------------------------------------------------------
// Attention (branch 0), f32x2 packed along key dim, split-K over SPLIT blocks.
// Block z handles key-chunks it = z, z+SPLIT, ... (23 chunks of 92 keys).
// Writes un-normalized partials (16 sums + l) to part[].
// ---------------------------------------------------------------------------
#define DCH 92
__global__ __launch_bounds__(128) void attn_k(
    const float* __restrict__ q0, const float* __restrict__ k0,
    const float* __restrict__ v0, float* __restrict__ part)
{
    __shared__ __align__(16) u64t sk2[HCH][DCH/2];
    __shared__ __align__(16) u64t sv2[HCH][DCH/2];

    const int nh = blockIdx.y;
    const int z  = blockIdx.z;
    const int n = nh >> 2, head = nh & 3;
    const int q = blockIdx.x * 128 + threadIdx.x;

    const float* qb = q0 + (n*CC + head*HCH)*PP + q;
    u64t qv2[HCH];
    #pragma unroll
    for (int c = 0; c < HCH; c++) { float qc = qb[c*PP]; qv2[c] = pack2(qc, qc); }

    u64t acc2[HCH];
    #pragma unroll
    for (int c = 0; c < HCH; c++) acc2[c] = 0ULL;
    float l = 0.f;

    const float* kb = k0 + (n*CC + head*HCH)*DD;
    const float* vb = v0 + (n*CC + head*HCH)*DD;

    for (int it = z; it < DD/DCH; it += SPLIT) {
        const int d0 = it * DCH;
        for (int idx = threadIdx.x; idx < HCH*(DCH/2)*2; idx += 128) {
            int half = idx >= HCH*(DCH/2);
            int i = idx - half*HCH*(DCH/2);
            int c = i / (DCH/2), jj = i % (DCH/2);
            const float* src = half ? vb : kb;
            u64t val = *(const u64t*)(src + c*DD + d0 + 2*jj);
            if (half) sv2[c][jj] = val; else sk2[c][jj] = val;
        }
        __syncthreads();

        #pragma unroll 1
        for (int jg = 0; jg < DCH/2; jg += 2) {
            u64t s2a = 0ULL, s2b = 0ULL;
            #pragma unroll
            for (int c = 0; c < HCH; c++) {
                ulonglong2 kk = *(const ulonglong2*)&sk2[c][jg];
                s2a = ffma2(qv2[c], kk.x, s2a);
                s2b = ffma2(qv2[c], kk.y, s2b);
            }
            float2 sa = unpack2(s2a), sb = unpack2(s2b);
            float p0 = __expf(sa.x), p1 = __expf(sa.y);
            float p2 = __expf(sb.x), p3 = __expf(sb.y);
            l += (p0 + p1) + (p2 + p3);
            u64t pA = pack2(p0, p1), pB = pack2(p2, p3);
            #pragma unroll
            for (int c = 0; c < HCH; c++) {
                ulonglong2 vv = *(const ulonglong2*)&sv2[c][jg];
                acc2[c] = ffma2(pA, vv.x, acc2[c]);
                acc2[c] = ffma2(pB, vv.y, acc2[c]);
            }
        }
        __syncthreads();
    }

    float* pb = part + ((z*(NB*HEADS) + nh)*17)*PP + q;
    #pragma unroll
    for (int c = 0; c < HCH; c++) {
        float2 a = unpack2(acc2[c]);
        pb[c*PP] = a.x + a.y;
    }
    pb[16*PP] = l;
}

// ---------------------------------------------------------------------------
// Combine split-K partials: A0 = (sum_z acc_z) / (sum_z l_z).
// ---------------------------------------------------------------------------
__global__ __launch_bounds__(128) void combine_k(
    const float* __restrict__ part, float* __restrict__ A0)
{
    const int nh = blockIdx.y;
    const int n = nh >> 2, head = nh & 3;
    const int q = blockIdx.x * 128 + threadIdx.x;

    float s[HCH];
    #pragma unroll
    for (int c = 0; c < HCH; c++) s[c] = 0.f;
    float l = 0.f;

    #pragma unroll
    for (int z = 0; z < SPLIT; z++) {
        const float* pb = part + ((z*(NB*HEADS) + nh)*17)*PP + q;
        l += pb[16*PP];
        #pragma unroll
        for (int c = 0; c < HCH; c++) s[c] += pb[c*PP];
    }
    const float inv = 1.f / l;
    float* ab = A0 + (n*CC + head*HCH)*PP + q;
    #pragma unroll
    for (int c = 0; c < HCH; c++) ab[c*PP] = s[c] * inv;
}

// ---------------------------------------------------------------------------
// a2 from window sums + Wv[2], then gate bias constants. One block per n.
// ---------------------------------------------------------------------------
__global__ __launch_bounds__(256) void a2gc_k(
    const float* __restrict__ S, const float* __restrict__ Wv,
    const float* __restrict__ Wproj, const float* __restrict__ bg,
    float* __restrict__ gc)
{
    __shared__ float sS[CC*9];
    __shared__ float a2[CC];
    const int n = blockIdx.x;
    const int t = threadIdx.x;
    const float* Wv2 = Wv + 2*CC*CC*9;

    for (int i = t; i < CC*9; i += 256) sS[i] = S[n*CC*9 + i];
    __syncthreads();

    {
        const int o = t >> 2, part = t & 3;
        const float* wrow = Wv2 + o*(CC*9) + part*(16*9);
        const float* srow = sS + part*(16*9);
        float acc = 0.f;
        #pragma unroll 4
        for (int i = 0; i < 16*9; i++) acc += wrow[i] * srow[i];
        acc += __shfl_xor_sync(0xffffffff, acc, 1);
        acc += __shfl_xor_sync(0xffffffff, acc, 2);
        if (part == 0) a2[o] = acc * (1.f / (float)DD);
    }
    __syncthreads();

    if (t < 3*CC) {
        int gi = t / CC, o = t % CC;
        int gate = (gi == 0) ? 0 : (gi == 1 ? 2 : 3);
        const float* wp = Wproj + ((gate*4 + 2)*CC + o)*CC;
        float acc = bg[gate*CC + o];
        #pragma unroll
        for (int c = 0; c < CC; c++) acc += wp[c] * a2[c];
        gc[(n*3 + gi)*CC + o] = acc;
    }
}

// ---------------------------------------------------------------------------
// Gates i,g,o + cell + hidden + fused output 1x1 projection.
// ---------------------------------------------------------------------------
__global__ __launch_bounds__(256) void gates_out_k(
    const float* __restrict__ A0, const float* __restrict__ Wproj,
    const float* __restrict__ gc, const float* __restrict__ W_out,
    const float* __restrict__ b_out, float* __restrict__ out)
{
    __shared__ float swiT[CC*CC];  // [c][o] ; later reused for W_out^T
    __shared__ float swgT[CC*CC];
    __shared__ float sx[CC][64];   // A0 tile; later reused for hout
    const int n  = blockIdx.y;
    const int p0 = blockIdx.x * 64;

    const float* Wi = Wproj + (0*4 + 0)*CC*CC;
    const float* Wg = Wproj + (2*4 + 0)*CC*CC;
    const float* Wo = Wproj + (3*4 + 0)*CC*CC;
    for (int idx = threadIdx.x; idx < CC*CC; idx += 256) {
        int o = idx & 63, c = idx >> 6;
        swiT[c*CC + o] = Wi[o*CC + c];
        swgT[c*CC + o] = Wg[o*CC + c];
        sx[c][o] = A0[(n*CC + c)*PP + p0 + o];
    }
    __syncthreads();

    const int px  = threadIdx.x >> 2;
    const int ocg = threadIdx.x & 3;
    const float* gcn = gc + n*3*CC;

    float ai[16], ag[16], ao[16];
    #pragma unroll
    for (int u = 0; u < 16; u++) {
        int oc = ocg + 4*u;
        ai[u] = gcn[oc]; ag[u] = gcn[CC + oc]; ao[u] = gcn[2*CC + oc];
    }

    #pragma unroll 2
    for (int c = 0; c < CC; c++) {
        float xv = sx[c][px];
        #pragma unroll
        for (int u = 0; u < 16; u++) {
            int oc = ocg + 4*u;
            ai[u] += swiT[c*CC + oc] * xv;
            ag[u] += swgT[c*CC + oc] * xv;
            ao[u] += __ldg(Wo + oc*CC + c) * xv;
        }
    }

    float hv[16];
    #pragma unroll
    for (int u = 0; u < 16; u++) {
        float ig = 1.f / (1.f + __expf(-ai[u]));
        float gg = tanhf(ag[u]);
        float og = 1.f / (1.f + __expf(-ao[u]));
        hv[u] = og * tanhf(ig * gg);
    }

    __syncthreads();
    #pragma unroll
    for (int u = 0; u < 16; u++) sx[ocg + 4*u][px] = hv[u];
    for (int idx = threadIdx.x; idx < CC*CC; idx += 256) {
        int o = idx & 63, c = idx >> 6;
        swiT[c*CC + o] = W_out[o*CC + c];
    }
    __syncthreads();

    float acc[16];
    #pragma unroll
    for (int u = 0; u < 16; u++) acc[u] = b_out[ocg + 4*u];
    #pragma unroll 4
    for (int c = 0; c < CC; c++) {
        float xv = sx[c][px];
        #pragma unroll
        for (int u = 0; u < 16; u++)
            acc[u] += swiT[c*CC + ocg + 4*u] * xv;
    }
    #pragma unroll
    for (int u = 0; u < 16; u++)
        out[(n*CC + ocg + 4*u)*PP + p0 + px] = acc[u];
}

// ---------------------------------------------------------------------------
extern "C" void kernel_launch(void* const* d_in, const int* in_sizes, int n_in,
                              void* d_out, int out_size)
{
    const float* x     = (const float*)d_in[0];
    const float* W_in  = (const float*)d_in[1];
    const float* b_in  = (const float*)d_in[2];
    const float* Wq    = (const float*)d_in[3];
    const float* Wk    = (const float*)d_in[4];
    const float* Wv    = (const float*)d_in[5];
    const float* Wproj = (const float*)d_in[6];
    const float* b_g   = (const float*)d_in[7];
    const float* W_out = (const float*)d_in[8];
    const float* b_out = (const float*)d_in[9];
    float* out = (float*)d_out;

    void* sp = nullptr;
    cudaGetSymbolAddress(&sp, g_scratch);
    float* s = (float*)sp;

    const dim3 pwGrid(PP/64, NB);

    pointwise_k<<<pwGrid, 256>>>(x, W_in, b_in, s + OFF_XIN);
    conv3_k<<<dim3(HH, NB, 3), 256>>>(s + OFF_XIN, Wq, Wk, Wv,
                                      s + OFF_Q0, s + OFF_K0, s + OFF_V0);
    winsum_k<<<dim3(CC, NB), 256>>>(s + OFF_XIN, s + OFF_S);
    attn_k<<<dim3(PP/128, NB*HEADS, SPLIT), 128>>>(s + OFF_Q0, s + OFF_K0,
                                                   s + OFF_V0, s + OFF_PART);
    combine_k<<<dim3(PP/128, NB*HEADS), 128>>>(s + OFF_PART, s + OFF_A0);
    a2gc_k<<<NB, 256>>>(s + OFF_S, Wv, Wproj, b_g, s + OFF_GC);
    gates_out_k<<<pwGrid, 256>>>(s + OFF_A0, Wproj, s + OFF_GC, W_out, b_out, out);
}

// round 6
// speedup vs baseline: 2.7534x; 1.0834x over previous
#include <cuda_runtime.h>
#include <math.h>

// Problem constants
#define NB    4
#define CC    64
#define HEADS 4
#define HCH   16
#define HH    48
#define WW    48
#define PP    (HH*WW)     // 2304
#define VH    46
#define VW    46
#define DD    (VH*VW)     // 2116

#define SPLIT 6           // key-dim split for attention

// Scratch layout (floats)
#define OFF_XIN   0
#define OFF_Q0    (OFF_XIN  + NB*CC*PP)
#define OFF_A0    (OFF_Q0   + NB*CC*PP)
#define OFF_K0    (OFF_A0   + NB*CC*PP)
#define OFF_V0    (OFF_K0   + NB*CC*DD)
#define OFF_S     (OFF_V0   + NB*CC*DD)
#define OFF_GC    (OFF_S    + NB*CC*9)
#define OFF_PART  (OFF_GC   + NB*3*CC)
#define SCRATCH_TOTAL (OFF_PART + SPLIT*NB*HEADS*17*PP)

__device__ float g_scratch[SCRATCH_TOTAL];

// ---- packed fp32x2 helpers -------------------------------------------------
typedef unsigned long long u64t;

__device__ __forceinline__ u64t pack2(float a, float b) {
    u64t r; asm("mov.b64 %0, {%1,%2};" : "=l"(r) : "f"(a), "f"(b)); return r;
}
__device__ __forceinline__ float2 unpack2(u64t v) {
    float2 r; asm("mov.b64 {%0,%1}, %2;" : "=f"(r.x), "=f"(r.y) : "l"(v)); return r;
}
__device__ __forceinline__ u64t ffma2(u64t a, u64t b, u64t c) {
    u64t d; asm("fma.rn.f32x2 %0, %1, %2, %3;" : "=l"(d) : "l"(a), "l"(b), "l"(c)); return d;
}

// ---------------------------------------------------------------------------
// Pointwise 1x1 conv (input projection).
// ---------------------------------------------------------------------------
__global__ __launch_bounds__(256) void pointwise_k(
    const float* __restrict__ in, const float* __restrict__ wmat,
    const float* __restrict__ bias, float* __restrict__ out)
{
    __shared__ float swT[CC*CC];   // [c][o]
    __shared__ float sx[CC][64];   // [c][px]
    const int n  = blockIdx.y;
    const int p0 = blockIdx.x * 64;

    for (int idx = threadIdx.x; idx < CC*CC; idx += 256) {
        int o = idx & 63, c = idx >> 6;
        swT[c*CC + o] = wmat[o*CC + c];
        sx[c][o] = in[(n*CC + c)*PP + p0 + o];
    }
    __syncthreads();

    const int px  = threadIdx.x >> 2;
    const int ocg = threadIdx.x & 3;

    float acc[16];
    #pragma unroll
    for (int u = 0; u < 16; u++) acc[u] = bias[ocg + 4*u];

    #pragma unroll 4
    for (int c = 0; c < CC; c++) {
        float xv = sx[c][px];
        #pragma unroll
        for (int u = 0; u < 16; u++)
            acc[u] += swT[c*CC + ocg + 4*u] * xv;
    }

    #pragma unroll
    for (int u = 0; u < 16; u++)
        out[(n*CC + ocg + 4*u)*PP + p0 + px] = acc[u];
}

// ---------------------------------------------------------------------------
// Fused 3x3 convs: branch 0 = q (SAME), 1 = k (VALID), 2 = v (VALID).
// ---------------------------------------------------------------------------
__global__ __launch_bounds__(256) void conv3_k(
    const float* __restrict__ xin,
    const float* __restrict__ Wq, const float* __restrict__ Wk,
    const float* __restrict__ Wv,
    float* __restrict__ Q0, float* __restrict__ K0, float* __restrict__ V0)
{
    const int br = blockIdx.z;
    const int y  = blockIdx.x;
    const int n  = blockIdx.y;
    if (br != 0 && y >= VH) return;

    const float* wgt; float* out; int ow, ohw, ofs;
    if (br == 0)      { wgt = Wq; out = Q0; ow = WW; ohw = PP; ofs = -1; }
    else if (br == 1) { wgt = Wk; out = K0; ow = VW; ohw = DD; ofs = 0;  }
    else              { wgt = Wv; out = V0; ow = VW; ohw = DD; ofs = 0;  }

    __shared__ float tile[CC][3][52];
    const float* inN = xin + n*CC*PP;
    for (int idx = threadIdx.x; idx < CC*3*52; idx += 256) {
        int c = idx / 156, rem = idx % 156, r = rem / 52, j = rem % 52;
        int gy = y + r + ofs, gx = j + ofs;
        float v = 0.f;
        if (gy >= 0 && gy < HH && gx >= 0 && gx < WW)
            v = inN[c*PP + gy*WW + gx];
        tile[c][r][j] = v;
    }
    __syncthreads();

    const int oc = threadIdx.x >> 2;
    const int x0 = (threadIdx.x & 3) * 12;   // 16B aligned

    float acc[12];
    #pragma unroll
    for (int i = 0; i < 12; i++) acc[i] = 0.f;

    const float* wo = wgt + oc*(CC*9);
    #pragma unroll 2
    for (int c = 0; c < CC; c++) {
        #pragma unroll
        for (int r = 0; r < 3; r++) {
            const float4* t4 = (const float4*)&tile[c][r][x0];
            float4 a = t4[0], b = t4[1], d = t4[2], e = t4[3];
            float v[16] = {a.x,a.y,a.z,a.w, b.x,b.y,b.z,b.w,
                           d.x,d.y,d.z,d.w, e.x,e.y,e.z,e.w};
            float w0 = __ldg(wo + c*9 + r*3 + 0);
            float w1 = __ldg(wo + c*9 + r*3 + 1);
            float w2 = __ldg(wo + c*9 + r*3 + 2);
            #pragma unroll
            for (int xi = 0; xi < 12; xi++)
                acc[xi] += w0*v[xi] + w1*v[xi+1] + w2*v[xi+2];
        }
    }

    float* ob = out + (n*CC + oc)*ohw + y*ow;
    #pragma unroll
    for (int xi = 0; xi < 12; xi++) {
        int x = x0 + xi;
        if (x < ow) ob[x] = acc[xi];
    }
}

// ---------------------------------------------------------------------------
// Window sums: S[n,c,r,s] = sum of xin[n,c] over 46x46 window at offset (r,s).
// ---------------------------------------------------------------------------
__global__ __launch_bounds__(256) void winsum_k(
    const float* __restrict__ xin, float* __restrict__ S)
{
    const int c = blockIdx.x, n = blockIdx.y;
    const float* ib = xin + (n*CC + c)*PP;

    float rect[9];
    #pragma unroll
    for (int i = 0; i < 9; i++) rect[i] = 0.f;

    for (int idx = threadIdx.x; idx < PP; idx += 256) {
        int y = idx / WW, x = idx % WW;
        float v = ib[idx];
        int rlo = y - 45 > 0 ? y - 45 : 0;
        int rhi = y < 2 ? y : 2;
        int slo = x - 45 > 0 ? x - 45 : 0;
        int shi = x < 2 ? x : 2;
        for (int r = rlo; r <= rhi; r++)
            for (int s = slo; s <= shi; s++)
                rect[r*3 + s] += v;
    }
    #pragma unroll
    for (int i = 0; i < 9; i++) {
        #pragma unroll
        for (int off = 16; off > 0; off >>= 1)
            rect[i] += __shfl_xor_sync(0xffffffff, rect[i], off);
    }
    __shared__ float red[8][9];
    const int warp = threadIdx.x >> 5, lane = threadIdx.x & 31;
    if (lane == 0) {
        #pragma unroll
        for (int i = 0; i < 9; i++) red[warp][i] = rect[i];
    }
    __syncthreads();
    if (threadIdx.x < 9) {
        float s = 0.f;
        #pragma unroll
        for (int w = 0; w < 8; w++) s += red[w][threadIdx.x];
        S[(n*CC + c)*9 + threadIdx.x] = s;
    }
}

// ---------------------------------------------------------------------------
// Attention (branch 0), f32x2 packed along key dim, split-K over SPLIT blocks,
// query-blocked x2: each thread owns queries qA and qB = qA+128, so every
// staged k/v register load feeds both queries' FFMA2s (LDS per query halved).
// ---------------------------------------------------------------------------
#define DCH 92
__global__ __launch_bounds__(128) void attn_k(
    const float* __restrict__ q0, const float* __restrict__ k0,
    const float* __restrict__ v0, float* __restrict__ part)
{
    __shared__ __align__(16) u64t sk2[HCH][DCH/2];
    __shared__ __align__(16) u64t sv2[HCH][DCH/2];

    const int nh = blockIdx.y;
    const int z  = blockIdx.z;
    const int n = nh >> 2, head = nh & 3;
    const int qA = blockIdx.x * 256 + threadIdx.x;
    const int qB = qA + 128;

    const float* qbase = q0 + (n*CC + head*HCH)*PP;
    u64t qvA[HCH], qvB[HCH];
    #pragma unroll
    for (int c = 0; c < HCH; c++) {
        float a = qbase[c*PP + qA]; qvA[c] = pack2(a, a);
        float b = qbase[c*PP + qB]; qvB[c] = pack2(b, b);
    }

    u64t accA[HCH], accB[HCH];
    #pragma unroll
    for (int c = 0; c < HCH; c++) { accA[c] = 0ULL; accB[c] = 0ULL; }
    float lA = 0.f, lB = 0.f;

    const float* kb = k0 + (n*CC + head*HCH)*DD;
    const float* vb = v0 + (n*CC + head*HCH)*DD;

    for (int it = z; it < DD/DCH; it += SPLIT) {
        const int d0 = it * DCH;
        for (int idx = threadIdx.x; idx < HCH*(DCH/2)*2; idx += 128) {
            int half = idx >= HCH*(DCH/2);
            int i = idx - half*HCH*(DCH/2);
            int c = i / (DCH/2), jj = i % (DCH/2);
            const float* src = half ? vb : kb;
            u64t val = *(const u64t*)(src + c*DD + d0 + 2*jj);
            if (half) sv2[c][jj] = val; else sk2[c][jj] = val;
        }
        __syncthreads();

        #pragma unroll 1
        for (int jg = 0; jg < DCH/2; jg += 2) {      // 4 keys per iteration
            u64t sAa = 0ULL, sAb = 0ULL, sBa = 0ULL, sBb = 0ULL;
            #pragma unroll
            for (int c = 0; c < HCH; c++) {
                ulonglong2 kk = *(const ulonglong2*)&sk2[c][jg];
                sAa = ffma2(qvA[c], kk.x, sAa);
                sAb = ffma2(qvA[c], kk.y, sAb);
                sBa = ffma2(qvB[c], kk.x, sBa);
                sBb = ffma2(qvB[c], kk.y, sBb);
            }
            float2 a0 = unpack2(sAa), a1 = unpack2(sAb);
            float2 b0 = unpack2(sBa), b1 = unpack2(sBb);
            float pA0 = __expf(a0.x), pA1 = __expf(a0.y);
            float pA2 = __expf(a1.x), pA3 = __expf(a1.y);
            float pB0 = __expf(b0.x), pB1 = __expf(b0.y);
            float pB2 = __expf(b1.x), pB3 = __expf(b1.y);
            lA += (pA0 + pA1) + (pA2 + pA3);
            lB += (pB0 + pB1) + (pB2 + pB3);
            u64t pAx = pack2(pA0, pA1), pAy = pack2(pA2, pA3);
            u64t pBx = pack2(pB0, pB1), pBy = pack2(pB2, pB3);
            #pragma unroll
            for (int c = 0; c < HCH; c++) {
                ulonglong2 vv = *(const ulonglong2*)&sv2[c][jg];
                accA[c] = ffma2(pAx, vv.x, accA[c]);
                accA[c] = ffma2(pAy, vv.y, accA[c]);
                accB[c] = ffma2(pBx, vv.x, accB[c]);
                accB[c] = ffma2(pBy, vv.y, accB[c]);
            }
        }
        __syncthreads();
    }

    float* pb = part + ((z*(NB*HEADS) + nh)*17)*PP;
    #pragma unroll
    for (int c = 0; c < HCH; c++) {
        float2 a = unpack2(accA[c]);
        float2 b = unpack2(accB[c]);
        pb[c*PP + qA] = a.x + a.y;
        pb[c*PP + qB] = b.x + b.y;
    }
    pb[16*PP + qA] = lA;
    pb[16*PP + qB] = lB;
}

// ---------------------------------------------------------------------------
// Combine split-K partials: A0 = (sum_z acc_z) / (sum_z l_z).
// ---------------------------------------------------------------------------
__global__ __launch_bounds__(128) void combine_k(
    const float* __restrict__ part, float* __restrict__ A0)
{
    const int nh = blockIdx.y;
    const int n = nh >> 2, head = nh & 3;
    const int q = blockIdx.x * 128 + threadIdx.x;

    float s[HCH];
    #pragma unroll
    for (int c = 0; c < HCH; c++) s[c] = 0.f;
    float l = 0.f;

    #pragma unroll
    for (int z = 0; z < SPLIT; z++) {
        const float* pb = part + ((z*(NB*HEADS) + nh)*17)*PP + q;
        l += pb[16*PP];
        #pragma unroll
        for (int c = 0; c < HCH; c++) s[c] += pb[c*PP];
    }
    const float inv = 1.f / l;
    float* ab = A0 + (n*CC + head*HCH)*PP + q;
    #pragma unroll
    for (int c = 0; c < HCH; c++) ab[c*PP] = s[c] * inv;
}

// ---------------------------------------------------------------------------
// a2 from window sums + Wv[2], then gate bias constants. One block per n.
// ---------------------------------------------------------------------------
__global__ __launch_bounds__(256) void a2gc_k(
    const float* __restrict__ S, const float* __restrict__ Wv,
    const float* __restrict__ Wproj, const float* __restrict__ bg,
    float* __restrict__ gc)
{
    __shared__ float sS[CC*9];
    __shared__ float a2[CC];
    const int n = blockIdx.x;
    const int t = threadIdx.x;
    const float* Wv2 = Wv + 2*CC*CC*9;

    for (int i = t; i < CC*9; i += 256) sS[i] = S[n*CC*9 + i];
    __syncthreads();

    {
        const int o = t >> 2, part = t & 3;
        const float* wrow = Wv2 + o*(CC*9) + part*(16*9);
        const float* srow = sS + part*(16*9);
        float acc = 0.f;
        #pragma unroll 4
        for (int i = 0; i < 16*9; i++) acc += wrow[i] * srow[i];
        acc += __shfl_xor_sync(0xffffffff, acc, 1);
        acc += __shfl_xor_sync(0xffffffff, acc, 2);
        if (part == 0) a2[o] = acc * (1.f / (float)DD);
    }
    __syncthreads();

    if (t < 3*CC) {
        int gi = t / CC, o = t % CC;
        int gate = (gi == 0) ? 0 : (gi == 1 ? 2 : 3);
        const float* wp = Wproj + ((gate*4 + 2)*CC + o)*CC;
        float acc = bg[gate*CC + o];
        #pragma unroll
        for (int c = 0; c < CC; c++) acc += wp[c] * a2[c];
        gc[(n*3 + gi)*CC + o] = acc;
    }
}

// ---------------------------------------------------------------------------
// Gates i,g,o + cell + hidden + fused output 1x1 projection.
// ---------------------------------------------------------------------------
__global__ __launch_bounds__(256) void gates_out_k(
    const float* __restrict__ A0, const float* __restrict__ Wproj,
    const float* __restrict__ gc, const float* __restrict__ W_out,
    const float* __restrict__ b_out, float* __restrict__ out)
{
    __shared__ float swiT[CC*CC];  // [c][o] ; later reused for W_out^T
    __shared__ float swgT[CC*CC];
    __shared__ float sx[CC][64];   // A0 tile; later reused for hout
    const int n  = blockIdx.y;
    const int p0 = blockIdx.x * 64;

    const float* Wi = Wproj + (0*4 + 0)*CC*CC;
    const float* Wg = Wproj + (2*4 + 0)*CC*CC;
    const float* Wo = Wproj + (3*4 + 0)*CC*CC;
    for (int idx = threadIdx.x; idx < CC*CC; idx += 256) {
        int o = idx & 63, c = idx >> 6;
        swiT[c*CC + o] = Wi[o*CC + c];
        swgT[c*CC + o] = Wg[o*CC + c];
        sx[c][o] = A0[(n*CC + c)*PP + p0 + o];
    }
    __syncthreads();

    const int px  = threadIdx.x >> 2;
    const int ocg = threadIdx.x & 3;
    const float* gcn = gc + n*3*CC;

    float ai[16], ag[16], ao[16];
    #pragma unroll
    for (int u = 0; u < 16; u++) {
        int oc = ocg + 4*u;
        ai[u] = gcn[oc]; ag[u] = gcn[CC + oc]; ao[u] = gcn[2*CC + oc];
    }

    #pragma unroll 2
    for (int c = 0; c < CC; c++) {
        float xv = sx[c][px];
        #pragma unroll
        for (int u = 0; u < 16; u++) {
            int oc = ocg + 4*u;
            ai[u] += swiT[c*CC + oc] * xv;
            ag[u] += swgT[c*CC + oc] * xv;
            ao[u] += __ldg(Wo + oc*CC + c) * xv;
        }
    }

    float hv[16];
    #pragma unroll
    for (int u = 0; u < 16; u++) {
        float ig = 1.f / (1.f + __expf(-ai[u]));
        float gg = tanhf(ag[u]);
        float og = 1.f / (1.f + __expf(-ao[u]));
        hv[u] = og * tanhf(ig * gg);
    }

    __syncthreads();
    #pragma unroll
    for (int u = 0; u < 16; u++) sx[ocg + 4*u][px] = hv[u];
    for (int idx = threadIdx.x; idx < CC*CC; idx += 256) {
        int o = idx & 63, c = idx >> 6;
        swiT[c*CC + o] = W_out[o*CC + c];
    }
    __syncthreads();

    float acc[16];
    #pragma unroll
    for (int u = 0; u < 16; u++) acc[u] = b_out[ocg + 4*u];
    #pragma unroll 4
    for (int c = 0; c < CC; c++) {
        float xv = sx[c][px];
        #pragma unroll
        for (int u = 0; u < 16; u++)
            acc[u] += swiT[c*CC + ocg + 4*u] * xv;
    }
    #pragma unroll
    for (int u = 0; u < 16; u++)
        out[(n*CC + ocg + 4*u)*PP + p0 + px] = acc[u];
}

// ---------------------------------------------------------------------------
extern "C" void kernel_launch(void* const* d_in, const int* in_sizes, int n_in,
                              void* d_out, int out_size)
{
    const float* x     = (const float*)d_in[0];
    const float* W_in  = (const float*)d_in[1];
    const float* b_in  = (const float*)d_in[2];
    const float* Wq    = (const float*)d_in[3];
    const float* Wk    = (const float*)d_in[4];
    const float* Wv    = (const float*)d_in[5];
    const float* Wproj = (const float*)d_in[6];
    const float* b_g   = (const float*)d_in[7];
    const float* W_out = (const float*)d_in[8];
    const float* b_out = (const float*)d_in[9];
    float* out = (float*)d_out;

    void* sp = nullptr;
    cudaGetSymbolAddress(&sp, g_scratch);
    float* s = (float*)sp;

    const dim3 pwGrid(PP/64, NB);

    pointwise_k<<<pwGrid, 256>>>(x, W_in, b_in, s + OFF_XIN);
    conv3_k<<<dim3(HH, NB, 3), 256>>>(s + OFF_XIN, Wq, Wk, Wv,
                                      s + OFF_Q0, s + OFF_K0, s + OFF_V0);
    winsum_k<<<dim3(CC, NB), 256>>>(s + OFF_XIN, s + OFF_S);
    attn_k<<<dim3(PP/256, NB*HEADS, SPLIT), 128>>>(s + OFF_Q0, s + OFF_K0,
                                                   s + OFF_V0, s + OFF_PART);
    combine_k<<<dim3(PP/128, NB*HEADS), 128>>>(s + OFF_PART, s + OFF_A0);
    a2gc_k<<<NB, 256>>>(s + OFF_S, Wv, Wproj, b_g, s + OFF_GC);
    gates_out_k<<<pwGrid, 256>>>(s + OFF_A0, Wproj, s + OFF_GC, W_out, b_out, out);
}

// round 9
// speedup vs baseline: 3.2886x; 1.1944x over previous
#include <cuda_runtime.h>
#include <math.h>

// Problem constants
#define NB    4
#define CC    64
#define HEADS 4
#define HCH   16
#define HH    48
#define WW    48
#define PP    (HH*WW)     // 2304
#define VH    46
#define VW    46
#define DD    (VH*VW)     // 2116

#define SPLIT 6           // key-dim split for attention
#define LOG2E 1.4426950408889634f

// Scratch layout (floats)
#define OFF_XIN   0
#define OFF_Q0    (OFF_XIN  + NB*CC*PP)
#define OFF_A0    (OFF_Q0   + NB*CC*PP)
#define OFF_K0    (OFF_A0   + NB*CC*PP)
#define OFF_V0    (OFF_K0   + NB*CC*DD)
#define OFF_S     (OFF_V0   + NB*CC*DD)
#define OFF_GC    (OFF_S    + NB*CC*9)
#define OFF_PART  (OFF_GC   + NB*3*CC)
#define SCRATCH_TOTAL (OFF_PART + SPLIT*NB*HEADS*17*PP)

__device__ float g_scratch[SCRATCH_TOTAL];

// ---- packed fp32x2 helpers -------------------------------------------------
typedef unsigned long long u64t;

__device__ __forceinline__ u64t pack2(float a, float b) {
    u64t r; asm("mov.b64 %0, {%1,%2};" : "=l"(r) : "f"(a), "f"(b)); return r;
}
__device__ __forceinline__ float2 unpack2(u64t v) {
    float2 r; asm("mov.b64 {%0,%1}, %2;" : "=f"(r.x), "=f"(r.y) : "l"(v)); return r;
}
__device__ __forceinline__ u64t ffma2(u64t a, u64t b, u64t c) {
    u64t d; asm("fma.rn.f32x2 %0, %1, %2, %3;" : "=l"(d) : "l"(a), "l"(b), "l"(c)); return d;
}
__device__ __forceinline__ u64t add2(u64t a, u64t b) {
    u64t d; asm("add.rn.f32x2 %0, %1, %2;" : "=l"(d) : "l"(a), "l"(b)); return d;
}
__device__ __forceinline__ float ex2(float x) {
    float r; asm("ex2.approx.f32 %0, %1;" : "=f"(r) : "f"(x)); return r;
}

// ---------------------------------------------------------------------------
// Pointwise 1x1 conv (input projection).
// ---------------------------------------------------------------------------
__global__ __launch_bounds__(256) void pointwise_k(
    const float* __restrict__ in, const float* __restrict__ wmat,
    const float* __restrict__ bias, float* __restrict__ out)
{
    __shared__ float swT[CC*CC];   // [c][o]
    __shared__ float sx[CC][64];   // [c][px]
    const int n  = blockIdx.y;
    const int p0 = blockIdx.x * 64;

    for (int idx = threadIdx.x; idx < CC*CC; idx += 256) {
        int o = idx & 63, c = idx >> 6;
        swT[c*CC + o] = wmat[o*CC + c];
        sx[c][o] = in[(n*CC + c)*PP + p0 + o];
    }
    __syncthreads();

    const int px  = threadIdx.x >> 2;
    const int ocg = threadIdx.x & 3;

    float acc[16];
    #pragma unroll
    for (int u = 0; u < 16; u++) acc[u] = bias[ocg + 4*u];

    #pragma unroll 4
    for (int c = 0; c < CC; c++) {
        float xv = sx[c][px];
        #pragma unroll
        for (int u = 0; u < 16; u++)
            acc[u] += swT[c*CC + ocg + 4*u] * xv;
    }

    #pragma unroll
    for (int u = 0; u < 16; u++)
        out[(n*CC + ocg + 4*u)*PP + p0 + px] = acc[u];
}

// ---------------------------------------------------------------------------
// Fused 3x3 convs, 2 output rows per block.
// branch 0 = q (SAME, 48 rows = 24 pairs), 1 = k, 2 = v (VALID, 46 rows = 23 pairs).
// 4-row input slab staged 32 channels at a time (2 passes, 26.6KB smem).
// Each staged row vector feeds BOTH output rows.
// ---------------------------------------------------------------------------
__global__ __launch_bounds__(256) void conv3_k(
    const float* __restrict__ xin,
    const float* __restrict__ Wq, const float* __restrict__ Wk,
    const float* __restrict__ Wv,
    float* __restrict__ Q0, float* __restrict__ K0, float* __restrict__ V0)
{
    const int br = blockIdx.z;
    const int yp = blockIdx.x;
    const int n  = blockIdx.y;
    if (br != 0 && yp >= VH/2) return;

    const float* wgt; float* out; int ow, ohw, ofs;
    if (br == 0)      { wgt = Wq; out = Q0; ow = WW; ohw = PP; ofs = -1; }
    else if (br == 1) { wgt = Wk; out = K0; ow = VW; ohw = DD; ofs = 0;  }
    else              { wgt = Wv; out = V0; ow = VW; ohw = DD; ofs = 0;  }

    const int y0 = yp * 2;

    __shared__ float tile[32][4][52];
    const float* inN = xin + n*CC*PP;

    const int oc = threadIdx.x >> 2;
    const int x0 = (threadIdx.x & 3) * 12;   // 16B aligned
    const float* wo = wgt + oc*(CC*9);

    float acc0[12], acc1[12];
    #pragma unroll
    for (int i = 0; i < 12; i++) { acc0[i] = 0.f; acc1[i] = 0.f; }

    for (int half = 0; half < 2; half++) {
        const int cbase = half * 32;
        __syncthreads();
        for (int idx = threadIdx.x; idx < 32*4*52; idx += 256) {
            int c = idx / 208, rem = idx % 208, r = rem / 52, j = rem % 52;
            int gy = y0 + r + ofs, gx = j + ofs;
            float v = 0.f;
            if (gy >= 0 && gy < HH && gx >= 0 && gx < WW)
                v = inN[(cbase + c)*PP + gy*WW + gx];
            tile[c][r][j] = v;
        }
        __syncthreads();

        #pragma unroll 2
        for (int c = 0; c < 32; c++) {
            float w[9];
            #pragma unroll
            for (int t = 0; t < 9; t++) w[t] = __ldg(wo + (cbase + c)*9 + t);

            #pragma unroll
            for (int r = 0; r < 4; r++) {
                const float4* t4 = (const float4*)&tile[c][r][x0];
                float4 a = t4[0], b = t4[1], d = t4[2], e = t4[3];
                float v[16] = {a.x,a.y,a.z,a.w, b.x,b.y,b.z,b.w,
                               d.x,d.y,d.z,d.w, e.x,e.y,e.z,e.w};
                if (r < 3) {
                    float w0 = w[r*3+0], w1 = w[r*3+1], w2 = w[r*3+2];
                    #pragma unroll
                    for (int xi = 0; xi < 12; xi++)
                        acc0[xi] += w0*v[xi] + w1*v[xi+1] + w2*v[xi+2];
                }
                if (r > 0) {
                    float w0 = w[(r-1)*3+0], w1 = w[(r-1)*3+1], w2 = w[(r-1)*3+2];
                    #pragma unroll
                    for (int xi = 0; xi < 12; xi++)
                        acc1[xi] += w0*v[xi] + w1*v[xi+1] + w2*v[xi+2];
                }
            }
        }
    }

    float* ob0 = out + (n*CC + oc)*ohw + y0*ow;
    float* ob1 = ob0 + ow;
    #pragma unroll
    for (int xi = 0; xi < 12; xi++) {
        int x = x0 + xi;
        if (x < ow) { ob0[x] = acc0[xi]; ob1[x] = acc1[xi]; }
    }
}

// ---------------------------------------------------------------------------
// Window sums: S[n,c,r,s] = sum of xin[n,c] over 46x46 window at offset (r,s).
// ---------------------------------------------------------------------------
__global__ __launch_bounds__(256) void winsum_k(
    const float* __restrict__ xin, float* __restrict__ S)
{
    const int c = blockIdx.x, n = blockIdx.y;
    const float* ib = xin + (n*CC + c)*PP;

    float rect[9];
    #pragma unroll
    for (int i = 0; i < 9; i++) rect[i] = 0.f;

    for (int idx = threadIdx.x; idx < PP; idx += 256) {
        int y = idx / WW, x = idx % WW;
        float v = ib[idx];
        int rlo = y - 45 > 0 ? y - 45 : 0;
        int rhi = y < 2 ? y : 2;
        int slo = x - 45 > 0 ? x - 45 : 0;
        int shi = x < 2 ? x : 2;
        for (int r = rlo; r <= rhi; r++)
            for (int s = slo; s <= shi; s++)
                rect[r*3 + s] += v;
    }
    #pragma unroll
    for (int i = 0; i < 9; i++) {
        #pragma unroll
        for (int off = 16; off > 0; off >>= 1)
            rect[i] += __shfl_xor_sync(0xffffffff, rect[i], off);
    }
    __shared__ float red[8][9];
    const int warp = threadIdx.x >> 5, lane = threadIdx.x & 31;
    if (lane == 0) {
        #pragma unroll
        for (int i = 0; i < 9; i++) red[warp][i] = rect[i];
    }
    __syncthreads();
    if (threadIdx.x < 9) {
        float s = 0.f;
        #pragma unroll
        for (int w = 0; w < 8; w++) s += red[w][threadIdx.x];
        S[(n*CC + c)*9 + threadIdx.x] = s;
    }
}

// ---------------------------------------------------------------------------
// Attention (branch 0), f32x2 packed along key dim, split-K over SPLIT blocks,
// query-blocked x2. q pre-scaled by log2e -> raw ex2 (no FMUL before MUFU).
// Packed denominator accumulators. Pinned to 3 blocks/SM.
// ---------------------------------------------------------------------------
#define DCH 92
__global__ __launch_bounds__(128, 3) void attn_k(
    const float* __restrict__ q0, const float* __restrict__ k0,
    const float* __restrict__ v0, float* __restrict__ part)
{
    __shared__ __align__(16) u64t sk2[HCH][DCH/2];
    __shared__ __align__(16) u64t sv2[HCH][DCH/2];

    const int nh = blockIdx.y;
    const int z  = blockIdx.z;
    const int n = nh >> 2, head = nh & 3;
    const int qA = blockIdx.x * 256 + threadIdx.x;
    const int qB = qA + 128;

    const float* qbase = q0 + (n*CC + head*HCH)*PP;
    u64t qvA[HCH], qvB[HCH];
    #pragma unroll
    for (int c = 0; c < HCH; c++) {
        float a = qbase[c*PP + qA] * LOG2E; qvA[c] = pack2(a, a);
        float b = qbase[c*PP + qB] * LOG2E; qvB[c] = pack2(b, b);
    }

    u64t accA[HCH], accB[HCH];
    #pragma unroll
    for (int c = 0; c < HCH; c++) { accA[c] = 0ULL; accB[c] = 0ULL; }
    u64t lA2 = 0ULL, lB2 = 0ULL;

    const float* kb = k0 + (n*CC + head*HCH)*DD;
    const float* vb = v0 + (n*CC + head*HCH)*DD;

    for (int it = z; it < DD/DCH; it += SPLIT) {
        const int d0 = it * DCH;
        for (int idx = threadIdx.x; idx < HCH*(DCH/2)*2; idx += 128) {
            int half = idx >= HCH*(DCH/2);
            int i = idx - half*HCH*(DCH/2);
            int c = i / (DCH/2), jj = i % (DCH/2);
            const float* src = half ? vb : kb;
            u64t val = *(const u64t*)(src + c*DD + d0 + 2*jj);
            if (half) sv2[c][jj] = val; else sk2[c][jj] = val;
        }
        __syncthreads();

        #pragma unroll 1
        for (int jg = 0; jg < DCH/2; jg += 2) {      // 4 keys per iteration
            u64t sAa = 0ULL, sAb = 0ULL, sBa = 0ULL, sBb = 0ULL;
            #pragma unroll
            for (int c = 0; c < HCH; c++) {
                ulonglong2 kk = *(const ulonglong2*)&sk2[c][jg];
                sAa = ffma2(qvA[c], kk.x, sAa);
                sAb = ffma2(qvA[c], kk.y, sAb);
                sBa = ffma2(qvB[c], kk.x, sBa);
                sBb = ffma2(qvB[c], kk.y, sBb);
            }
            float2 a0 = unpack2(sAa), a1 = unpack2(sAb);
            float2 b0 = unpack2(sBa), b1 = unpack2(sBb);
            float pA0 = ex2(a0.x), pA1 = ex2(a0.y);
            float pA2 = ex2(a1.x), pA3 = ex2(a1.y);
            float pB0 = ex2(b0.x), pB1 = ex2(b0.y);
            float pB2 = ex2(b1.x), pB3 = ex2(b1.y);
            u64t pAx = pack2(pA0, pA1), pAy = pack2(pA2, pA3);
            u64t pBx = pack2(pB0, pB1), pBy = pack2(pB2, pB3);
            lA2 = add2(lA2, add2(pAx, pAy));
            lB2 = add2(lB2, add2(pBx, pBy));
            #pragma unroll
            for (int c = 0; c < HCH; c++) {
                ulonglong2 vv = *(const ulonglong2*)&sv2[c][jg];
                accA[c] = ffma2(pAx, vv.x, accA[c]);
                accA[c] = ffma2(pAy, vv.y, accA[c]);
                accB[c] = ffma2(pBx, vv.x, accB[c]);
                accB[c] = ffma2(pBy, vv.y, accB[c]);
            }
        }
        __syncthreads();
    }

    float* pb = part + ((z*(NB*HEADS) + nh)*17)*PP;
    #pragma unroll
    for (int c = 0; c < HCH; c++) {
        float2 a = unpack2(accA[c]);
        float2 b = unpack2(accB[c]);
        pb[c*PP + qA] = a.x + a.y;
        pb[c*PP + qB] = b.x + b.y;
    }
    float2 la = unpack2(lA2), lb = unpack2(lB2);
    pb[16*PP + qA] = la.x + la.y;
    pb[16*PP + qB] = lb.x + lb.y;
}

// ---------------------------------------------------------------------------
// Combine split-K partials: A0 = (sum_z acc_z) / (sum_z l_z).
// ---------------------------------------------------------------------------
__global__ __launch_bounds__(128) void combine_k(
    const float* __restrict__ part, float* __restrict__ A0)
{
    const int nh = blockIdx.y;
    const int n = nh >> 2, head = nh & 3;
    const int q = blockIdx.x * 128 + threadIdx.x;

    float s[HCH];
    #pragma unroll
    for (int c = 0; c < HCH; c++) s[c] = 0.f;
    float l = 0.f;

    #pragma unroll
    for (int z = 0; z < SPLIT; z++) {
        const float* pb = part + ((z*(NB*HEADS) + nh)*17)*PP + q;
        l += pb[16*PP];
        #pragma unroll
        for (int c = 0; c < HCH; c++) s[c] += pb[c*PP];
    }
    const float inv = 1.f / l;
    float* ab = A0 + (n*CC + head*HCH)*PP + q;
    #pragma unroll
    for (int c = 0; c < HCH; c++) ab[c*PP] = s[c] * inv;
}

// ---------------------------------------------------------------------------
// a2 from window sums + Wv[2], then gate bias constants. One block per n.
// ---------------------------------------------------------------------------
__global__ __launch_bounds__(256) void a2gc_k(
    const float* __restrict__ S, const float* __restrict__ Wv,
    const float* __restrict__ Wproj, const float* __restrict__ bg,
    float* __restrict__ gc)
{
    __shared__ float sS[CC*9];
    __shared__ float a2[CC];
    const int n = blockIdx.x;
    const int t = threadIdx.x;
    const float* Wv2 = Wv + 2*CC*CC*9;

    for (int i = t; i < CC*9; i += 256) sS[i] = S[n*CC*9 + i];
    __syncthreads();

    {
        const int o = t >> 2, part = t & 3;
        const float* wrow = Wv2 + o*(CC*9) + part*(16*9);
        const float* srow = sS + part*(16*9);
        float acc = 0.f;
        #pragma unroll 4
        for (int i = 0; i < 16*9; i++) acc += wrow[i] * srow[i];
        acc += __shfl_xor_sync(0xffffffff, acc, 1);
        acc += __shfl_xor_sync(0xffffffff, acc, 2);
        if (part == 0) a2[o] = acc * (1.f / (float)DD);
    }
    __syncthreads();

    if (t < 3*CC) {
        int gi = t / CC, o = t % CC;
        int gate = (gi == 0) ? 0 : (gi == 1 ? 2 : 3);
        const float* wp = Wproj + ((gate*4 + 2)*CC + o)*CC;
        float acc = bg[gate*CC + o];
        #pragma unroll
        for (int c = 0; c < CC; c++) acc += wp[c] * a2[c];
        gc[(n*3 + gi)*CC + o] = acc;
    }
}

// ---------------------------------------------------------------------------
// Gates i,g,o + cell + hidden + fused output 1x1 projection.
// ---------------------------------------------------------------------------
__global__ __launch_bounds__(256) void gates_out_k(
    const float* __restrict__ A0, const float* __restrict__ Wproj,
    const float* __restrict__ gc, const float* __restrict__ W_out,
    const float* __restrict__ b_out, float* __restrict__ out)
{
    __shared__ float swiT[CC*CC];  // [c][o] ; later reused for W_out^T
    __shared__ float swgT[CC*CC];
    __shared__ float sx[CC][64];   // A0 tile; later reused for hout
    const int n  = blockIdx.y;
    const int p0 = blockIdx.x * 64;

    const float* Wi = Wproj + (0*4 + 0)*CC*CC;
    const float* Wg = Wproj + (2*4 + 0)*CC*CC;
    const float* Wo = Wproj + (3*4 + 0)*CC*CC;
    for (int idx = threadIdx.x; idx < CC*CC; idx += 256) {
        int o = idx & 63, c = idx >> 6;
        swiT[c*CC + o] = Wi[o*CC + c];
        swgT[c*CC + o] = Wg[o*CC + c];
        sx[c][o] = A0[(n*CC + c)*PP + p0 + o];
    }
    __syncthreads();

    const int px  = threadIdx.x >> 2;
    const int ocg = threadIdx.x & 3;
    const float* gcn = gc + n*3*CC;

    float ai[16], ag[16], ao[16];
    #pragma unroll
    for (int u = 0; u < 16; u++) {
        int oc = ocg + 4*u;
        ai[u] = gcn[oc]; ag[u] = gcn[CC + oc]; ao[u] = gcn[2*CC + oc];
    }

    #pragma unroll 2
    for (int c = 0; c < CC; c++) {
        float xv = sx[c][px];
        #pragma unroll
        for (int u = 0; u < 16; u++) {
            int oc = ocg + 4*u;
            ai[u] += swiT[c*CC + oc] * xv;
            ag[u] += swgT[c*CC + oc] * xv;
            ao[u] += __ldg(Wo + oc*CC + c) * xv;
        }
    }

    float hv[16];
    #pragma unroll
    for (int u = 0; u < 16; u++) {
        float ig = 1.f / (1.f + __expf(-ai[u]));
        float gg = tanhf(ag[u]);
        float og = 1.f / (1.f + __expf(-ao[u]));
        hv[u] = og * tanhf(ig * gg);
    }

    __syncthreads();
    #pragma unroll
    for (int u = 0; u < 16; u++) sx[ocg + 4*u][px] = hv[u];
    for (int idx = threadIdx.x; idx < CC*CC; idx += 256) {
        int o = idx & 63, c = idx >> 6;
        swiT[c*CC + o] = W_out[o*CC + c];
    }
    __syncthreads();

    float acc[16];
    #pragma unroll
    for (int u = 0; u < 16; u++) acc[u] = b_out[ocg + 4*u];
    #pragma unroll 4
    for (int c = 0; c < CC; c++) {
        float xv = sx[c][px];
        #pragma unroll
        for (int u = 0; u < 16; u++)
            acc[u] += swiT[c*CC + ocg + 4*u] * xv;
    }
    #pragma unroll
    for (int u = 0; u < 16; u++)
        out[(n*CC + ocg + 4*u)*PP + p0 + px] = acc[u];
}

// ---------------------------------------------------------------------------
extern "C" void kernel_launch(void* const* d_in, const int* in_sizes, int n_in,
                              void* d_out, int out_size)
{
    const float* x     = (const float*)d_in[0];
    const float* W_in  = (const float*)d_in[1];
    const float* b_in  = (const float*)d_in[2];
    const float* Wq    = (const float*)d_in[3];
    const float* Wk    = (const float*)d_in[4];
    const float* Wv    = (const float*)d_in[5];
    const float* Wproj = (const float*)d_in[6];
    const float* b_g   = (const float*)d_in[7];
    const float* W_out = (const float*)d_in[8];
    const float* b_out = (const float*)d_in[9];
    float* out = (float*)d_out;

    void* sp = nullptr;
    cudaGetSymbolAddress(&sp, g_scratch);
    float* s = (float*)sp;

    const dim3 pwGrid(PP/64, NB);

    pointwise_k<<<pwGrid, 256>>>(x, W_in, b_in, s + OFF_XIN);
    conv3_k<<<dim3(HH/2, NB, 3), 256>>>(s + OFF_XIN, Wq, Wk, Wv,
                                        s + OFF_Q0, s + OFF_K0, s + OFF_V0);
    winsum_k<<<dim3(CC, NB), 256>>>(s + OFF_XIN, s + OFF_S);
    attn_k<<<dim3(PP/256, NB*HEADS, SPLIT), 128>>>(s + OFF_Q0, s + OFF_K0,
                                                   s + OFF_V0, s + OFF_PART);
    combine_k<<<dim3(PP/128, NB*HEADS), 128>>>(s + OFF_PART, s + OFF_A0);
    a2gc_k<<<NB, 256>>>(s + OFF_S, Wv, Wproj, b_g, s + OFF_GC);
    gates_out_k<<<pwGrid, 256>>>(s + OFF_A0, Wproj, s + OFF_GC, W_out, b_out, out);
}

// round 10
// speedup vs baseline: 3.3177x; 1.0088x over previous
#include <cuda_runtime.h>
#include <math.h>

// Problem constants
#define NB    4
#define CC    64
#define HEADS 4
#define HCH   16
#define HH    48
#define WW    48
#define PP    (HH*WW)     // 2304
#define VH    46
#define VW    46
#define DD    (VH*VW)     // 2116

#define SPLIT 6           // key-dim split for attention
#define LOG2E 1.4426950408889634f

// Scratch layout (floats)
#define OFF_XIN   0
#define OFF_Q0    (OFF_XIN  + NB*CC*PP)
#define OFF_A0    (OFF_Q0   + NB*CC*PP)
#define OFF_K0    (OFF_A0   + NB*CC*PP)
#define OFF_V0    (OFF_K0   + NB*CC*DD)
#define OFF_S     (OFF_V0   + NB*CC*DD)
#define OFF_GC    (OFF_S    + NB*CC*9)
#define OFF_PART  (OFF_GC   + NB*3*CC)
#define SCRATCH_TOTAL (OFF_PART + SPLIT*NB*HEADS*17*PP)

__device__ float g_scratch[SCRATCH_TOTAL];

// ---- packed fp32x2 helpers -------------------------------------------------
typedef unsigned long long u64t;

__device__ __forceinline__ u64t pack2(float a, float b) {
    u64t r; asm("mov.b64 %0, {%1,%2};" : "=l"(r) : "f"(a), "f"(b)); return r;
}
__device__ __forceinline__ float2 unpack2(u64t v) {
    float2 r; asm("mov.b64 {%0,%1}, %2;" : "=f"(r.x), "=f"(r.y) : "l"(v)); return r;
}
__device__ __forceinline__ u64t ffma2(u64t a, u64t b, u64t c) {
    u64t d; asm("fma.rn.f32x2 %0, %1, %2, %3;" : "=l"(d) : "l"(a), "l"(b), "l"(c)); return d;
}
__device__ __forceinline__ u64t add2(u64t a, u64t b) {
    u64t d; asm("add.rn.f32x2 %0, %1, %2;" : "=l"(d) : "l"(a), "l"(b)); return d;
}
__device__ __forceinline__ float ex2(float x) {
    float r; asm("ex2.approx.f32 %0, %1;" : "=f"(r) : "f"(x)); return r;
}

// ---------------------------------------------------------------------------
// Pointwise 1x1 conv (input projection).
// ---------------------------------------------------------------------------
__global__ __launch_bounds__(256) void pointwise_k(
    const float* __restrict__ in, const float* __restrict__ wmat,
    const float* __restrict__ bias, float* __restrict__ out)
{
    __shared__ float swT[CC*CC];   // [c][o]
    __shared__ float sx[CC][64];   // [c][px]
    const int n  = blockIdx.y;
    const int p0 = blockIdx.x * 64;

    for (int idx = threadIdx.x; idx < CC*CC; idx += 256) {
        int o = idx & 63, c = idx >> 6;
        swT[c*CC + o] = wmat[o*CC + c];
        sx[c][o] = in[(n*CC + c)*PP + p0 + o];
    }
    __syncthreads();

    const int px  = threadIdx.x >> 2;
    const int ocg = threadIdx.x & 3;

    float acc[16];
    #pragma unroll
    for (int u = 0; u < 16; u++) acc[u] = bias[ocg + 4*u];

    #pragma unroll 4
    for (int c = 0; c < CC; c++) {
        float xv = sx[c][px];
        #pragma unroll
        for (int u = 0; u < 16; u++)
            acc[u] += swT[c*CC + ocg + 4*u] * xv;
    }

    #pragma unroll
    for (int u = 0; u < 16; u++)
        out[(n*CC + ocg + 4*u)*PP + p0 + px] = acc[u];
}

// ---------------------------------------------------------------------------
// Fused 3x3 convs, 2 output rows per block, FFMA2 over x-pixel pairs.
// branch 0 = q (SAME, 24 row-pairs), 1 = k, 2 = v (VALID, 23 row-pairs).
// 4-row input slab staged 32 channels at a time. Each thread computes 12
// output pixels x 2 rows as 6 packed f32x2 accumulators per row.
// Even packs (v2m, v2m+1) are direct ulonglong2 register pairs from smem;
// odd packs (v2m+1, v2m+2) are rebuilt with MOVs (alu pipe, overlaps fma).
// ---------------------------------------------------------------------------
__global__ __launch_bounds__(256) void conv3_k(
    const float* __restrict__ xin,
    const float* __restrict__ Wq, const float* __restrict__ Wk,
    const float* __restrict__ Wv,
    float* __restrict__ Q0, float* __restrict__ K0, float* __restrict__ V0)
{
    const int br = blockIdx.z;
    const int yp = blockIdx.x;
    const int n  = blockIdx.y;
    if (br != 0 && yp >= VH/2) return;

    const float* wgt; float* out; int ow, ohw, ofs;
    if (br == 0)      { wgt = Wq; out = Q0; ow = WW; ohw = PP; ofs = -1; }
    else if (br == 1) { wgt = Wk; out = K0; ow = VW; ohw = DD; ofs = 0;  }
    else              { wgt = Wv; out = V0; ow = VW; ohw = DD; ofs = 0;  }

    const int y0 = yp * 2;

    __shared__ __align__(16) float tile[32][4][52];
    const float* inN = xin + n*CC*PP;

    const int oc = threadIdx.x >> 2;
    const int x0 = (threadIdx.x & 3) * 12;   // 0,12,24,36 -> 16B aligned
    const float* wo = wgt + oc*(CC*9);

    u64t acc0[6], acc1[6];
    #pragma unroll
    for (int m = 0; m < 6; m++) { acc0[m] = 0ULL; acc1[m] = 0ULL; }

    for (int half = 0; half < 2; half++) {
        const int cbase = half * 32;
        __syncthreads();
        for (int idx = threadIdx.x; idx < 32*4*52; idx += 256) {
            int c = idx / 208, rem = idx % 208, r = rem / 52, j = rem % 52;
            int gy = y0 + r + ofs, gx = j + ofs;
            float v = 0.f;
            if (gy >= 0 && gy < HH && gx >= 0 && gx < WW)
                v = inN[(cbase + c)*PP + gy*WW + gx];
            tile[c][r][j] = v;
        }
        __syncthreads();

        #pragma unroll 2
        for (int c = 0; c < 32; c++) {
            u64t wd[9];
            #pragma unroll
            for (int t = 0; t < 9; t++) {
                float w = __ldg(wo + (cbase + c)*9 + t);
                wd[t] = pack2(w, w);
            }

            #pragma unroll
            for (int r = 0; r < 4; r++) {
                const ulonglong2* tp = (const ulonglong2*)&tile[c][r][x0];
                ulonglong2 Aq = tp[0], Bq = tp[1], Cq = tp[2], Dq = tp[3];
                u64t P[8] = {Aq.x, Aq.y, Bq.x, Bq.y, Cq.x, Cq.y, Dq.x, Dq.y};
                // odd packs O[m] = (v_{2m+1}, v_{2m+2})
                u64t O[6];
                #pragma unroll
                for (int m = 0; m < 6; m++) {
                    float2 lo = unpack2(P[m]);
                    float2 hi = unpack2(P[m+1]);
                    O[m] = pack2(lo.y, hi.x);
                }
                if (r < 3) {
                    u64t w0 = wd[r*3+0], w1 = wd[r*3+1], w2 = wd[r*3+2];
                    #pragma unroll
                    for (int m = 0; m < 6; m++) {
                        acc0[m] = ffma2(w0, P[m],   acc0[m]);
                        acc0[m] = ffma2(w1, O[m],   acc0[m]);
                        acc0[m] = ffma2(w2, P[m+1], acc0[m]);
                    }
                }
                if (r > 0) {
                    u64t w0 = wd[(r-1)*3+0], w1 = wd[(r-1)*3+1], w2 = wd[(r-1)*3+2];
                    #pragma unroll
                    for (int m = 0; m < 6; m++) {
                        acc1[m] = ffma2(w0, P[m],   acc1[m]);
                        acc1[m] = ffma2(w1, O[m],   acc1[m]);
                        acc1[m] = ffma2(w2, P[m+1], acc1[m]);
                    }
                }
            }
        }
    }

    float* ob0 = out + (n*CC + oc)*ohw + y0*ow;
    float* ob1 = ob0 + ow;
    #pragma unroll
    for (int m = 0; m < 6; m++) {
        float2 a = unpack2(acc0[m]);
        float2 b = unpack2(acc1[m]);
        int x = x0 + 2*m;
        if (x < ow)     { ob0[x]   = a.x; ob1[x]   = b.x; }
        if (x + 1 < ow) { ob0[x+1] = a.y; ob1[x+1] = b.y; }
    }
}

// ---------------------------------------------------------------------------
// Window sums: S[n,c,r,s] = sum of xin[n,c] over 46x46 window at offset (r,s).
// ---------------------------------------------------------------------------
__global__ __launch_bounds__(256) void winsum_k(
    const float* __restrict__ xin, float* __restrict__ S)
{
    const int c = blockIdx.x, n = blockIdx.y;
    const float* ib = xin + (n*CC + c)*PP;

    float rect[9];
    #pragma unroll
    for (int i = 0; i < 9; i++) rect[i] = 0.f;

    for (int idx = threadIdx.x; idx < PP; idx += 256) {
        int y = idx / WW, x = idx % WW;
        float v = ib[idx];
        int rlo = y - 45 > 0 ? y - 45 : 0;
        int rhi = y < 2 ? y : 2;
        int slo = x - 45 > 0 ? x - 45 : 0;
        int shi = x < 2 ? x : 2;
        for (int r = rlo; r <= rhi; r++)
            for (int s = slo; s <= shi; s++)
                rect[r*3 + s] += v;
    }
    #pragma unroll
    for (int i = 0; i < 9; i++) {
        #pragma unroll
        for (int off = 16; off > 0; off >>= 1)
            rect[i] += __shfl_xor_sync(0xffffffff, rect[i], off);
    }
    __shared__ float red[8][9];
    const int warp = threadIdx.x >> 5, lane = threadIdx.x & 31;
    if (lane == 0) {
        #pragma unroll
        for (int i = 0; i < 9; i++) red[warp][i] = rect[i];
    }
    __syncthreads();
    if (threadIdx.x < 9) {
        float s = 0.f;
        #pragma unroll
        for (int w = 0; w < 8; w++) s += red[w][threadIdx.x];
        S[(n*CC + c)*9 + threadIdx.x] = s;
    }
}

// ---------------------------------------------------------------------------
// Attention (branch 0), f32x2 packed along key dim, split-K over SPLIT blocks,
// query-blocked x2, ex2 with log2e-prescaled q. Pinned to 3 blocks/SM.
// ---------------------------------------------------------------------------
#define DCH 92
__global__ __launch_bounds__(128, 3) void attn_k(
    const float* __restrict__ q0, const float* __restrict__ k0,
    const float* __restrict__ v0, float* __restrict__ part)
{
    __shared__ __align__(16) u64t sk2[HCH][DCH/2];
    __shared__ __align__(16) u64t sv2[HCH][DCH/2];

    const int nh = blockIdx.y;
    const int z  = blockIdx.z;
    const int n = nh >> 2, head = nh & 3;
    const int qA = blockIdx.x * 256 + threadIdx.x;
    const int qB = qA + 128;

    const float* qbase = q0 + (n*CC + head*HCH)*PP;
    u64t qvA[HCH], qvB[HCH];
    #pragma unroll
    for (int c = 0; c < HCH; c++) {
        float a = qbase[c*PP + qA] * LOG2E; qvA[c] = pack2(a, a);
        float b = qbase[c*PP + qB] * LOG2E; qvB[c] = pack2(b, b);
    }

    u64t accA[HCH], accB[HCH];
    #pragma unroll
    for (int c = 0; c < HCH; c++) { accA[c] = 0ULL; accB[c] = 0ULL; }
    u64t lA2 = 0ULL, lB2 = 0ULL;

    const float* kb = k0 + (n*CC + head*HCH)*DD;
    const float* vb = v0 + (n*CC + head*HCH)*DD;

    for (int it = z; it < DD/DCH; it += SPLIT) {
        const int d0 = it * DCH;
        for (int idx = threadIdx.x; idx < HCH*(DCH/2)*2; idx += 128) {
            int half = idx >= HCH*(DCH/2);
            int i = idx - half*HCH*(DCH/2);
            int c = i / (DCH/2), jj = i % (DCH/2);
            const float* src = half ? vb : kb;
            u64t val = *(const u64t*)(src + c*DD + d0 + 2*jj);
            if (half) sv2[c][jj] = val; else sk2[c][jj] = val;
        }
        __syncthreads();

        #pragma unroll 1
        for (int jg = 0; jg < DCH/2; jg += 2) {      // 4 keys per iteration
            u64t sAa = 0ULL, sAb = 0ULL, sBa = 0ULL, sBb = 0ULL;
            #pragma unroll
            for (int c = 0; c < HCH; c++) {
                ulonglong2 kk = *(const ulonglong2*)&sk2[c][jg];
                sAa = ffma2(qvA[c], kk.x, sAa);
                sAb = ffma2(qvA[c], kk.y, sAb);
                sBa = ffma2(qvB[c], kk.x, sBa);
                sBb = ffma2(qvB[c], kk.y, sBb);
            }
            float2 a0 = unpack2(sAa), a1 = unpack2(sAb);
            float2 b0 = unpack2(sBa), b1 = unpack2(sBb);
            float pA0 = ex2(a0.x), pA1 = ex2(a0.y);
            float pA2 = ex2(a1.x), pA3 = ex2(a1.y);
            float pB0 = ex2(b0.x), pB1 = ex2(b0.y);
            float pB2 = ex2(b1.x), pB3 = ex2(b1.y);
            u64t pAx = pack2(pA0, pA1), pAy = pack2(pA2, pA3);
            u64t pBx = pack2(pB0, pB1), pBy = pack2(pB2, pB3);
            lA2 = add2(lA2, add2(pAx, pAy));
            lB2 = add2(lB2, add2(pBx, pBy));
            #pragma unroll
            for (int c = 0; c < HCH; c++) {
                ulonglong2 vv = *(const ulonglong2*)&sv2[c][jg];
                accA[c] = ffma2(pAx, vv.x, accA[c]);
                accA[c] = ffma2(pAy, vv.y, accA[c]);
                accB[c] = ffma2(pBx, vv.x, accB[c]);
                accB[c] = ffma2(pBy, vv.y, accB[c]);
            }
        }
        __syncthreads();
    }

    float* pb = part + ((z*(NB*HEADS) + nh)*17)*PP;
    #pragma unroll
    for (int c = 0; c < HCH; c++) {
        float2 a = unpack2(accA[c]);
        float2 b = unpack2(accB[c]);
        pb[c*PP + qA] = a.x + a.y;
        pb[c*PP + qB] = b.x + b.y;
    }
    float2 la = unpack2(lA2), lb = unpack2(lB2);
    pb[16*PP + qA] = la.x + la.y;
    pb[16*PP + qB] = lb.x + lb.y;
}

// ---------------------------------------------------------------------------
// a2 from window sums + Wv[2], then gate bias constants. One block per n.
// ---------------------------------------------------------------------------
__global__ __launch_bounds__(256) void a2gc_k(
    const float* __restrict__ S, const float* __restrict__ Wv,
    const float* __restrict__ Wproj, const float* __restrict__ bg,
    float* __restrict__ gc)
{
    __shared__ float sS[CC*9];
    __shared__ float a2[CC];
    const int n = blockIdx.x;
    const int t = threadIdx.x;
    const float* Wv2 = Wv + 2*CC*CC*9;

    for (int i = t; i < CC*9; i += 256) sS[i] = S[n*CC*9 + i];
    __syncthreads();

    {
        const int o = t >> 2, part = t & 3;
        const float* wrow = Wv2 + o*(CC*9) + part*(16*9);
        const float* srow = sS + part*(16*9);
        float acc = 0.f;
        #pragma unroll 4
        for (int i = 0; i < 16*9; i++) acc += wrow[i] * srow[i];
        acc += __shfl_xor_sync(0xffffffff, acc, 1);
        acc += __shfl_xor_sync(0xffffffff, acc, 2);
        if (part == 0) a2[o] = acc * (1.f / (float)DD);
    }
    __syncthreads();

    if (t < 3*CC) {
        int gi = t / CC, o = t % CC;
        int gate = (gi == 0) ? 0 : (gi == 1 ? 2 : 3);
        const float* wp = Wproj + ((gate*4 + 2)*CC + o)*CC;
        float acc = bg[gate*CC + o];
        #pragma unroll
        for (int c = 0; c < CC; c++) acc += wp[c] * a2[c];
        gc[(n*3 + gi)*CC + o] = acc;
    }
}

// ---------------------------------------------------------------------------
// Split-K combine (inline) + gates i,g,o + cell + hidden + output projection.
// Stages A0 tile directly from attention partials: sum over z, normalize by
// summed softmax denominator.
// ---------------------------------------------------------------------------
__global__ __launch_bounds__(256) void gates_out_k(
    const float* __restrict__ part, const float* __restrict__ Wproj,
    const float* __restrict__ gc, const float* __restrict__ W_out,
    const float* __restrict__ b_out, float* __restrict__ out)
{
    __shared__ float swiT[CC*CC];  // [c][o] ; later reused for W_out^T
    __shared__ float swgT[CC*CC];
    __shared__ float sx[CC][64];   // combined A0 tile; later reused for hout
    __shared__ float linv[HEADS][64];
    const int n  = blockIdx.y;
    const int p0 = blockIdx.x * 64;

    // denominators: one per (head, px)
    {
        int head = threadIdx.x >> 6;   // 0..3
        int px   = threadIdx.x & 63;
        float l = 0.f;
        #pragma unroll
        for (int z = 0; z < SPLIT; z++)
            l += part[((z*(NB*HEADS) + n*HEADS + head)*17 + 16)*PP + p0 + px];
        linv[head][px] = 1.f / l;
    }
    const float* Wi = Wproj + (0*4 + 0)*CC*CC;
    const float* Wg = Wproj + (2*4 + 0)*CC*CC;
    const float* Wo = Wproj + (3*4 + 0)*CC*CC;
    for (int idx = threadIdx.x; idx < CC*CC; idx += 256) {
        int o = idx & 63, c = idx >> 6;
        swiT[c*CC + o] = Wi[o*CC + c];
        swgT[c*CC + o] = Wg[o*CC + c];
    }
    __syncthreads();

    // combined A0 tile
    for (int idx = threadIdx.x; idx < CC*64; idx += 256) {
        int c = idx >> 6, px = idx & 63;
        int head = c >> 4, hc = c & 15;
        float a = 0.f;
        #pragma unroll
        for (int z = 0; z < SPLIT; z++)
            a += part[((z*(NB*HEADS) + n*HEADS + head)*17 + hc)*PP + p0 + px];
        sx[c][px] = a * linv[head][px];
    }
    __syncthreads();

    const int px  = threadIdx.x >> 2;
    const int ocg = threadIdx.x & 3;
    const float* gcn = gc + n*3*CC;

    float ai[16], ag[16], ao[16];
    #pragma unroll
    for (int u = 0; u < 16; u++) {
        int oc = ocg + 4*u;
        ai[u] = gcn[oc]; ag[u] = gcn[CC + oc]; ao[u] = gcn[2*CC + oc];
    }

    #pragma unroll 2
    for (int c = 0; c < CC; c++) {
        float xv = sx[c][px];
        #pragma unroll
        for (int u = 0; u < 16; u++) {
            int oc = ocg + 4*u;
            ai[u] += swiT[c*CC + oc] * xv;
            ag[u] += swgT[c*CC + oc] * xv;
            ao[u] += __ldg(Wo + oc*CC + c) * xv;
        }
    }

    float hv[16];
    #pragma unroll
    for (int u = 0; u < 16; u++) {
        float ig = 1.f / (1.f + __expf(-ai[u]));
        float gg = tanhf(ag[u]);
        float og = 1.f / (1.f + __expf(-ao[u]));
        hv[u] = og * tanhf(ig * gg);
    }

    __syncthreads();
    #pragma unroll
    for (int u = 0; u < 16; u++) sx[ocg + 4*u][px] = hv[u];
    for (int idx = threadIdx.x; idx < CC*CC; idx += 256) {
        int o = idx & 63, c = idx >> 6;
        swiT[c*CC + o] = W_out[o*CC + c];
    }
    __syncthreads();

    float acc[16];
    #pragma unroll
    for (int u = 0; u < 16; u++) acc[u] = b_out[ocg + 4*u];
    #pragma unroll 4
    for (int c = 0; c < CC; c++) {
        float xv = sx[c][px];
        #pragma unroll
        for (int u = 0; u < 16; u++)
            acc[u] += swiT[c*CC + ocg + 4*u] * xv;
    }
    #pragma unroll
    for (int u = 0; u < 16; u++)
        out[(n*CC + ocg + 4*u)*PP + p0 + px] = acc[u];
}

// ---------------------------------------------------------------------------
extern "C" void kernel_launch(void* const* d_in, const int* in_sizes, int n_in,
                              void* d_out, int out_size)
{
    const float* x     = (const float*)d_in[0];
    const float* W_in  = (const float*)d_in[1];
    const float* b_in  = (const float*)d_in[2];
    const float* Wq    = (const float*)d_in[3];
    const float* Wk    = (const float*)d_in[4];
    const float* Wv    = (const float*)d_in[5];
    const float* Wproj = (const float*)d_in[6];
    const float* b_g   = (const float*)d_in[7];
    const float* W_out = (const float*)d_in[8];
    const float* b_out = (const float*)d_in[9];
    float* out = (float*)d_out;

    void* sp = nullptr;
    cudaGetSymbolAddress(&sp, g_scratch);
    float* s = (float*)sp;

    const dim3 pwGrid(PP/64, NB);

    pointwise_k<<<pwGrid, 256>>>(x, W_in, b_in, s + OFF_XIN);
    conv3_k<<<dim3(HH/2, NB, 3), 256>>>(s + OFF_XIN, Wq, Wk, Wv,
                                        s + OFF_Q0, s + OFF_K0, s + OFF_V0);
    winsum_k<<<dim3(CC, NB), 256>>>(s + OFF_XIN, s + OFF_S);
    attn_k<<<dim3(PP/256, NB*HEADS, SPLIT), 128>>>(s + OFF_Q0, s + OFF_K0,
                                                   s + OFF_V0, s + OFF_PART);
    a2gc_k<<<NB, 256>>>(s + OFF_S, Wv, Wproj, b_g, s + OFF_GC);
    gates_out_k<<<pwGrid, 256>>>(s + OFF_PART, Wproj, s + OFF_GC, W_out, b_out, out);
}

// round 11
// speedup vs baseline: 3.4436x; 1.0379x over previous
#include <cuda_runtime.h>
#include <math.h>

// Problem constants
#define NB    4
#define CC    64
#define HEADS 4
#define HCH   16
#define HH    48
#define WW    48
#define PP    (HH*WW)     // 2304
#define VH    46
#define VW    46
#define DD    (VH*VW)     // 2116

#define LOG2E 1.4426950408889634f

// Scratch layout (floats)
#define OFF_XIN   0
#define OFF_Q0    (OFF_XIN  + NB*CC*PP)
#define OFF_A0    (OFF_Q0   + NB*CC*PP)
#define OFF_K0    (OFF_A0   + NB*CC*PP)
#define OFF_V0    (OFF_K0   + NB*CC*DD)
#define OFF_S     (OFF_V0   + NB*CC*DD)
#define OFF_GC    (OFF_S    + NB*CC*9)
#define SCRATCH_TOTAL (OFF_GC + NB*3*CC)

__device__ float g_scratch[SCRATCH_TOTAL];

// ---- packed fp32x2 helpers -------------------------------------------------
typedef unsigned long long u64t;

__device__ __forceinline__ u64t pack2(float a, float b) {
    u64t r; asm("mov.b64 %0, {%1,%2};" : "=l"(r) : "f"(a), "f"(b)); return r;
}
__device__ __forceinline__ float2 unpack2(u64t v) {
    float2 r; asm("mov.b64 {%0,%1}, %2;" : "=f"(r.x), "=f"(r.y) : "l"(v)); return r;
}
__device__ __forceinline__ u64t ffma2(u64t a, u64t b, u64t c) {
    u64t d; asm("fma.rn.f32x2 %0, %1, %2, %3;" : "=l"(d) : "l"(a), "l"(b), "l"(c)); return d;
}
__device__ __forceinline__ float ex2(float x) {
    float r; asm("ex2.approx.f32 %0, %1;" : "=f"(r) : "f"(x)); return r;
}
__device__ __forceinline__ unsigned f2tf(float x) {
    unsigned r; asm("cvt.rna.tf32.f32 %0, %1;" : "=r"(r) : "f"(x)); return r;
}
// m16n8k8 tf32 mma, fp32 accumulate in-place.
__device__ __forceinline__ void mma_tf32(
    float& d0, float& d1, float& d2, float& d3,
    unsigned a0, unsigned a1, unsigned a2, unsigned a3,
    unsigned b0, unsigned b1)
{
    asm volatile(
        "mma.sync.aligned.m16n8k8.row.col.f32.tf32.tf32.f32 "
        "{%0,%1,%2,%3}, {%4,%5,%6,%7}, {%8,%9}, {%0,%1,%2,%3};\n"
        : "+f"(d0), "+f"(d1), "+f"(d2), "+f"(d3)
        : "r"(a0), "r"(a1), "r"(a2), "r"(a3), "r"(b0), "r"(b1));
}

// ---------------------------------------------------------------------------
// Pointwise 1x1 conv (input projection).
// ---------------------------------------------------------------------------
__global__ __launch_bounds__(256) void pointwise_k(
    const float* __restrict__ in, const float* __restrict__ wmat,
    const float* __restrict__ bias, float* __restrict__ out)
{
    __shared__ float swT[CC*CC];   // [c][o]
    __shared__ float sx[CC][64];   // [c][px]
    const int n  = blockIdx.y;
    const int p0 = blockIdx.x * 64;

    for (int idx = threadIdx.x; idx < CC*CC; idx += 256) {
        int o = idx & 63, c = idx >> 6;
        swT[c*CC + o] = wmat[o*CC + c];
        sx[c][o] = in[(n*CC + c)*PP + p0 + o];
    }
    __syncthreads();

    const int px  = threadIdx.x >> 2;
    const int ocg = threadIdx.x & 3;

    float acc[16];
    #pragma unroll
    for (int u = 0; u < 16; u++) acc[u] = bias[ocg + 4*u];

    #pragma unroll 4
    for (int c = 0; c < CC; c++) {
        float xv = sx[c][px];
        #pragma unroll
        for (int u = 0; u < 16; u++)
            acc[u] += swT[c*CC + ocg + 4*u] * xv;
    }

    #pragma unroll
    for (int u = 0; u < 16; u++)
        out[(n*CC + ocg + 4*u)*PP + p0 + px] = acc[u];
}

// ---------------------------------------------------------------------------
// Fused 3x3 convs, 2 output rows per block, FFMA2 over x-pixel pairs.
// ---------------------------------------------------------------------------
__global__ __launch_bounds__(256) void conv3_k(
    const float* __restrict__ xin,
    const float* __restrict__ Wq, const float* __restrict__ Wk,
    const float* __restrict__ Wv,
    float* __restrict__ Q0, float* __restrict__ K0, float* __restrict__ V0)
{
    const int br = blockIdx.z;
    const int yp = blockIdx.x;
    const int n  = blockIdx.y;
    if (br != 0 && yp >= VH/2) return;

    const float* wgt; float* out; int ow, ohw, ofs;
    if (br == 0)      { wgt = Wq; out = Q0; ow = WW; ohw = PP; ofs = -1; }
    else if (br == 1) { wgt = Wk; out = K0; ow = VW; ohw = DD; ofs = 0;  }
    else              { wgt = Wv; out = V0; ow = VW; ohw = DD; ofs = 0;  }

    const int y0 = yp * 2;

    __shared__ __align__(16) float tile[32][4][52];
    const float* inN = xin + n*CC*PP;

    const int oc = threadIdx.x >> 2;
    const int x0 = (threadIdx.x & 3) * 12;   // 16B aligned
    const float* wo = wgt + oc*(CC*9);

    u64t acc0[6], acc1[6];
    #pragma unroll
    for (int m = 0; m < 6; m++) { acc0[m] = 0ULL; acc1[m] = 0ULL; }

    for (int half = 0; half < 2; half++) {
        const int cbase = half * 32;
        __syncthreads();
        for (int idx = threadIdx.x; idx < 32*4*52; idx += 256) {
            int c = idx / 208, rem = idx % 208, r = rem / 52, j = rem % 52;
            int gy = y0 + r + ofs, gx = j + ofs;
            float v = 0.f;
            if (gy >= 0 && gy < HH && gx >= 0 && gx < WW)
                v = inN[(cbase + c)*PP + gy*WW + gx];
            tile[c][r][j] = v;
        }
        __syncthreads();

        #pragma unroll 2
        for (int c = 0; c < 32; c++) {
            u64t wd[9];
            #pragma unroll
            for (int t = 0; t < 9; t++) {
                float w = __ldg(wo + (cbase + c)*9 + t);
                wd[t] = pack2(w, w);
            }

            #pragma unroll
            for (int r = 0; r < 4; r++) {
                const ulonglong2* tp = (const ulonglong2*)&tile[c][r][x0];
                ulonglong2 Aq = tp[0], Bq = tp[1], Cq = tp[2], Dq = tp[3];
                u64t P[8] = {Aq.x, Aq.y, Bq.x, Bq.y, Cq.x, Cq.y, Dq.x, Dq.y};
                u64t O[6];
                #pragma unroll
                for (int m = 0; m < 6; m++) {
                    float2 lo = unpack2(P[m]);
                    float2 hi = unpack2(P[m+1]);
                    O[m] = pack2(lo.y, hi.x);
                }
                if (r < 3) {
                    u64t w0 = wd[r*3+0], w1 = wd[r*3+1], w2 = wd[r*3+2];
                    #pragma unroll
                    for (int m = 0; m < 6; m++) {
                        acc0[m] = ffma2(w0, P[m],   acc0[m]);
                        acc0[m] = ffma2(w1, O[m],   acc0[m]);
                        acc0[m] = ffma2(w2, P[m+1], acc0[m]);
                    }
                }
                if (r > 0) {
                    u64t w0 = wd[(r-1)*3+0], w1 = wd[(r-1)*3+1], w2 = wd[(r-1)*3+2];
                    #pragma unroll
                    for (int m = 0; m < 6; m++) {
                        acc1[m] = ffma2(w0, P[m],   acc1[m]);
                        acc1[m] = ffma2(w1, O[m],   acc1[m]);
                        acc1[m] = ffma2(w2, P[m+1], acc1[m]);
                    }
                }
            }
        }
    }

    float* ob0 = out + (n*CC + oc)*ohw + y0*ow;
    float* ob1 = ob0 + ow;
    #pragma unroll
    for (int m = 0; m < 6; m++) {
        float2 a = unpack2(acc0[m]);
        float2 b = unpack2(acc1[m]);
        int x = x0 + 2*m;
        if (x < ow)     { ob0[x]   = a.x; ob1[x]   = b.x; }
        if (x + 1 < ow) { ob0[x+1] = a.y; ob1[x+1] = b.y; }
    }
}

// ---------------------------------------------------------------------------
// Window sums.
// ---------------------------------------------------------------------------
__global__ __launch_bounds__(256) void winsum_k(
    const float* __restrict__ xin, float* __restrict__ S)
{
    const int c = blockIdx.x, n = blockIdx.y;
    const float* ib = xin + (n*CC + c)*PP;

    float rect[9];
    #pragma unroll
    for (int i = 0; i < 9; i++) rect[i] = 0.f;

    for (int idx = threadIdx.x; idx < PP; idx += 256) {
        int y = idx / WW, x = idx % WW;
        float v = ib[idx];
        int rlo = y - 45 > 0 ? y - 45 : 0;
        int rhi = y < 2 ? y : 2;
        int slo = x - 45 > 0 ? x - 45 : 0;
        int shi = x < 2 ? x : 2;
        for (int r = rlo; r <= rhi; r++)
            for (int s = slo; s <= shi; s++)
                rect[r*3 + s] += v;
    }
    #pragma unroll
    for (int i = 0; i < 9; i++) {
        #pragma unroll
        for (int off = 16; off > 0; off >>= 1)
            rect[i] += __shfl_xor_sync(0xffffffff, rect[i], off);
    }
    __shared__ float red[8][9];
    const int warp = threadIdx.x >> 5, lane = threadIdx.x & 31;
    if (lane == 0) {
        #pragma unroll
        for (int i = 0; i < 9; i++) red[warp][i] = rect[i];
    }
    __syncthreads();
    if (threadIdx.x < 9) {
        float s = 0.f;
        #pragma unroll
        for (int w = 0; w < 8; w++) s += red[w][threadIdx.x];
        S[(n*CC + c)*9 + threadIdx.x] = s;
    }
}

// ---------------------------------------------------------------------------
// Attention via tf32 mma.sync (tensor pipe). 128 threads = 4 warps; each warp
// owns 16 queries. K/V staged per 96-key chunk into smem in exact B-fragment
// order (one LDS.64 per mma operand). S computed as m16n8k8 C-frags, exp'd,
// reshuffled to A-frags for PV. Out-of-range keys masked (p=0, v=0).
// ---------------------------------------------------------------------------
#define TK  96
#define NKG 12
__global__ __launch_bounds__(128) void attn_mma_k(
    const float* __restrict__ q0, const float* __restrict__ k0,
    const float* __restrict__ v0, float* __restrict__ A0)
{
    __shared__ __align__(8) unsigned skf[NKG][2][32][2];  // [kg][kstep][lane][reg]
    __shared__ __align__(8) unsigned svf[NKG][2][32][2];  // [kg][nhalf][lane][reg]

    const int nh = blockIdx.y;
    const int n = nh >> 2, head = nh & 3;
    const int warp = threadIdx.x >> 5;
    const int lane = threadIdx.x & 31;
    const int g = lane >> 2, t = lane & 3;
    const int qb = blockIdx.x * 64 + warp * 16;

    const float* qsl = q0 + (n*CC + head*HCH)*PP;
    const float* ksl = k0 + (n*CC + head*HCH)*DD;
    const float* vsl = v0 + (n*CC + head*HCH)*DD;

    // Q A-fragments (2 ksteps), log2e folded, tf32.
    unsigned qa[2][4];
    #pragma unroll
    for (int ks = 0; ks < 2; ks++) {
        int cA = ks*8 + t, cB = cA + 4;
        qa[ks][0] = f2tf(qsl[cA*PP + qb + g]     * LOG2E);
        qa[ks][1] = f2tf(qsl[cA*PP + qb + 8 + g] * LOG2E);
        qa[ks][2] = f2tf(qsl[cB*PP + qb + g]     * LOG2E);
        qa[ks][3] = f2tf(qsl[cB*PP + qb + 8 + g] * LOG2E);
    }

    float o00=0.f,o01=0.f,o02=0.f,o03=0.f;   // channels 0..7
    float o10=0.f,o11=0.f,o12=0.f,o13=0.f;   // channels 8..15
    float l_lo = 0.f, l_hi = 0.f;
    const unsigned fm = 0xffffffffu;

    for (int d0 = 0; d0 < DD; d0 += TK) {
        __syncthreads();
        // --- stage K fragments: skf[kg][ks][4*g2+t2][r] = K[ks*8+t2+4r][d0+kg*8+g2]
        for (int task = threadIdx.x; task < 192; task += 128) {
            int kg = task >> 4;
            int ks = (task >> 3) & 1;
            int t2 = (task >> 1) & 3;
            int r  = task & 1;
            int c  = ks*8 + t2 + 4*r;
            const float4* src = (const float4*)(ksl + c*DD + d0 + kg*8);
            float4 f0 = src[0], f1 = src[1];
            float v[8] = {f0.x,f0.y,f0.z,f0.w,f1.x,f1.y,f1.z,f1.w};
            #pragma unroll
            for (int g2 = 0; g2 < 8; g2++)
                skf[kg][ks][4*g2 + t2][r] = f2tf(v[g2]);
        }
        // --- stage V fragments: svf[kg][h][4*g2+t2][r] = V[8h+g2][d0+kg*8+t2+4r]
        for (int task = threadIdx.x; task < 192; task += 128) {
            int kg = task >> 4;
            int h  = (task >> 3) & 1;
            int g2 = task & 7;
            int c  = 8*h + g2;
            int d  = d0 + kg*8;
            const float4* src = (const float4*)(vsl + c*DD + d);
            float4 f0 = src[0], f1 = src[1];
            float v[8] = {f0.x,f0.y,f0.z,f0.w,f1.x,f1.y,f1.z,f1.w};
            #pragma unroll
            for (int j = 0; j < 8; j++) {
                float val = (d + j < DD) ? v[j] : 0.f;
                svf[kg][h][4*g2 + (j & 3)][j >> 2] = f2tf(val);
            }
        }
        __syncthreads();

        #pragma unroll 1
        for (int kg = 0; kg < NKG; kg++) {
            float s0=0.f,s1=0.f,s2=0.f,s3=0.f;
            {
                uint2 bk0 = *(const uint2*)&skf[kg][0][lane][0];
                mma_tf32(s0,s1,s2,s3, qa[0][0],qa[0][1],qa[0][2],qa[0][3], bk0.x,bk0.y);
                uint2 bk1 = *(const uint2*)&skf[kg][1][lane][0];
                mma_tf32(s0,s1,s2,s3, qa[1][0],qa[1][1],qa[1][2],qa[1][3], bk1.x,bk1.y);
            }
            int col0 = d0 + kg*8 + 2*t;
            bool v0c = col0 < DD, v1c = (col0 + 1) < DD;
            float p0 = v0c ? ex2(s0) : 0.f;
            float p1 = v1c ? ex2(s1) : 0.f;
            float p2 = v0c ? ex2(s2) : 0.f;
            float p3 = v1c ? ex2(s3) : 0.f;
            l_lo += p0 + p1;
            l_hi += p2 + p3;

            // C-frag -> A-frag (P) via shuffles.
            int srcA = (lane & ~3) | (t >> 1);
            int srcB = srcA + 2;
            float x0 = __shfl_sync(fm, p0, srcA), x1 = __shfl_sync(fm, p1, srcA);
            float y0 = __shfl_sync(fm, p0, srcB), y1 = __shfl_sync(fm, p1, srcB);
            float z0 = __shfl_sync(fm, p2, srcA), z1 = __shfl_sync(fm, p3, srcA);
            float w0 = __shfl_sync(fm, p2, srcB), w1 = __shfl_sync(fm, p3, srcB);
            bool odd = (t & 1);
            unsigned a0 = f2tf(odd ? x1 : x0);
            unsigned a1 = f2tf(odd ? z1 : z0);
            unsigned a2 = f2tf(odd ? y1 : y0);
            unsigned a3 = f2tf(odd ? w1 : w0);

            uint2 bv0 = *(const uint2*)&svf[kg][0][lane][0];
            mma_tf32(o00,o01,o02,o03, a0,a1,a2,a3, bv0.x,bv0.y);
            uint2 bv1 = *(const uint2*)&svf[kg][1][lane][0];
            mma_tf32(o10,o11,o12,o13, a0,a1,a2,a3, bv1.x,bv1.y);
        }
    }

    // denominator across the 4 threads of each row group
    l_lo += __shfl_xor_sync(fm, l_lo, 1);
    l_lo += __shfl_xor_sync(fm, l_lo, 2);
    l_hi += __shfl_xor_sync(fm, l_hi, 1);
    l_hi += __shfl_xor_sync(fm, l_hi, 2);
    float inv_lo = 1.f / l_lo, inv_hi = 1.f / l_hi;

    float* ab = A0 + (n*CC + head*HCH)*PP;
    int qlo = qb + g, qhi = qb + 8 + g;
    ab[(2*t    )*PP + qlo] = o00 * inv_lo;
    ab[(2*t + 1)*PP + qlo] = o01 * inv_lo;
    ab[(2*t    )*PP + qhi] = o02 * inv_hi;
    ab[(2*t + 1)*PP + qhi] = o03 * inv_hi;
    ab[(8 + 2*t    )*PP + qlo] = o10 * inv_lo;
    ab[(8 + 2*t + 1)*PP + qlo] = o11 * inv_lo;
    ab[(8 + 2*t    )*PP + qhi] = o12 * inv_hi;
    ab[(8 + 2*t + 1)*PP + qhi] = o13 * inv_hi;
}

// ---------------------------------------------------------------------------
// a2 from window sums + Wv[2], then gate bias constants. One block per n.
// ---------------------------------------------------------------------------
__global__ __launch_bounds__(256) void a2gc_k(
    const float* __restrict__ S, const float* __restrict__ Wv,
    const float* __restrict__ Wproj, const float* __restrict__ bg,
    float* __restrict__ gc)
{
    __shared__ float sS[CC*9];
    __shared__ float a2[CC];
    const int n = blockIdx.x;
    const int t = threadIdx.x;
    const float* Wv2 = Wv + 2*CC*CC*9;

    for (int i = t; i < CC*9; i += 256) sS[i] = S[n*CC*9 + i];
    __syncthreads();

    {
        const int o = t >> 2, part = t & 3;
        const float* wrow = Wv2 + o*(CC*9) + part*(16*9);
        const float* srow = sS + part*(16*9);
        float acc = 0.f;
        #pragma unroll 4
        for (int i = 0; i < 16*9; i++) acc += wrow[i] * srow[i];
        acc += __shfl_xor_sync(0xffffffff, acc, 1);
        acc += __shfl_xor_sync(0xffffffff, acc, 2);
        if (part == 0) a2[o] = acc * (1.f / (float)DD);
    }
    __syncthreads();

    if (t < 3*CC) {
        int gi = t / CC, o = t % CC;
        int gate = (gi == 0) ? 0 : (gi == 1 ? 2 : 3);
        const float* wp = Wproj + ((gate*4 + 2)*CC + o)*CC;
        float acc = bg[gate*CC + o];
        #pragma unroll
        for (int c = 0; c < CC; c++) acc += wp[c] * a2[c];
        gc[(n*3 + gi)*CC + o] = acc;
    }
}

// ---------------------------------------------------------------------------
// Gates i,g,o + cell + hidden + fused output 1x1 projection (reads A0).
// ---------------------------------------------------------------------------
__global__ __launch_bounds__(256) void gates_out_k(
    const float* __restrict__ A0, const float* __restrict__ Wproj,
    const float* __restrict__ gc, const float* __restrict__ W_out,
    const float* __restrict__ b_out, float* __restrict__ out)
{
    __shared__ float swiT[CC*CC];  // [c][o] ; later reused for W_out^T
    __shared__ float swgT[CC*CC];
    __shared__ float sx[CC][64];   // A0 tile; later reused for hout
    const int n  = blockIdx.y;
    const int p0 = blockIdx.x * 64;

    const float* Wi = Wproj + (0*4 + 0)*CC*CC;
    const float* Wg = Wproj + (2*4 + 0)*CC*CC;
    const float* Wo = Wproj + (3*4 + 0)*CC*CC;
    for (int idx = threadIdx.x; idx < CC*CC; idx += 256) {
        int o = idx & 63, c = idx >> 6;
        swiT[c*CC + o] = Wi[o*CC + c];
        swgT[c*CC + o] = Wg[o*CC + c];
        sx[c][o] = A0[(n*CC + c)*PP + p0 + o];
    }
    __syncthreads();

    const int px  = threadIdx.x >> 2;
    const int ocg = threadIdx.x & 3;
    const float* gcn = gc + n*3*CC;

    float ai[16], ag[16], ao[16];
    #pragma unroll
    for (int u = 0; u < 16; u++) {
        int oc = ocg + 4*u;
        ai[u] = gcn[oc]; ag[u] = gcn[CC + oc]; ao[u] = gcn[2*CC + oc];
    }

    #pragma unroll 2
    for (int c = 0; c < CC; c++) {
        float xv = sx[c][px];
        #pragma unroll
        for (int u = 0; u < 16; u++) {
            int oc = ocg + 4*u;
            ai[u] += swiT[c*CC + oc] * xv;
            ag[u] += swgT[c*CC + oc] * xv;
            ao[u] += __ldg(Wo + oc*CC + c) * xv;
        }
    }

    float hv[16];
    #pragma unroll
    for (int u = 0; u < 16; u++) {
        float ig = 1.f / (1.f + __expf(-ai[u]));
        float gg = tanhf(ag[u]);
        float og = 1.f / (1.f + __expf(-ao[u]));
        hv[u] = og * tanhf(ig * gg);
    }

    __syncthreads();
    #pragma unroll
    for (int u = 0; u < 16; u++) sx[ocg + 4*u][px] = hv[u];
    for (int idx = threadIdx.x; idx < CC*CC; idx += 256) {
        int o = idx & 63, c = idx >> 6;
        swiT[c*CC + o] = W_out[o*CC + c];
    }
    __syncthreads();

    float acc[16];
    #pragma unroll
    for (int u = 0; u < 16; u++) acc[u] = b_out[ocg + 4*u];
    #pragma unroll 4
    for (int c = 0; c < CC; c++) {
        float xv = sx[c][px];
        #pragma unroll
        for (int u = 0; u < 16; u++)
            acc[u] += swiT[c*CC + ocg + 4*u] * xv;
    }
    #pragma unroll
    for (int u = 0; u < 16; u++)
        out[(n*CC + ocg + 4*u)*PP + p0 + px] = acc[u];
}

// ---------------------------------------------------------------------------
extern "C" void kernel_launch(void* const* d_in, const int* in_sizes, int n_in,
                              void* d_out, int out_size)
{
    const float* x     = (const float*)d_in[0];
    const float* W_in  = (const float*)d_in[1];
    const float* b_in  = (const float*)d_in[2];
    const float* Wq    = (const float*)d_in[3];
    const float* Wk    = (const float*)d_in[4];
    const float* Wv    = (const float*)d_in[5];
    const float* Wproj = (const float*)d_in[6];
    const float* b_g   = (const float*)d_in[7];
    const float* W_out = (const float*)d_in[8];
    const float* b_out = (const float*)d_in[9];
    float* out = (float*)d_out;

    void* sp = nullptr;
    cudaGetSymbolAddress(&sp, g_scratch);
    float* s = (float*)sp;

    const dim3 pwGrid(PP/64, NB);

    pointwise_k<<<pwGrid, 256>>>(x, W_in, b_in, s + OFF_XIN);
    conv3_k<<<dim3(HH/2, NB, 3), 256>>>(s + OFF_XIN, Wq, Wk, Wv,
                                        s + OFF_Q0, s + OFF_K0, s + OFF_V0);
    winsum_k<<<dim3(CC, NB), 256>>>(s + OFF_XIN, s + OFF_S);
    attn_mma_k<<<dim3(PP/64, NB*HEADS), 128>>>(s + OFF_Q0, s + OFF_K0,
                                               s + OFF_V0, s + OFF_A0);
    a2gc_k<<<NB, 256>>>(s + OFF_S, Wv, Wproj, b_g, s + OFF_GC);
    gates_out_k<<<pwGrid, 256>>>(s + OFF_A0, Wproj, s + OFF_GC, W_out, b_out, out);
}

// round 14
// speedup vs baseline: 3.6575x; 1.0621x over previous
#include <cuda_runtime.h>
#include <math.h>

// Problem constants
#define NB    4
#define CC    64
#define HEADS 4
#define HCH   16
#define HH    48
#define WW    48
#define PP    (HH*WW)     // 2304
#define VH    46
#define VW    46
#define DD    (VH*VW)     // 2116

#define LOG2E 1.4426950408889634f

// Scratch layout (floats)
#define OFF_XIN   0
#define OFF_Q0    (OFF_XIN  + NB*CC*PP)
#define OFF_A0    (OFF_Q0   + NB*CC*PP)
#define OFF_K0    (OFF_A0   + NB*CC*PP)
#define OFF_V0    (OFF_K0   + NB*CC*DD)
#define OFF_S     (OFF_V0   + NB*CC*DD)
#define OFF_GC    (OFF_S    + NB*CC*9)
#define SCRATCH_TOTAL (OFF_GC + NB*3*CC)

__device__ float g_scratch[SCRATCH_TOTAL];

// ---- packed fp32x2 helpers -------------------------------------------------
typedef unsigned long long u64t;

__device__ __forceinline__ u64t pack2(float a, float b) {
    u64t r; asm("mov.b64 %0, {%1,%2};" : "=l"(r) : "f"(a), "f"(b)); return r;
}
__device__ __forceinline__ float2 unpack2(u64t v) {
    float2 r; asm("mov.b64 {%0,%1}, %2;" : "=f"(r.x), "=f"(r.y) : "l"(v)); return r;
}
__device__ __forceinline__ u64t ffma2(u64t a, u64t b, u64t c) {
    u64t d; asm("fma.rn.f32x2 %0, %1, %2, %3;" : "=l"(d) : "l"(a), "l"(b), "l"(c)); return d;
}
__device__ __forceinline__ float ex2(float x) {
    float r; asm("ex2.approx.f32 %0, %1;" : "=f"(r) : "f"(x)); return r;
}
__device__ __forceinline__ unsigned f2tf(float x) {
    unsigned r; asm("cvt.rna.tf32.f32 %0, %1;" : "=r"(r) : "f"(x)); return r;
}
// m16n8k8 tf32 mma, fp32 accumulate in-place.
__device__ __forceinline__ void mma_tf32(
    float& d0, float& d1, float& d2, float& d3,
    unsigned a0, unsigned a1, unsigned a2, unsigned a3,
    unsigned b0, unsigned b1)
{
    asm volatile(
        "mma.sync.aligned.m16n8k8.row.col.f32.tf32.tf32.f32 "
        "{%0,%1,%2,%3}, {%4,%5,%6,%7}, {%8,%9}, {%0,%1,%2,%3};\n"
        : "+f"(d0), "+f"(d1), "+f"(d2), "+f"(d3)
        : "r"(a0), "r"(a1), "r"(a2), "r"(a3), "r"(b0), "r"(b1));
}

// ---------------------------------------------------------------------------
// Pointwise 1x1 conv (input projection).
// ---------------------------------------------------------------------------
__global__ __launch_bounds__(256) void pointwise_k(
    const float* __restrict__ in, const float* __restrict__ wmat,
    const float* __restrict__ bias, float* __restrict__ out)
{
    __shared__ float swT[CC*CC];   // [c][o]
    __shared__ float sx[CC][64];   // [c][px]
    const int n  = blockIdx.y;
    const int p0 = blockIdx.x * 64;

    for (int idx = threadIdx.x; idx < CC*CC; idx += 256) {
        int o = idx & 63, c = idx >> 6;
        swT[c*CC + o] = wmat[o*CC + c];
        sx[c][o] = in[(n*CC + c)*PP + p0 + o];
    }
    __syncthreads();

    const int px  = threadIdx.x >> 2;
    const int ocg = threadIdx.x & 3;

    float acc[16];
    #pragma unroll
    for (int u = 0; u < 16; u++) acc[u] = bias[ocg + 4*u];

    #pragma unroll 4
    for (int c = 0; c < CC; c++) {
        float xv = sx[c][px];
        #pragma unroll
        for (int u = 0; u < 16; u++)
            acc[u] += swT[c*CC + ocg + 4*u] * xv;
    }

    #pragma unroll
    for (int u = 0; u < 16; u++)
        out[(n*CC + ocg + 4*u)*PP + p0 + px] = acc[u];
}

// ---------------------------------------------------------------------------
// Fused 3x3 convs, 2 output rows per block, FFMA2 over x-pixel pairs.
// ---------------------------------------------------------------------------
__global__ __launch_bounds__(256) void conv3_k(
    const float* __restrict__ xin,
    const float* __restrict__ Wq, const float* __restrict__ Wk,
    const float* __restrict__ Wv,
    float* __restrict__ Q0, float* __restrict__ K0, float* __restrict__ V0)
{
    const int br = blockIdx.z;
    const int yp = blockIdx.x;
    const int n  = blockIdx.y;
    if (br != 0 && yp >= VH/2) return;

    const float* wgt; float* out; int ow, ohw, ofs;
    if (br == 0)      { wgt = Wq; out = Q0; ow = WW; ohw = PP; ofs = -1; }
    else if (br == 1) { wgt = Wk; out = K0; ow = VW; ohw = DD; ofs = 0;  }
    else              { wgt = Wv; out = V0; ow = VW; ohw = DD; ofs = 0;  }

    const int y0 = yp * 2;

    __shared__ __align__(16) float tile[32][4][52];
    const float* inN = xin + n*CC*PP;

    const int oc = threadIdx.x >> 2;
    const int x0 = (threadIdx.x & 3) * 12;   // 16B aligned
    const float* wo = wgt + oc*(CC*9);

    u64t acc0[6], acc1[6];
    #pragma unroll
    for (int m = 0; m < 6; m++) { acc0[m] = 0ULL; acc1[m] = 0ULL; }

    for (int half = 0; half < 2; half++) {
        const int cbase = half * 32;
        __syncthreads();
        for (int idx = threadIdx.x; idx < 32*4*52; idx += 256) {
            int c = idx / 208, rem = idx % 208, r = rem / 52, j = rem % 52;
            int gy = y0 + r + ofs, gx = j + ofs;
            float v = 0.f;
            if (gy >= 0 && gy < HH && gx >= 0 && gx < WW)
                v = inN[(cbase + c)*PP + gy*WW + gx];
            tile[c][r][j] = v;
        }
        __syncthreads();

        #pragma unroll 2
        for (int c = 0; c < 32; c++) {
            u64t wd[9];
            #pragma unroll
            for (int t = 0; t < 9; t++) {
                float w = __ldg(wo + (cbase + c)*9 + t);
                wd[t] = pack2(w, w);
            }

            #pragma unroll
            for (int r = 0; r < 4; r++) {
                const ulonglong2* tp = (const ulonglong2*)&tile[c][r][x0];
                ulonglong2 Aq = tp[0], Bq = tp[1], Cq = tp[2], Dq = tp[3];
                u64t P[8] = {Aq.x, Aq.y, Bq.x, Bq.y, Cq.x, Cq.y, Dq.x, Dq.y};
                u64t O[6];
                #pragma unroll
                for (int m = 0; m < 6; m++) {
                    float2 lo = unpack2(P[m]);
                    float2 hi = unpack2(P[m+1]);
                    O[m] = pack2(lo.y, hi.x);
                }
                if (r < 3) {
                    u64t w0 = wd[r*3+0], w1 = wd[r*3+1], w2 = wd[r*3+2];
                    #pragma unroll
                    for (int m = 0; m < 6; m++) {
                        acc0[m] = ffma2(w0, P[m],   acc0[m]);
                        acc0[m] = ffma2(w1, O[m],   acc0[m]);
                        acc0[m] = ffma2(w2, P[m+1], acc0[m]);
                    }
                }
                if (r > 0) {
                    u64t w0 = wd[(r-1)*3+0], w1 = wd[(r-1)*3+1], w2 = wd[(r-1)*3+2];
                    #pragma unroll
                    for (int m = 0; m < 6; m++) {
                        acc1[m] = ffma2(w0, P[m],   acc1[m]);
                        acc1[m] = ffma2(w1, O[m],   acc1[m]);
                        acc1[m] = ffma2(w2, P[m+1], acc1[m]);
                    }
                }
            }
        }
    }

    float* ob0 = out + (n*CC + oc)*ohw + y0*ow;
    float* ob1 = ob0 + ow;
    #pragma unroll
    for (int m = 0; m < 6; m++) {
        float2 a = unpack2(acc0[m]);
        float2 b = unpack2(acc1[m]);
        int x = x0 + 2*m;
        if (x < ow)     { ob0[x]   = a.x; ob1[x]   = b.x; }
        if (x + 1 < ow) { ob0[x+1] = a.y; ob1[x+1] = b.y; }
    }
}

// ---------------------------------------------------------------------------
// Window sums.
// ---------------------------------------------------------------------------
__global__ __launch_bounds__(256) void winsum_k(
    const float* __restrict__ xin, float* __restrict__ S)
{
    const int c = blockIdx.x, n = blockIdx.y;
    const float* ib = xin + (n*CC + c)*PP;

    float rect[9];
    #pragma unroll
    for (int i = 0; i < 9; i++) rect[i] = 0.f;

    for (int idx = threadIdx.x; idx < PP; idx += 256) {
        int y = idx / WW, x = idx % WW;
        float v = ib[idx];
        int rlo = y - 45 > 0 ? y - 45 : 0;
        int rhi = y < 2 ? y : 2;
        int slo = x - 45 > 0 ? x - 45 : 0;
        int shi = x < 2 ? x : 2;
        for (int r = rlo; r <= rhi; r++)
            for (int s = slo; s <= shi; s++)
                rect[r*3 + s] += v;
    }
    #pragma unroll
    for (int i = 0; i < 9; i++) {
        #pragma unroll
        for (int off = 16; off > 0; off >>= 1)
            rect[i] += __shfl_xor_sync(0xffffffff, rect[i], off);
    }
    __shared__ float red[8][9];
    const int warp = threadIdx.x >> 5, lane = threadIdx.x & 31;
    if (lane == 0) {
        #pragma unroll
        for (int i = 0; i < 9; i++) red[warp][i] = rect[i];
    }
    __syncthreads();
    if (threadIdx.x < 9) {
        float s = 0.f;
        #pragma unroll
        for (int w = 0; w < 8; w++) s += red[w][threadIdx.x];
        S[(n*CC + c)*9 + threadIdx.x] = s;
    }
}

// ---------------------------------------------------------------------------
// Attention via tf32 mma.sync, phase-batched for ILP:
//  phase 1: all 24 QK mmas of the 96-key chunk (independent)
//  phase 2: all 48 ex2 + masks + denominator
//  phase 3: shuffles + PV mmas with even/odd-kg accumulator chains
// Staging + fragment layouts identical to the verified R11 version.
// ---------------------------------------------------------------------------
#define TK  96
#define NKG 12
__global__ __launch_bounds__(128, 4) void attn_mma_k(
    const float* __restrict__ q0, const float* __restrict__ k0,
    const float* __restrict__ v0, float* __restrict__ A0)
{
    __shared__ __align__(8) unsigned skf[NKG][2][32][2];  // [kg][kstep][lane][reg]
    __shared__ __align__(8) unsigned svf[NKG][2][32][2];  // [kg][nhalf][lane][reg]

    const int nh = blockIdx.y;
    const int n = nh >> 2, head = nh & 3;
    const int warp = threadIdx.x >> 5;
    const int lane = threadIdx.x & 31;
    const int g = lane >> 2, t = lane & 3;
    const int qb = blockIdx.x * 64 + warp * 16;

    const float* qsl = q0 + (n*CC + head*HCH)*PP;
    const float* ksl = k0 + (n*CC + head*HCH)*DD;
    const float* vsl = v0 + (n*CC + head*HCH)*DD;

    // Q A-fragments (2 ksteps), log2e folded, tf32.
    unsigned qa[2][4];
    #pragma unroll
    for (int ks = 0; ks < 2; ks++) {
        int cA = ks*8 + t, cB = cA + 4;
        qa[ks][0] = f2tf(qsl[cA*PP + qb + g]     * LOG2E);
        qa[ks][1] = f2tf(qsl[cA*PP + qb + 8 + g] * LOG2E);
        qa[ks][2] = f2tf(qsl[cB*PP + qb + g]     * LOG2E);
        qa[ks][3] = f2tf(qsl[cB*PP + qb + 8 + g] * LOG2E);
    }

    // even/odd kg accumulator chains
    float oE[8] = {0,0,0,0,0,0,0,0};
    float oO[8] = {0,0,0,0,0,0,0,0};
    float l_lo = 0.f, l_hi = 0.f;
    const unsigned fm = 0xffffffffu;

    #pragma unroll 1
    for (int d0 = 0; d0 < DD; d0 += TK) {
        __syncthreads();
        // --- stage K fragments: skf[kg][ks][4*g2+t2][r] = K[ks*8+t2+4r][d0+kg*8+g2]
        for (int task = threadIdx.x; task < 192; task += 128) {
            int kg = task >> 4;
            int ks = (task >> 3) & 1;
            int t2 = (task >> 1) & 3;
            int r  = task & 1;
            int c  = ks*8 + t2 + 4*r;
            const float4* src = (const float4*)(ksl + c*DD + d0 + kg*8);
            float4 f0 = src[0], f1 = src[1];
            float v[8] = {f0.x,f0.y,f0.z,f0.w,f1.x,f1.y,f1.z,f1.w};
            #pragma unroll
            for (int g2 = 0; g2 < 8; g2++)
                skf[kg][ks][4*g2 + t2][r] = f2tf(v[g2]);
        }
        // --- stage V fragments: svf[kg][h][4*g2+t2][r] = V[8h+g2][d0+kg*8+t2+4r]
        for (int task = threadIdx.x; task < 192; task += 128) {
            int kg = task >> 4;
            int h  = (task >> 3) & 1;
            int g2 = task & 7;
            int c  = 8*h + g2;
            int d  = d0 + kg*8;
            const float4* src = (const float4*)(vsl + c*DD + d);
            float4 f0 = src[0], f1 = src[1];
            float v[8] = {f0.x,f0.y,f0.z,f0.w,f1.x,f1.y,f1.z,f1.w};
            #pragma unroll
            for (int j = 0; j < 8; j++) {
                float val = (d + j < DD) ? v[j] : 0.f;
                svf[kg][h][4*g2 + (j & 3)][j >> 2] = f2tf(val);
            }
        }
        __syncthreads();

        // --- phase 1: all QK mmas (independent)
        float sf[NKG][4];
        #pragma unroll
        for (int kg = 0; kg < NKG; kg++) {
            float s0=0.f,s1=0.f,s2=0.f,s3=0.f;
            uint2 bk0 = *(const uint2*)&skf[kg][0][lane][0];
            mma_tf32(s0,s1,s2,s3, qa[0][0],qa[0][1],qa[0][2],qa[0][3], bk0.x,bk0.y);
            uint2 bk1 = *(const uint2*)&skf[kg][1][lane][0];
            mma_tf32(s0,s1,s2,s3, qa[1][0],qa[1][1],qa[1][2],qa[1][3], bk1.x,bk1.y);
            sf[kg][0]=s0; sf[kg][1]=s1; sf[kg][2]=s2; sf[kg][3]=s3;
        }

        // --- phase 2: exp + mask + denominator
        #pragma unroll
        for (int kg = 0; kg < NKG; kg++) {
            int col0 = d0 + kg*8 + 2*t;
            bool v0c = col0 < DD, v1c = (col0 + 1) < DD;
            float p0 = v0c ? ex2(sf[kg][0]) : 0.f;
            float p1 = v1c ? ex2(sf[kg][1]) : 0.f;
            float p2 = v0c ? ex2(sf[kg][2]) : 0.f;
            float p3 = v1c ? ex2(sf[kg][3]) : 0.f;
            l_lo += p0 + p1;
            l_hi += p2 + p3;
            sf[kg][0]=p0; sf[kg][1]=p1; sf[kg][2]=p2; sf[kg][3]=p3;
        }

        // --- phase 3: C-frag -> A-frag shuffles + PV mmas (2 chains x 2 targets)
        #pragma unroll
        for (int kg = 0; kg < NKG; kg++) {
            float p0 = sf[kg][0], p1 = sf[kg][1], p2 = sf[kg][2], p3 = sf[kg][3];
            int srcA = (lane & ~3) | (t >> 1);
            int srcB = srcA + 2;
            float x0 = __shfl_sync(fm, p0, srcA), x1 = __shfl_sync(fm, p1, srcA);
            float y0 = __shfl_sync(fm, p0, srcB), y1 = __shfl_sync(fm, p1, srcB);
            float z0 = __shfl_sync(fm, p2, srcA), z1 = __shfl_sync(fm, p3, srcA);
            float w0 = __shfl_sync(fm, p2, srcB), w1 = __shfl_sync(fm, p3, srcB);
            bool odd = (t & 1);
            unsigned a0 = f2tf(odd ? x1 : x0);
            unsigned a1 = f2tf(odd ? z1 : z0);
            unsigned a2 = f2tf(odd ? y1 : y0);
            unsigned a3 = f2tf(odd ? w1 : w0);

            float* oc = (kg & 1) ? oO : oE;
            uint2 bv0 = *(const uint2*)&svf[kg][0][lane][0];
            mma_tf32(oc[0],oc[1],oc[2],oc[3], a0,a1,a2,a3, bv0.x,bv0.y);
            uint2 bv1 = *(const uint2*)&svf[kg][1][lane][0];
            mma_tf32(oc[4],oc[5],oc[6],oc[7], a0,a1,a2,a3, bv1.x,bv1.y);
        }
    }

    float o00 = oE[0]+oO[0], o01 = oE[1]+oO[1], o02 = oE[2]+oO[2], o03 = oE[3]+oO[3];
    float o10 = oE[4]+oO[4], o11 = oE[5]+oO[5], o12 = oE[6]+oO[6], o13 = oE[7]+oO[7];

    // denominator across the 4 threads of each row group
    l_lo += __shfl_xor_sync(fm, l_lo, 1);
    l_lo += __shfl_xor_sync(fm, l_lo, 2);
    l_hi += __shfl_xor_sync(fm, l_hi, 1);
    l_hi += __shfl_xor_sync(fm, l_hi, 2);
    float inv_lo = 1.f / l_lo, inv_hi = 1.f / l_hi;

    float* ab = A0 + (n*CC + head*HCH)*PP;
    int qlo = qb + g, qhi = qb + 8 + g;
    ab[(2*t    )*PP + qlo] = o00 * inv_lo;
    ab[(2*t + 1)*PP + qlo] = o01 * inv_lo;
    ab[(2*t    )*PP + qhi] = o02 * inv_hi;
    ab[(2*t + 1)*PP + qhi] = o03 * inv_hi;
    ab[(8 + 2*t    )*PP + qlo] = o10 * inv_lo;
    ab[(8 + 2*t + 1)*PP + qlo] = o11 * inv_lo;
    ab[(8 + 2*t    )*PP + qhi] = o12 * inv_hi;
    ab[(8 + 2*t + 1)*PP + qhi] = o13 * inv_hi;
}

// ---------------------------------------------------------------------------
// a2 from window sums + Wv[2], then gate bias constants. One block per n.
// ---------------------------------------------------------------------------
__global__ __launch_bounds__(256) void a2gc_k(
    const float* __restrict__ S, const float* __restrict__ Wv,
    const float* __restrict__ Wproj, const float* __restrict__ bg,
    float* __restrict__ gc)
{
    __shared__ float sS[CC*9];
    __shared__ float a2[CC];
    const int n = blockIdx.x;
    const int t = threadIdx.x;
    const float* Wv2 = Wv + 2*CC*CC*9;

    for (int i = t; i < CC*9; i += 256) sS[i] = S[n*CC*9 + i];
    __syncthreads();

    {
        const int o = t >> 2, part = t & 3;
        const float* wrow = Wv2 + o*(CC*9) + part*(16*9);
        const float* srow = sS + part*(16*9);
        float acc = 0.f;
        #pragma unroll 4
        for (int i = 0; i < 16*9; i++) acc += wrow[i] * srow[i];
        acc += __shfl_xor_sync(0xffffffff, acc, 1);
        acc += __shfl_xor_sync(0xffffffff, acc, 2);
        if (part == 0) a2[o] = acc * (1.f / (float)DD);
    }
    __syncthreads();

    if (t < 3*CC) {
        int gi = t / CC, o = t % CC;
        int gate = (gi == 0) ? 0 : (gi == 1 ? 2 : 3);
        const float* wp = Wproj + ((gate*4 + 2)*CC + o)*CC;
        float acc = bg[gate*CC + o];
        #pragma unroll
        for (int c = 0; c < CC; c++) acc += wp[c] * a2[c];
        gc[(n*3 + gi)*CC + o] = acc;
    }
}

// ---------------------------------------------------------------------------
// Gates i,g,o + cell + hidden + fused output 1x1 projection (reads A0).
// ---------------------------------------------------------------------------
__global__ __launch_bounds__(256) void gates_out_k(
    const float* __restrict__ A0, const float* __restrict__ Wproj,
    const float* __restrict__ gc, const float* __restrict__ W_out,
    const float* __restrict__ b_out, float* __restrict__ out)
{
    __shared__ float swiT[CC*CC];  // [c][o] ; later reused for W_out^T
    __shared__ float swgT[CC*CC];
    __shared__ float sx[CC][64];   // A0 tile; later reused for hout
    const int n  = blockIdx.y;
    const int p0 = blockIdx.x * 64;

    const float* Wi = Wproj + (0*4 + 0)*CC*CC;
    const float* Wg = Wproj + (2*4 + 0)*CC*CC;
    const float* Wo = Wproj + (3*4 + 0)*CC*CC;
    for (int idx = threadIdx.x; idx < CC*CC; idx += 256) {
        int o = idx & 63, c = idx >> 6;
        swiT[c*CC + o] = Wi[o*CC + c];
        swgT[c*CC + o] = Wg[o*CC + c];
        sx[c][o] = A0[(n*CC + c)*PP + p0 + o];
    }
    __syncthreads();

    const int px  = threadIdx.x >> 2;
    const int ocg = threadIdx.x & 3;
    const float* gcn = gc + n*3*CC;

    float ai[16], ag[16], ao[16];
    #pragma unroll
    for (int u = 0; u < 16; u++) {
        int oc = ocg + 4*u;
        ai[u] = gcn[oc]; ag[u] = gcn[CC + oc]; ao[u] = gcn[2*CC + oc];
    }

    #pragma unroll 2
    for (int c = 0; c < CC; c++) {
        float xv = sx[c][px];
        #pragma unroll
        for (int u = 0; u < 16; u++) {
            int oc = ocg + 4*u;
            ai[u] += swiT[c*CC + oc] * xv;
            ag[u] += swgT[c*CC + oc] * xv;
            ao[u] += __ldg(Wo + oc*CC + c) * xv;
        }
    }

    float hv[16];
    #pragma unroll
    for (int u = 0; u < 16; u++) {
        float ig = 1.f / (1.f + __expf(-ai[u]));
        float gg = tanhf(ag[u]);
        float og = 1.f / (1.f + __expf(-ao[u]));
        hv[u] = og * tanhf(ig * gg);
    }

    __syncthreads();
    #pragma unroll
    for (int u = 0; u < 16; u++) sx[ocg + 4*u][px] = hv[u];
    for (int idx = threadIdx.x; idx < CC*CC; idx += 256) {
        int o = idx & 63, c = idx >> 6;
        swiT[c*CC + o] = W_out[o*CC + c];
    }
    __syncthreads();

    float acc[16];
    #pragma unroll
    for (int u = 0; u < 16; u++) acc[u] = b_out[ocg + 4*u];
    #pragma unroll 4
    for (int c = 0; c < CC; c++) {
        float xv = sx[c][px];
        #pragma unroll
        for (int u = 0; u < 16; u++)
            acc[u] += swiT[c*CC + ocg + 4*u] * xv;
    }
    #pragma unroll
    for (int u = 0; u < 16; u++)
        out[(n*CC + ocg + 4*u)*PP + p0 + px] = acc[u];
}

// ---------------------------------------------------------------------------
extern "C" void kernel_launch(void* const* d_in, const int* in_sizes, int n_in,
                              void* d_out, int out_size)
{
    const float* x     = (const float*)d_in[0];
    const float* W_in  = (const float*)d_in[1];
    const float* b_in  = (const float*)d_in[2];
    const float* Wq    = (const float*)d_in[3];
    const float* Wk    = (const float*)d_in[4];
    const float* Wv    = (const float*)d_in[5];
    const float* Wproj = (const float*)d_in[6];
    const float* b_g   = (const float*)d_in[7];
    const float* W_out = (const float*)d_in[8];
    const float* b_out = (const float*)d_in[9];
    float* out = (float*)d_out;

    void* sp = nullptr;
    cudaGetSymbolAddress(&sp, g_scratch);
    float* s = (float*)sp;

    const dim3 pwGrid(PP/64, NB);

    pointwise_k<<<pwGrid, 256>>>(x, W_in, b_in, s + OFF_XIN);
    conv3_k<<<dim3(HH/2, NB, 3), 256>>>(s + OFF_XIN, Wq, Wk, Wv,
                                        s + OFF_Q0, s + OFF_K0, s + OFF_V0);
    winsum_k<<<dim3(CC, NB), 256>>>(s + OFF_XIN, s + OFF_S);
    attn_mma_k<<<dim3(PP/64, NB*HEADS), 128>>>(s + OFF_Q0, s + OFF_K0,
                                               s + OFF_V0, s + OFF_A0);
    a2gc_k<<<NB, 256>>>(s + OFF_S, Wv, Wproj, b_g, s + OFF_GC);
    gates_out_k<<<pwGrid, 256>>>(s + OFF_A0, Wproj, s + OFF_GC, W_out, b_out, out);
}

// round 15
// speedup vs baseline: 3.7254x; 1.0186x over previous
#include <cuda_runtime.h>
#include <math.h>

// Problem constants
#define NB    4
#define CC    64
#define HEADS 4
#define HCH   16
#define HH    48
#define WW    48
#define PP    (HH*WW)     // 2304
#define VH    46
#define VW    46
#define DD    (VH*VW)     // 2116

#define LOG2E 1.4426950408889634f

// Scratch layout (floats)
#define OFF_XIN   0
#define OFF_Q0    (OFF_XIN  + NB*CC*PP)
#define OFF_A0    (OFF_Q0   + NB*CC*PP)
#define OFF_K0    (OFF_A0   + NB*CC*PP)
#define OFF_V0    (OFF_K0   + NB*CC*DD)
#define OFF_S     (OFF_V0   + NB*CC*DD)
#define OFF_GC    (OFF_S    + NB*CC*9)
#define SCRATCH_TOTAL (OFF_GC + NB*3*CC)

__device__ float g_scratch[SCRATCH_TOTAL];

// ---- packed fp32x2 helpers -------------------------------------------------
typedef unsigned long long u64t;

__device__ __forceinline__ u64t pack2(float a, float b) {
    u64t r; asm("mov.b64 %0, {%1,%2};" : "=l"(r) : "f"(a), "f"(b)); return r;
}
__device__ __forceinline__ float2 unpack2(u64t v) {
    float2 r; asm("mov.b64 {%0,%1}, %2;" : "=f"(r.x), "=f"(r.y) : "l"(v)); return r;
}
__device__ __forceinline__ u64t ffma2(u64t a, u64t b, u64t c) {
    u64t d; asm("fma.rn.f32x2 %0, %1, %2, %3;" : "=l"(d) : "l"(a), "l"(b), "l"(c)); return d;
}
__device__ __forceinline__ float ex2(float x) {
    float r; asm("ex2.approx.f32 %0, %1;" : "=f"(r) : "f"(x)); return r;
}
__device__ __forceinline__ unsigned f2tf(float x) {
    unsigned r; asm("cvt.rna.tf32.f32 %0, %1;" : "=r"(r) : "f"(x)); return r;
}
// m16n8k8 tf32 mma, fp32 accumulate in-place.
__device__ __forceinline__ void mma_tf32(
    float& d0, float& d1, float& d2, float& d3,
    unsigned a0, unsigned a1, unsigned a2, unsigned a3,
    unsigned b0, unsigned b1)
{
    asm volatile(
        "mma.sync.aligned.m16n8k8.row.col.f32.tf32.tf32.f32 "
        "{%0,%1,%2,%3}, {%4,%5,%6,%7}, {%8,%9}, {%0,%1,%2,%3};\n"
        : "+f"(d0), "+f"(d1), "+f"(d2), "+f"(d3)
        : "r"(a0), "r"(a1), "r"(a2), "r"(a3), "r"(b0), "r"(b1));
}

// ---------------------------------------------------------------------------
// Pointwise 1x1 conv (input projection).
// ---------------------------------------------------------------------------
__global__ __launch_bounds__(256) void pointwise_k(
    const float* __restrict__ in, const float* __restrict__ wmat,
    const float* __restrict__ bias, float* __restrict__ out)
{
    __shared__ float swT[CC*CC];   // [c][o]
    __shared__ float sx[CC][64];   // [c][px]
    const int n  = blockIdx.y;
    const int p0 = blockIdx.x * 64;

    for (int idx = threadIdx.x; idx < CC*CC; idx += 256) {
        int o = idx & 63, c = idx >> 6;
        swT[c*CC + o] = wmat[o*CC + c];
        sx[c][o] = in[(n*CC + c)*PP + p0 + o];
    }
    __syncthreads();

    const int px  = threadIdx.x >> 2;
    const int ocg = threadIdx.x & 3;

    float acc[16];
    #pragma unroll
    for (int u = 0; u < 16; u++) acc[u] = bias[ocg + 4*u];

    #pragma unroll 4
    for (int c = 0; c < CC; c++) {
        float xv = sx[c][px];
        #pragma unroll
        for (int u = 0; u < 16; u++)
            acc[u] += swT[c*CC + ocg + 4*u] * xv;
    }

    #pragma unroll
    for (int u = 0; u < 16; u++)
        out[(n*CC + ocg + 4*u)*PP + p0 + px] = acc[u];
}

// ---------------------------------------------------------------------------
// Fused 3x3 convs, 2 output rows per block, FFMA2 over x-pixel pairs.
// ---------------------------------------------------------------------------
__global__ __launch_bounds__(256) void conv3_k(
    const float* __restrict__ xin,
    const float* __restrict__ Wq, const float* __restrict__ Wk,
    const float* __restrict__ Wv,
    float* __restrict__ Q0, float* __restrict__ K0, float* __restrict__ V0)
{
    const int br = blockIdx.z;
    const int yp = blockIdx.x;
    const int n  = blockIdx.y;
    if (br != 0 && yp >= VH/2) return;

    const float* wgt; float* out; int ow, ohw, ofs;
    if (br == 0)      { wgt = Wq; out = Q0; ow = WW; ohw = PP; ofs = -1; }
    else if (br == 1) { wgt = Wk; out = K0; ow = VW; ohw = DD; ofs = 0;  }
    else              { wgt = Wv; out = V0; ow = VW; ohw = DD; ofs = 0;  }

    const int y0 = yp * 2;

    __shared__ __align__(16) float tile[32][4][52];
    const float* inN = xin + n*CC*PP;

    const int oc = threadIdx.x >> 2;
    const int x0 = (threadIdx.x & 3) * 12;   // 16B aligned
    const float* wo = wgt + oc*(CC*9);

    u64t acc0[6], acc1[6];
    #pragma unroll
    for (int m = 0; m < 6; m++) { acc0[m] = 0ULL; acc1[m] = 0ULL; }

    for (int half = 0; half < 2; half++) {
        const int cbase = half * 32;
        __syncthreads();
        for (int idx = threadIdx.x; idx < 32*4*52; idx += 256) {
            int c = idx / 208, rem = idx % 208, r = rem / 52, j = rem % 52;
            int gy = y0 + r + ofs, gx = j + ofs;
            float v = 0.f;
            if (gy >= 0 && gy < HH && gx >= 0 && gx < WW)
                v = inN[(cbase + c)*PP + gy*WW + gx];
            tile[c][r][j] = v;
        }
        __syncthreads();

        #pragma unroll 2
        for (int c = 0; c < 32; c++) {
            u64t wd[9];
            #pragma unroll
            for (int t = 0; t < 9; t++) {
                float w = __ldg(wo + (cbase + c)*9 + t);
                wd[t] = pack2(w, w);
            }

            #pragma unroll
            for (int r = 0; r < 4; r++) {
                const ulonglong2* tp = (const ulonglong2*)&tile[c][r][x0];
                ulonglong2 Aq = tp[0], Bq = tp[1], Cq = tp[2], Dq = tp[3];
                u64t P[8] = {Aq.x, Aq.y, Bq.x, Bq.y, Cq.x, Cq.y, Dq.x, Dq.y};
                u64t O[6];
                #pragma unroll
                for (int m = 0; m < 6; m++) {
                    float2 lo = unpack2(P[m]);
                    float2 hi = unpack2(P[m+1]);
                    O[m] = pack2(lo.y, hi.x);
                }
                if (r < 3) {
                    u64t w0 = wd[r*3+0], w1 = wd[r*3+1], w2 = wd[r*3+2];
                    #pragma unroll
                    for (int m = 0; m < 6; m++) {
                        acc0[m] = ffma2(w0, P[m],   acc0[m]);
                        acc0[m] = ffma2(w1, O[m],   acc0[m]);
                        acc0[m] = ffma2(w2, P[m+1], acc0[m]);
                    }
                }
                if (r > 0) {
                    u64t w0 = wd[(r-1)*3+0], w1 = wd[(r-1)*3+1], w2 = wd[(r-1)*3+2];
                    #pragma unroll
                    for (int m = 0; m < 6; m++) {
                        acc1[m] = ffma2(w0, P[m],   acc1[m]);
                        acc1[m] = ffma2(w1, O[m],   acc1[m]);
                        acc1[m] = ffma2(w2, P[m+1], acc1[m]);
                    }
                }
            }
        }
    }

    float* ob0 = out + (n*CC + oc)*ohw + y0*ow;
    float* ob1 = ob0 + ow;
    #pragma unroll
    for (int m = 0; m < 6; m++) {
        float2 a = unpack2(acc0[m]);
        float2 b = unpack2(acc1[m]);
        int x = x0 + 2*m;
        if (x < ow)     { ob0[x]   = a.x; ob1[x]   = b.x; }
        if (x + 1 < ow) { ob0[x+1] = a.y; ob1[x+1] = b.y; }
    }
}

// ---------------------------------------------------------------------------
// Window sums.
// ---------------------------------------------------------------------------
__global__ __launch_bounds__(256) void winsum_k(
    const float* __restrict__ xin, float* __restrict__ S)
{
    const int c = blockIdx.x, n = blockIdx.y;
    const float* ib = xin + (n*CC + c)*PP;

    float rect[9];
    #pragma unroll
    for (int i = 0; i < 9; i++) rect[i] = 0.f;

    for (int idx = threadIdx.x; idx < PP; idx += 256) {
        int y = idx / WW, x = idx % WW;
        float v = ib[idx];
        int rlo = y - 45 > 0 ? y - 45 : 0;
        int rhi = y < 2 ? y : 2;
        int slo = x - 45 > 0 ? x - 45 : 0;
        int shi = x < 2 ? x : 2;
        for (int r = rlo; r <= rhi; r++)
            for (int s = slo; s <= shi; s++)
                rect[r*3 + s] += v;
    }
    #pragma unroll
    for (int i = 0; i < 9; i++) {
        #pragma unroll
        for (int off = 16; off > 0; off >>= 1)
            rect[i] += __shfl_xor_sync(0xffffffff, rect[i], off);
    }
    __shared__ float red[8][9];
    const int warp = threadIdx.x >> 5, lane = threadIdx.x & 31;
    if (lane == 0) {
        #pragma unroll
        for (int i = 0; i < 9; i++) red[warp][i] = rect[i];
    }
    __syncthreads();
    if (threadIdx.x < 9) {
        float s = 0.f;
        #pragma unroll
        for (int w = 0; w < 8; w++) s += red[w][threadIdx.x];
        S[(n*CC + c)*9 + threadIdx.x] = s;
    }
}

// ---------------------------------------------------------------------------
// Attention via tf32 mma.sync. 256 threads = 8 warps x 16 queries (128 q/blk).
// Double-buffered 96-key chunks, one barrier per chunk. Staging uses raw
// float bits for K (HW tf32 truncation; random logit error), rounded cvt for
// V (avoids systematic bias). Vector STS (uint2 for K, uint4 pair for V).
// Fragment layouts identical to the verified R11/R14 versions.
// ---------------------------------------------------------------------------
#define TK  96
#define NKG 12

__device__ __forceinline__ void stage_chunk(
    const float* __restrict__ ksl, const float* __restrict__ vsl, int d0,
    unsigned (*skb)[2][32][2], unsigned (*svb)[2][32][2], int tid)
{
    #pragma unroll 2
    for (int task = tid; task < 288; task += 256) {
        if (task < 96) {
            // K: skb[kg][ks][4*g2+t2] = {K[ks*8+t2][d0+kg*8+g2], K[ks*8+t2+4][...]}
            int kg = task % 12;
            int rs = task / 12;            // ks*4 + t2
            int ks = rs >> 2, t2 = rs & 3;
            int c0 = ks*8 + t2;
            const float4* s0 = (const float4*)(ksl + c0*DD + d0 + kg*8);
            const float4* s1 = (const float4*)(ksl + (c0+4)*DD + d0 + kg*8);
            float4 a0 = s0[0], a1 = s0[1];
            float4 b0 = s1[0], b1 = s1[1];
            float va[8] = {a0.x,a0.y,a0.z,a0.w,a1.x,a1.y,a1.z,a1.w};
            float vb[8] = {b0.x,b0.y,b0.z,b0.w,b1.x,b1.y,b1.z,b1.w};
            #pragma unroll
            for (int g2 = 0; g2 < 8; g2++) {
                uint2 w = make_uint2(__float_as_uint(va[g2]), __float_as_uint(vb[g2]));
                *(uint2*)&skb[kg][ks][4*g2 + t2][0] = w;
            }
        } else {
            // V: svb[kg][h][4*g2+(j&3)][j>>2] = tf32(V[8h+g2][d0+kg*8+j]), masked
            int tv = task - 96;
            int kg = tv % 12;
            int rs = tv / 12;              // h*8 + g2
            int h = rs >> 3, g2 = rs & 7;
            int c = 8*h + g2;
            int d = d0 + kg*8;
            const float4* src = (const float4*)(vsl + c*DD + d);
            float4 f0 = src[0], f1 = src[1];
            float v[8] = {f0.x,f0.y,f0.z,f0.w,f1.x,f1.y,f1.z,f1.w};
            unsigned b[8];
            #pragma unroll
            for (int j = 0; j < 8; j++)
                b[j] = (d + j < DD) ? f2tf(v[j]) : 0u;
            uint4* dst = (uint4*)&svb[kg][h][4*g2][0];
            dst[0] = make_uint4(b[0], b[4], b[1], b[5]);
            dst[1] = make_uint4(b[2], b[6], b[3], b[7]);
        }
    }
}

__global__ __launch_bounds__(256, 2) void attn_mma_k(
    const float* __restrict__ q0, const float* __restrict__ k0,
    const float* __restrict__ v0, float* __restrict__ A0)
{
    __shared__ __align__(16) unsigned skf[2][NKG][2][32][2];
    __shared__ __align__(16) unsigned svf[2][NKG][2][32][2];

    const int nh = blockIdx.y;
    const int n = nh >> 2, head = nh & 3;
    const int tid  = threadIdx.x;
    const int warp = tid >> 5;
    const int lane = tid & 31;
    const int g = lane >> 2, t = lane & 3;
    const int qb = blockIdx.x * 128 + warp * 16;

    const float* qsl = q0 + (n*CC + head*HCH)*PP;
    const float* ksl = k0 + (n*CC + head*HCH)*DD;
    const float* vsl = v0 + (n*CC + head*HCH)*DD;

    // Q A-fragments (2 ksteps), log2e folded, tf32.
    unsigned qa[2][4];
    #pragma unroll
    for (int ks = 0; ks < 2; ks++) {
        int cA = ks*8 + t, cB = cA + 4;
        qa[ks][0] = f2tf(qsl[cA*PP + qb + g]     * LOG2E);
        qa[ks][1] = f2tf(qsl[cA*PP + qb + 8 + g] * LOG2E);
        qa[ks][2] = f2tf(qsl[cB*PP + qb + g]     * LOG2E);
        qa[ks][3] = f2tf(qsl[cB*PP + qb + 8 + g] * LOG2E);
    }

    // even/odd kg accumulator chains
    float oE[8] = {0,0,0,0,0,0,0,0};
    float oO[8] = {0,0,0,0,0,0,0,0};
    float l_lo = 0.f, l_hi = 0.f;
    const unsigned fm = 0xffffffffu;

    const int nch = (DD + TK - 1) / TK;   // 23

    stage_chunk(ksl, vsl, 0, skf[0], svf[0], tid);
    __syncthreads();

    #pragma unroll 1
    for (int ci = 0; ci < nch; ci++) {
        const int cur = ci & 1;
        const int d0 = ci * TK;

        if (ci + 1 < nch)
            stage_chunk(ksl, vsl, d0 + TK, skf[cur^1], svf[cur^1], tid);

        // --- phase 1: all QK mmas (independent)
        float sf[NKG][4];
        #pragma unroll
        for (int kg = 0; kg < NKG; kg++) {
            float s0=0.f,s1=0.f,s2=0.f,s3=0.f;
            uint2 bk0 = *(const uint2*)&skf[cur][kg][0][lane][0];
            mma_tf32(s0,s1,s2,s3, qa[0][0],qa[0][1],qa[0][2],qa[0][3], bk0.x,bk0.y);
            uint2 bk1 = *(const uint2*)&skf[cur][kg][1][lane][0];
            mma_tf32(s0,s1,s2,s3, qa[1][0],qa[1][1],qa[1][2],qa[1][3], bk1.x,bk1.y);
            sf[kg][0]=s0; sf[kg][1]=s1; sf[kg][2]=s2; sf[kg][3]=s3;
        }

        // --- phase 2: exp + mask + denominator
        #pragma unroll
        for (int kg = 0; kg < NKG; kg++) {
            int col0 = d0 + kg*8 + 2*t;
            bool v0c = col0 < DD, v1c = (col0 + 1) < DD;
            float p0 = v0c ? ex2(sf[kg][0]) : 0.f;
            float p1 = v1c ? ex2(sf[kg][1]) : 0.f;
            float p2 = v0c ? ex2(sf[kg][2]) : 0.f;
            float p3 = v1c ? ex2(sf[kg][3]) : 0.f;
            l_lo += p0 + p1;
            l_hi += p2 + p3;
            sf[kg][0]=p0; sf[kg][1]=p1; sf[kg][2]=p2; sf[kg][3]=p3;
        }

        // --- phase 3: C-frag -> A-frag shuffles + PV mmas (even/odd chains)
        #pragma unroll
        for (int kg = 0; kg < NKG; kg++) {
            float p0 = sf[kg][0], p1 = sf[kg][1], p2 = sf[kg][2], p3 = sf[kg][3];
            int srcA = (lane & ~3) | (t >> 1);
            int srcB = srcA + 2;
            float x0 = __shfl_sync(fm, p0, srcA), x1 = __shfl_sync(fm, p1, srcA);
            float y0 = __shfl_sync(fm, p0, srcB), y1 = __shfl_sync(fm, p1, srcB);
            float z0 = __shfl_sync(fm, p2, srcA), z1 = __shfl_sync(fm, p3, srcA);
            float w0 = __shfl_sync(fm, p2, srcB), w1 = __shfl_sync(fm, p3, srcB);
            bool odd = (t & 1);
            unsigned a0 = f2tf(odd ? x1 : x0);
            unsigned a1 = f2tf(odd ? z1 : z0);
            unsigned a2 = f2tf(odd ? y1 : y0);
            unsigned a3 = f2tf(odd ? w1 : w0);

            float* oc = (kg & 1) ? oO : oE;
            uint2 bv0 = *(const uint2*)&svf[cur][kg][0][lane][0];
            mma_tf32(oc[0],oc[1],oc[2],oc[3], a0,a1,a2,a3, bv0.x,bv0.y);
            uint2 bv1 = *(const uint2*)&svf[cur][kg][1][lane][0];
            mma_tf32(oc[4],oc[5],oc[6],oc[7], a0,a1,a2,a3, bv1.x,bv1.y);
        }

        __syncthreads();
    }

    float o00 = oE[0]+oO[0], o01 = oE[1]+oO[1], o02 = oE[2]+oO[2], o03 = oE[3]+oO[3];
    float o10 = oE[4]+oO[4], o11 = oE[5]+oO[5], o12 = oE[6]+oO[6], o13 = oE[7]+oO[7];

    // denominator across the 4 threads of each row group
    l_lo += __shfl_xor_sync(fm, l_lo, 1);
    l_lo += __shfl_xor_sync(fm, l_lo, 2);
    l_hi += __shfl_xor_sync(fm, l_hi, 1);
    l_hi += __shfl_xor_sync(fm, l_hi, 2);
    float inv_lo = 1.f / l_lo, inv_hi = 1.f / l_hi;

    float* ab = A0 + (n*CC + head*HCH)*PP;
    int qlo = qb + g, qhi = qb + 8 + g;
    ab[(2*t    )*PP + qlo] = o00 * inv_lo;
    ab[(2*t + 1)*PP + qlo] = o01 * inv_lo;
    ab[(2*t    )*PP + qhi] = o02 * inv_hi;
    ab[(2*t + 1)*PP + qhi] = o03 * inv_hi;
    ab[(8 + 2*t    )*PP + qlo] = o10 * inv_lo;
    ab[(8 + 2*t + 1)*PP + qlo] = o11 * inv_lo;
    ab[(8 + 2*t    )*PP + qhi] = o12 * inv_hi;
    ab[(8 + 2*t + 1)*PP + qhi] = o13 * inv_hi;
}

// ---------------------------------------------------------------------------
// a2 from window sums + Wv[2], then gate bias constants. One block per n.
// ---------------------------------------------------------------------------
__global__ __launch_bounds__(256) void a2gc_k(
    const float* __restrict__ S, const float* __restrict__ Wv,
    const float* __restrict__ Wproj, const float* __restrict__ bg,
    float* __restrict__ gc)
{
    __shared__ float sS[CC*9];
    __shared__ float a2[CC];
    const int n = blockIdx.x;
    const int t = threadIdx.x;
    const float* Wv2 = Wv + 2*CC*CC*9;

    for (int i = t; i < CC*9; i += 256) sS[i] = S[n*CC*9 + i];
    __syncthreads();

    {
        const int o = t >> 2, part = t & 3;
        const float* wrow = Wv2 + o*(CC*9) + part*(16*9);
        const float* srow = sS + part*(16*9);
        float acc = 0.f;
        #pragma unroll 4
        for (int i = 0; i < 16*9; i++) acc += wrow[i] * srow[i];
        acc += __shfl_xor_sync(0xffffffff, acc, 1);
        acc += __shfl_xor_sync(0xffffffff, acc, 2);
        if (part == 0) a2[o] = acc * (1.f / (float)DD);
    }
    __syncthreads();

    if (t < 3*CC) {
        int gi = t / CC, o = t % CC;
        int gate = (gi == 0) ? 0 : (gi == 1 ? 2 : 3);
        const float* wp = Wproj + ((gate*4 + 2)*CC + o)*CC;
        float acc = bg[gate*CC + o];
        #pragma unroll
        for (int c = 0; c < CC; c++) acc += wp[c] * a2[c];
        gc[(n*3 + gi)*CC + o] = acc;
    }
}

// ---------------------------------------------------------------------------
// Gates i,g,o + cell + hidden + fused output 1x1 projection (reads A0).
// ---------------------------------------------------------------------------
__global__ __launch_bounds__(256) void gates_out_k(
    const float* __restrict__ A0, const float* __restrict__ Wproj,
    const float* __restrict__ gc, const float* __restrict__ W_out,
    const float* __restrict__ b_out, float* __restrict__ out)
{
    __shared__ float swiT[CC*CC];  // [c][o] ; later reused for W_out^T
    __shared__ float swgT[CC*CC];
    __shared__ float sx[CC][64];   // A0 tile; later reused for hout
    const int n  = blockIdx.y;
    const int p0 = blockIdx.x * 64;

    const float* Wi = Wproj + (0*4 + 0)*CC*CC;
    const float* Wg = Wproj + (2*4 + 0)*CC*CC;
    const float* Wo = Wproj + (3*4 + 0)*CC*CC;
    for (int idx = threadIdx.x; idx < CC*CC; idx += 256) {
        int o = idx & 63, c = idx >> 6;
        swiT[c*CC + o] = Wi[o*CC + c];
        swgT[c*CC + o] = Wg[o*CC + c];
        sx[c][o] = A0[(n*CC + c)*PP + p0 + o];
    }
    __syncthreads();

    const int px  = threadIdx.x >> 2;
    const int ocg = threadIdx.x & 3;
    const float* gcn = gc + n*3*CC;

    float ai[16], ag[16], ao[16];
    #pragma unroll
    for (int u = 0; u < 16; u++) {
        int oc = ocg + 4*u;
        ai[u] = gcn[oc]; ag[u] = gcn[CC + oc]; ao[u] = gcn[2*CC + oc];
    }

    #pragma unroll 2
    for (int c = 0; c < CC; c++) {
        float xv = sx[c][px];
        #pragma unroll
        for (int u = 0; u < 16; u++) {
            int oc = ocg + 4*u;
            ai[u] += swiT[c*CC + oc] * xv;
            ag[u] += swgT[c*CC + oc] * xv;
            ao[u] += __ldg(Wo + oc*CC + c) * xv;
        }
    }

    float hv[16];
    #pragma unroll
    for (int u = 0; u < 16; u++) {
        float ig = 1.f / (1.f + __expf(-ai[u]));
        float gg = tanhf(ag[u]);
        float og = 1.f / (1.f + __expf(-ao[u]));
        hv[u] = og * tanhf(ig * gg);
    }

    __syncthreads();
    #pragma unroll
    for (int u = 0; u < 16; u++) sx[ocg + 4*u][px] = hv[u];
    for (int idx = threadIdx.x; idx < CC*CC; idx += 256) {
        int o = idx & 63, c = idx >> 6;
        swiT[c*CC + o] = W_out[o*CC + c];
    }
    __syncthreads();

    float acc[16];
    #pragma unroll
    for (int u = 0; u < 16; u++) acc[u] = b_out[ocg + 4*u];
    #pragma unroll 4
    for (int c = 0; c < CC; c++) {
        float xv = sx[c][px];
        #pragma unroll
        for (int u = 0; u < 16; u++)
            acc[u] += swiT[c*CC + ocg + 4*u] * xv;
    }
    #pragma unroll
    for (int u = 0; u < 16; u++)
        out[(n*CC + ocg + 4*u)*PP + p0 + px] = acc[u];
}

// ---------------------------------------------------------------------------
extern "C" void kernel_launch(void* const* d_in, const int* in_sizes, int n_in,
                              void* d_out, int out_size)
{
    const float* x     = (const float*)d_in[0];
    const float* W_in  = (const float*)d_in[1];
    const float* b_in  = (const float*)d_in[2];
    const float* Wq    = (const float*)d_in[3];
    const float* Wk    = (const float*)d_in[4];
    const float* Wv    = (const float*)d_in[5];
    const float* Wproj = (const float*)d_in[6];
    const float* b_g   = (const float*)d_in[7];
    const float* W_out = (const float*)d_in[8];
    const float* b_out = (const float*)d_in[9];
    float* out = (float*)d_out;

    void* sp = nullptr;
    cudaGetSymbolAddress(&sp, g_scratch);
    float* s = (float*)sp;

    const dim3 pwGrid(PP/64, NB);

    pointwise_k<<<pwGrid, 256>>>(x, W_in, b_in, s + OFF_XIN);
    conv3_k<<<dim3(HH/2, NB, 3), 256>>>(s + OFF_XIN, Wq, Wk, Wv,
                                        s + OFF_Q0, s + OFF_K0, s + OFF_V0);
    winsum_k<<<dim3(CC, NB), 256>>>(s + OFF_XIN, s + OFF_S);
    attn_mma_k<<<dim3(PP/128, NB*HEADS), 256>>>(s + OFF_Q0, s + OFF_K0,
                                                s + OFF_V0, s + OFF_A0);
    a2gc_k<<<NB, 256>>>(s + OFF_S, Wv, Wproj, b_g, s + OFF_GC);
    gates_out_k<<<pwGrid, 256>>>(s + OFF_A0, Wproj, s + OFF_GC, W_out, b_out, out);
}